// round 9
// baseline (speedup 1.0000x reference)
#include <cuda_runtime.h>
#include <math.h>
#include <stdint.h>

#define BB 2
#define SS 1024
#define DD 1024
#define NH 16
#define HD 64
#define NL 12
#define DFF 4096
#define RH 128
#define VOC 32000
#define MM (BB*SS)
#define BHT (BB*NH)
#define QKVS 3072

// ---- static scratch ----
__device__ float g_h [MM*DD];
__device__ float g_h1[MM*DD];
__device__ float g_t [MM*DD];
__device__ float g_t2[MM*DD];
__device__ float g_qkv[MM*QKVS];
__device__ float g_a [MM*DD];
__device__ float g_f1[MM*DFF];
__device__ float g_zr[MM*RH];
__device__ float g_sc[(size_t)BHT*SS*SS];
__device__ unsigned char g_skip[MM];
__device__ int g_idx[MM];
__device__ int g_nact;
__device__ int g_cnt[3];
__device__ float g_wqkv_h[(size_t)QKVS*DD], g_wqkv_l[(size_t)QKVS*DD];
__device__ float g_wo_h[(size_t)DD*DD],     g_wo_l[(size_t)DD*DD];
__device__ float g_wf1_h[(size_t)DFF*DD],   g_wf1_l[(size_t)DFF*DD];
__device__ float g_wf2_h[(size_t)DD*DFF],   g_wf2_l[(size_t)DD*DFF];
__device__ float g_wout_h[(size_t)VOC*DD],  g_wout_l[(size_t)VOC*DD];
__device__ float g_bqkv[QKVS];

static __device__ __forceinline__ unsigned smem_u32(const void* p) {
    unsigned r;
    asm("{ .reg .u64 t; cvta.to.shared.u64 t, %1; cvt.u32.u64 %0, t; }" : "=r"(r) : "l"(p));
    return r;
}
static __device__ __forceinline__ float to_tf32f(float x) {
    float r; asm("cvt.rna.tf32.f32 %0, %1;" : "=f"(r) : "f"(x)); return r;
}
static __device__ __forceinline__ void mma8(float* c, const unsigned* a, const unsigned* b) {
    asm volatile(
        "mma.sync.aligned.m16n8k8.row.col.f32.tf32.tf32.f32 "
        "{%0,%1,%2,%3}, {%4,%5,%6,%7}, {%8,%9}, {%0,%1,%2,%3};"
        : "+f"(c[0]), "+f"(c[1]), "+f"(c[2]), "+f"(c[3])
        : "r"(a[0]), "r"(a[1]), "r"(a[2]), "r"(a[3]), "r"(b[0]), "r"(b[1]));
}
static __device__ __forceinline__ void ldsm4(unsigned* r, unsigned addr) {
    asm volatile("ldmatrix.sync.aligned.m8n8.x4.shared.b16 {%0,%1,%2,%3}, [%4];"
        : "=r"(r[0]), "=r"(r[1]), "=r"(r[2]), "=r"(r[3]) : "r"(addr));
}
static __device__ __forceinline__ float4 hi4(float4 v) {
    return make_float4(to_tf32f(v.x), to_tf32f(v.y), to_tf32f(v.z), to_tf32f(v.w));
}
static __device__ __forceinline__ float4 lo4(float4 v, float4 h) {
    return make_float4(to_tf32f(v.x - h.x), to_tf32f(v.y - h.y),
                       to_tf32f(v.z - h.z), to_tf32f(v.w - h.w));
}
#define CP16(dst, src) \
    asm volatile("cp.async.cg.shared.global [%0], [%1], 16;" :: "r"(dst), "l"(src))

__global__ void zero_cnt_kernel() { if (threadIdx.x < 3) g_cnt[threadIdx.x] = 0; }

// deterministic compaction of active (non-skip) token indices
__global__ __launch_bounds__(1024) void compact_kernel() {
    __shared__ int ps[1024];
    int tid = threadIdx.x;
    int a0 = g_skip[2 * tid] ? 0 : 1;
    int a1 = g_skip[2 * tid + 1] ? 0 : 1;
    ps[tid] = a0 + a1;
    __syncthreads();
    for (int off = 1; off < 1024; off <<= 1) {
        int v = ps[tid];
        int add = (tid >= off) ? ps[tid - off] : 0;
        __syncthreads();
        ps[tid] = v + add;
        __syncthreads();
    }
    int base = ps[tid] - (a0 + a1);
    if (a0) g_idx[base] = 2 * tid;
    if (a1) g_idx[base + a0] = 2 * tid + 1;
    if (tid == 1023) g_nact = ps[1023];
}

// W[K][N] -> Th/Tl [N][K] with tf32 hi/lo split
__global__ __launch_bounds__(256) void wtrans_kernel(const float* __restrict__ W,
                                                     float* __restrict__ Th,
                                                     float* __restrict__ Tl, int K, int N) {
    __shared__ float tile[32][33];
    int n0 = blockIdx.x * 32, k0 = blockIdx.y * 32;
    int tx = threadIdx.x & 31, ty = threadIdx.x >> 5;
    for (int i = ty; i < 32; i += 8) tile[i][tx] = W[(size_t)(k0 + i) * N + n0 + tx];
    __syncthreads();
    for (int i = ty; i < 32; i += 8) {
        float v = tile[tx][i];
        float hv = to_tf32f(v);
        float lv = to_tf32f(v - hv);
        size_t o = (size_t)(n0 + i) * K + k0 + tx;
        Th[o] = hv; Tl[o] = lv;
    }
}

__global__ void bcat_kernel(const float* __restrict__ bq, const float* __restrict__ bk,
                            const float* __restrict__ bv) {
    int i = blockIdx.x * 256 + threadIdx.x;
    g_bqkv[i] = (i < 1024) ? bq[i] : (i < 2048) ? bk[i - 1024] : bv[i - 2048];
}

__global__ __launch_bounds__(256) void embed_kernel(const int* __restrict__ x,
                                                    const float* __restrict__ emb) {
    int tok = blockIdx.x, s = tok % SS, id = x[tok];
    int d0 = threadIdx.x * 4;
    float4 ev = *(const float4*)(emb + (size_t)id * DD + d0);
    float o[4] = {ev.x, ev.y, ev.z, ev.w};
#pragma unroll
    for (int j = 0; j < 4; j++) {
        int d = d0 + j;
        float ang = (float)s * expf((float)(d & ~1) * (-9.210340371976184f / 1024.0f));
        o[j] = o[j] * 32.0f + ((d & 1) ? cosf(ang) : sinf(ang));
    }
    *(float4*)(g_h + (size_t)tok * DD + d0) = make_float4(o[0], o[1], o[2], o[3]);
}

// ===== mma.sync 3xTF32 GEMM (ldmatrix), split-K + row compaction =====
#define KCH 16
#define ROWW 20
#define MATB (128*ROWW*4)
#define STGB (3*MATB)
#define TGSM (3*STGB)

__global__ __launch_bounds__(256, 2)
void tgemm_kernel(const float* __restrict__ A, const float* __restrict__ Bh,
                  const float* __restrict__ Bl, const float* __restrict__ bias,
                  float* __restrict__ C0, float* __restrict__ C1,
                  int M, int N, int Ksub, int ldk, int relu, int mode) {
    extern __shared__ char smem[];
    unsigned sb = smem_u32(smem);
    int bm = blockIdx.y * 128, bn = blockIdx.x * 128;
    int Meff = M;
    if (mode) {
        Meff = g_nact;
        if (bm >= Meff) return;
    }
    int z = blockIdx.z;
    A  += (size_t)z * Ksub;
    Bh += (size_t)z * Ksub;
    Bl += (size_t)z * Ksub;
    float* C = z ? C1 : C0;
    int tid = threadIdx.x, wid = tid >> 5, lane = tid & 31;
    int grp = lane >> 2, qid = lane & 3;
    int wm0 = (wid & 3) * 32, wn0 = (wid >> 2) * 64;
    // ldmatrix lane->row/col mapping
    int lr = lane & 7, sel = lane >> 3;
    int mrow = (sel & 1) * 8 + lr;
    int mcolw = (sel >> 1) * 4;

    float acc[2][8][4];
#pragma unroll
    for (int mt = 0; mt < 2; mt++)
#pragma unroll
        for (int nt = 0; nt < 8; nt++)
#pragma unroll
            for (int e = 0; e < 4; e++) acc[mt][nt][e] = 0.f;

    int nchunks = Ksub / KCH;
    int r0 = tid >> 2, kc0 = (tid & 3) * 16;
    int r1 = (tid + 256) >> 2, kc1 = ((tid + 256) & 3) * 16;

    const float *Ar0, *Ar1;
    {
        int rr0 = bm + r0, rr1 = bm + r1;
        if (mode == 1) {
            rr0 = g_idx[rr0 < Meff ? rr0 : Meff - 1];
            rr1 = g_idx[rr1 < Meff ? rr1 : Meff - 1];
        }
        Ar0 = A + (size_t)rr0 * ldk;
        Ar1 = A + (size_t)rr1 * ldk;
    }

#pragma unroll
    for (int c = 0; c < 2; c++) {
        int kb = c * KCH;
        unsigned st = sb + (c % 3) * STGB;
        CP16(st + r0 * 80 + kc0, Ar0 + kb + kc0 / 4);
        CP16(st + r1 * 80 + kc1, Ar1 + kb + kc1 / 4);
        CP16(st + MATB + r0 * 80 + kc0, Bh + (size_t)(bn + r0) * ldk + kb + kc0 / 4);
        CP16(st + MATB + r1 * 80 + kc1, Bh + (size_t)(bn + r1) * ldk + kb + kc1 / 4);
        CP16(st + 2 * MATB + r0 * 80 + kc0, Bl + (size_t)(bn + r0) * ldk + kb + kc0 / 4);
        CP16(st + 2 * MATB + r1 * 80 + kc1, Bl + (size_t)(bn + r1) * ldk + kb + kc1 / 4);
        asm volatile("cp.async.commit_group;");
    }

    for (int c = 0; c < nchunks; c++) {
        if (c + 2 < nchunks) asm volatile("cp.async.wait_group 1;");
        else                 asm volatile("cp.async.wait_group 0;");
        __syncthreads();
        unsigned sA  = sb + (c % 3) * STGB;
        unsigned sBh = sA + MATB;
        unsigned sBl = sA + 2 * MATB;
#pragma unroll
        for (int s8 = 0; s8 < 2; s8++) {
            int k8 = s8 * 8;
            unsigned Ahr[2][4], Alr[2][4];
#pragma unroll
            for (int mt = 0; mt < 2; mt++) {
                unsigned araw[4];
                ldsm4(araw, sA + ((wm0 + mt * 16 + mrow) * ROWW + k8 + mcolw) * 4);
#pragma unroll
                for (int e = 0; e < 4; e++) {
                    float xv = __uint_as_float(araw[e]);
                    float hv = to_tf32f(xv);
                    Ahr[mt][e] = __float_as_uint(hv);
                    Alr[mt][e] = __float_as_uint(to_tf32f(xv - hv));
                }
            }
#pragma unroll
            for (int j = 0; j < 4; j++) {
                unsigned off = ((wn0 + j * 16 + mrow) * ROWW + k8 + mcolw) * 4;
                unsigned bhf[4], blf[4];
                ldsm4(bhf, sBh + off);
                ldsm4(blf, sBl + off);
                unsigned b0h[2] = {bhf[0], bhf[2]}, b1h[2] = {bhf[1], bhf[3]};
                unsigned b0l[2] = {blf[0], blf[2]}, b1l[2] = {blf[1], blf[3]};
#pragma unroll
                for (int mt = 0; mt < 2; mt++) {
                    mma8(acc[mt][2 * j],     Ahr[mt], b0h);
                    mma8(acc[mt][2 * j],     Ahr[mt], b0l);
                    mma8(acc[mt][2 * j],     Alr[mt], b0h);
                    mma8(acc[mt][2 * j + 1], Ahr[mt], b1h);
                    mma8(acc[mt][2 * j + 1], Ahr[mt], b1l);
                    mma8(acc[mt][2 * j + 1], Alr[mt], b1h);
                }
            }
        }
        __syncthreads();
        if (c + 2 < nchunks) {
            int kb = (c + 2) * KCH;
            unsigned st = sb + ((c + 2) % 3) * STGB;
            CP16(st + r0 * 80 + kc0, Ar0 + kb + kc0 / 4);
            CP16(st + r1 * 80 + kc1, Ar1 + kb + kc1 / 4);
            CP16(st + MATB + r0 * 80 + kc0, Bh + (size_t)(bn + r0) * ldk + kb + kc0 / 4);
            CP16(st + MATB + r1 * 80 + kc1, Bh + (size_t)(bn + r1) * ldk + kb + kc1 / 4);
            CP16(st + 2 * MATB + r0 * 80 + kc0, Bl + (size_t)(bn + r0) * ldk + kb + kc0 / 4);
            CP16(st + 2 * MATB + r1 * 80 + kc1, Bl + (size_t)(bn + r1) * ldk + kb + kc1 / 4);
            asm volatile("cp.async.commit_group;");
        }
    }

#pragma unroll
    for (int mt = 0; mt < 2; mt++) {
#pragma unroll
        for (int nt = 0; nt < 8; nt++) {
            int row0 = bm + wm0 + mt * 16 + grp;
            int col = bn + wn0 + nt * 8 + 2 * qid;
            float2 v0 = make_float2(acc[mt][nt][0], acc[mt][nt][1]);
            float2 v1 = make_float2(acc[mt][nt][2], acc[mt][nt][3]);
            if (bias) {
                float2 bv = *(const float2*)(bias + col);
                v0.x += bv.x; v0.y += bv.y; v1.x += bv.x; v1.y += bv.y;
            }
            if (relu) {
                v0.x = fmaxf(v0.x, 0.f); v0.y = fmaxf(v0.y, 0.f);
                v1.x = fmaxf(v1.x, 0.f); v1.y = fmaxf(v1.y, 0.f);
            }
            if (row0 < Meff)
                *(float2*)(C + (size_t)row0 * N + col) = v0;
            if (row0 + 8 < Meff)
                *(float2*)(C + (size_t)(row0 + 8) * N + col) = v1;
        }
    }
}

// ===== tensor-core attention scores (ldmatrix) =====
#define ASTR 68
#define SCSM (4*128*ASTR*4)

__global__ __launch_bounds__(256)
void attn_scores_mma_kernel() {
    int t = blockIdx.x;
    int qt = (int)((sqrtf(8.f * t + 1.f) - 1.f) * 0.5f);
    while ((qt + 1) * (qt + 2) / 2 <= t) qt++;
    while (qt * (qt + 1) / 2 > t) qt--;
    int kt = t - qt * (qt + 1) / 2;
    int bh = blockIdx.y;
    int b = bh >> 4, hh = bh & 15;

    extern __shared__ float sm[];
    unsigned sQH = smem_u32(sm);
    unsigned sQL = sQH + 128 * ASTR * 4;
    unsigned sKH = sQL + 128 * ASTR * 4;
    unsigned sKL = sKH + 128 * ASTR * 4;
    float* QH = sm;
    float* QL = QH + 128 * ASTR;
    float* KH = QL + 128 * ASTR;
    float* KL = KH + 128 * ASTR;

    int tid = threadIdx.x, wid = tid >> 5, lane = tid & 31;
    int grp = lane >> 2, qid = lane & 3;
    int wm0 = (wid & 3) * 32, wn0 = (wid >> 2) * 64;
    int lr = lane & 7, sel = lane >> 3;
    int mrow = (sel & 1) * 8 + lr;
    int mcolw = (sel >> 1) * 4;

    const float* qb = g_qkv + ((size_t)(b * SS + qt * 128)) * QKVS + hh * HD;
    const float* kb = g_qkv + ((size_t)(b * SS + kt * 128)) * QKVS + 1024 + hh * HD;
    for (int i = tid; i < 128 * 16; i += 256) {
        int row = i >> 4, c4 = (i & 15) * 4;
        float4 v = *(const float4*)(qb + (size_t)row * QKVS + c4);
        float4 h = hi4(v);
        *(float4*)(QH + row * ASTR + c4) = h;
        *(float4*)(QL + row * ASTR + c4) = lo4(v, h);
        float4 w = *(const float4*)(kb + (size_t)row * QKVS + c4);
        float4 wh = hi4(w);
        *(float4*)(KH + row * ASTR + c4) = wh;
        *(float4*)(KL + row * ASTR + c4) = lo4(w, wh);
    }
    __syncthreads();

    float acc[2][8][4];
#pragma unroll
    for (int mt = 0; mt < 2; mt++)
#pragma unroll
        for (int nt = 0; nt < 8; nt++)
#pragma unroll
            for (int e = 0; e < 4; e++) acc[mt][nt][e] = 0.f;

#pragma unroll
    for (int s = 0; s < 8; s++) {
        int k8 = s * 8;
        unsigned Ahr[2][4], Alr[2][4];
#pragma unroll
        for (int mt = 0; mt < 2; mt++) {
            unsigned off = ((wm0 + mt * 16 + mrow) * ASTR + k8 + mcolw) * 4;
            ldsm4(Ahr[mt], sQH + off);
            ldsm4(Alr[mt], sQL + off);
        }
#pragma unroll
        for (int j = 0; j < 4; j++) {
            unsigned off = ((wn0 + j * 16 + mrow) * ASTR + k8 + mcolw) * 4;
            unsigned bhf[4], blf[4];
            ldsm4(bhf, sKH + off);
            ldsm4(blf, sKL + off);
            unsigned b0h[2] = {bhf[0], bhf[2]}, b1h[2] = {bhf[1], bhf[3]};
            unsigned b0l[2] = {blf[0], blf[2]}, b1l[2] = {blf[1], blf[3]};
#pragma unroll
            for (int mt = 0; mt < 2; mt++) {
                mma8(acc[mt][2 * j],     Ahr[mt], b0h);
                mma8(acc[mt][2 * j],     Ahr[mt], b0l);
                mma8(acc[mt][2 * j],     Alr[mt], b0h);
                mma8(acc[mt][2 * j + 1], Ahr[mt], b1h);
                mma8(acc[mt][2 * j + 1], Ahr[mt], b1l);
                mma8(acc[mt][2 * j + 1], Alr[mt], b1h);
            }
        }
    }

    bool diag = (kt == qt);
#pragma unroll
    for (int mt = 0; mt < 2; mt++) {
#pragma unroll
        for (int nt = 0; nt < 8; nt++) {
            int r0 = qt * 128 + wm0 + mt * 16 + grp;
            int c0 = kt * 128 + wn0 + nt * 8 + 2 * qid;
            float v0 = acc[mt][nt][0] * 0.125f, v1 = acc[mt][nt][1] * 0.125f;
            float v2 = acc[mt][nt][2] * 0.125f, v3 = acc[mt][nt][3] * 0.125f;
            if (diag) {
                if (c0 > r0)     v0 = -1e30f;
                if (c0 + 1 > r0) v1 = -1e30f;
                if (c0 > r0 + 8)     v2 = -1e30f;
                if (c0 + 1 > r0 + 8) v3 = -1e30f;
            }
            float* p0 = g_sc + ((size_t)bh * SS + r0) * SS + c0;
            *(float2*)p0 = make_float2(v0, v1);
            *(float2*)(p0 + 8 * SS) = make_float2(v2, v3);
        }
    }
}

// ===== prefix softmax =====
__global__ __launch_bounds__(256) void softmax_kernel() {
    int row = blockIdx.x;
    int qr = row & (SS - 1);
    int L = ((qr >> 7) + 1) << 7;
    float* sc = g_sc + (size_t)row * SS;
    int tid = threadIdx.x;
    bool valid = (tid * 4 < L);
    float4 v = valid ? *(float4*)&sc[tid * 4] : make_float4(-1e30f, -1e30f, -1e30f, -1e30f);
    __shared__ float red[8];
    __shared__ float stat;
    float m = fmaxf(fmaxf(v.x, v.y), fmaxf(v.z, v.w));
    for (int o = 16; o; o >>= 1) m = fmaxf(m, __shfl_down_sync(~0u, m, o));
    if ((tid & 31) == 0) red[tid >> 5] = m;
    __syncthreads();
    if (tid == 0) {
        float t = red[0];
        for (int i = 1; i < 8; i++) t = fmaxf(t, red[i]);
        stat = t;
    }
    __syncthreads();
    float mx = stat;
    float e0 = expf(v.x - mx), e1 = expf(v.y - mx), e2 = expf(v.z - mx), e3 = expf(v.w - mx);
    float s = e0 + e1 + e2 + e3;
    for (int o = 16; o; o >>= 1) s += __shfl_down_sync(~0u, s, o);
    __syncthreads();
    if ((tid & 31) == 0) red[tid >> 5] = s;
    __syncthreads();
    if (tid == 0) {
        float t = 0.f;
        for (int i = 0; i < 8; i++) t += red[i];
        stat = t;
    }
    __syncthreads();
    float inv = 1.0f / stat;
    if (valid) *(float4*)&sc[tid * 4] = make_float4(e0 * inv, e1 * inv, e2 * inv, e3 * inv);
}

// ===== tensor-core AV (ldmatrix) =====
#define AVSM ((2*128 + 2*64)*ASTR*4)

__global__ __launch_bounds__(256)
void attn_av_mma_kernel() {
    int qt = blockIdx.x, bh = blockIdx.y;
    int b = bh >> 4, hh = bh & 15;

    extern __shared__ float sm[];
    unsigned sPH = smem_u32(sm);
    unsigned sPL = sPH + 128 * ASTR * 4;
    unsigned sVH = sPL + 128 * ASTR * 4;
    unsigned sVL = sVH + 64 * ASTR * 4;
    float* PH = sm;
    float* PL = PH + 128 * ASTR;
    float* VH = PL + 128 * ASTR;
    float* VL = VH + 64 * ASTR;

    int tid = threadIdx.x, wid = tid >> 5, lane = tid & 31;
    int grp = lane >> 2, qid = lane & 3;
    int wm0 = (wid & 3) * 32, wn0 = (wid >> 2) * 32;
    int lr = lane & 7, sel = lane >> 3;
    int mrow = (sel & 1) * 8 + lr;
    int mcolw = (sel >> 1) * 4;

    float acc[2][4][4];
#pragma unroll
    for (int mt = 0; mt < 2; mt++)
#pragma unroll
        for (int nt = 0; nt < 4; nt++)
#pragma unroll
            for (int e = 0; e < 4; e++) acc[mt][nt][e] = 0.f;

    int nchunks = (qt + 1) * 2;
    for (int kc = 0; kc < nchunks; kc++) {
        const float* pb = g_sc + ((size_t)bh * SS + qt * 128) * SS + kc * 64;
        for (int i = tid; i < 128 * 16; i += 256) {
            int row = i >> 4, c4 = (i & 15) * 4;
            float4 v = *(const float4*)(pb + (size_t)row * SS + c4);
            float4 h = hi4(v);
            *(float4*)(PH + row * ASTR + c4) = h;
            *(float4*)(PL + row * ASTR + c4) = lo4(v, h);
        }
        const float* vb = g_qkv + ((size_t)(b * SS + kc * 64)) * QKVS + 2048 + hh * HD;
        for (int i = tid; i < 64 * 16; i += 256) {
            int tok = i >> 4, d4 = (i & 15) * 4;
            float4 v = *(const float4*)(vb + (size_t)tok * QKVS + d4);
            float4 h = hi4(v);
            float4 l = lo4(v, h);
            VH[(d4 + 0) * ASTR + tok] = h.x; VL[(d4 + 0) * ASTR + tok] = l.x;
            VH[(d4 + 1) * ASTR + tok] = h.y; VL[(d4 + 1) * ASTR + tok] = l.y;
            VH[(d4 + 2) * ASTR + tok] = h.z; VL[(d4 + 2) * ASTR + tok] = l.z;
            VH[(d4 + 3) * ASTR + tok] = h.w; VL[(d4 + 3) * ASTR + tok] = l.w;
        }
        __syncthreads();
#pragma unroll
        for (int s = 0; s < 8; s++) {
            int k8 = s * 8;
            unsigned Ahr[2][4], Alr[2][4];
#pragma unroll
            for (int mt = 0; mt < 2; mt++) {
                unsigned off = ((wm0 + mt * 16 + mrow) * ASTR + k8 + mcolw) * 4;
                ldsm4(Ahr[mt], sPH + off);
                ldsm4(Alr[mt], sPL + off);
            }
#pragma unroll
            for (int j = 0; j < 2; j++) {
                unsigned off = ((wn0 + j * 16 + mrow) * ASTR + k8 + mcolw) * 4;
                unsigned bhf[4], blf[4];
                ldsm4(bhf, sVH + off);
                ldsm4(blf, sVL + off);
                unsigned b0h[2] = {bhf[0], bhf[2]}, b1h[2] = {bhf[1], bhf[3]};
                unsigned b0l[2] = {blf[0], blf[2]}, b1l[2] = {blf[1], blf[3]};
#pragma unroll
                for (int mt = 0; mt < 2; mt++) {
                    mma8(acc[mt][2 * j],     Ahr[mt], b0h);
                    mma8(acc[mt][2 * j],     Ahr[mt], b0l);
                    mma8(acc[mt][2 * j],     Alr[mt], b0h);
                    mma8(acc[mt][2 * j + 1], Ahr[mt], b1h);
                    mma8(acc[mt][2 * j + 1], Ahr[mt], b1l);
                    mma8(acc[mt][2 * j + 1], Alr[mt], b1h);
                }
            }
        }
        __syncthreads();
    }

#pragma unroll
    for (int mt = 0; mt < 2; mt++) {
#pragma unroll
        for (int nt = 0; nt < 4; nt++) {
            int r0 = qt * 128 + wm0 + mt * 16 + grp;
            int c0 = hh * HD + wn0 + nt * 8 + 2 * qid;
            float* p0 = g_a + ((size_t)(b * SS) + r0) * DD + c0;
            *(float2*)p0 = make_float2(acc[mt][nt][0], acc[mt][nt][1]);
            *(float2*)(p0 + 8 * DD) = make_float2(acc[mt][nt][2], acc[mt][nt][3]);
        }
    }
}

// ===== SIMT SGEMM (router GEMM1) =====
__global__ __launch_bounds__(256) void sgemm_kernel(const float* __restrict__ A,
                                                    const float* __restrict__ B,
                                                    const float* __restrict__ bias,
                                                    float* __restrict__ C,
                                                    int M, int N, int K) {
    __shared__ float Ast[16][128];
    __shared__ float Bs[16][64];
    int tid = threadIdx.x;
    int bm = blockIdx.y * 128, bn = blockIdx.x * 64;
    int tx = tid & 15, ty = tid >> 4;
    int m0 = ty * 8, n0 = tx * 4;
    float acc[8][4];
#pragma unroll
    for (int i = 0; i < 8; i++)
#pragma unroll
        for (int j = 0; j < 4; j++) acc[i][j] = 0.f;
    int arow = tid >> 2, ak4 = (tid & 3) * 4, bk = tid >> 4, bc4 = (tid & 15) * 4;
    for (int kb = 0; kb < K; kb += 16) {
#pragma unroll
        for (int p = 0; p < 2; p++) {
            int r = arow + p * 64;
            float4 av = *(const float4*)(A + (size_t)(bm + r) * K + kb + ak4);
            Ast[ak4+0][r] = av.x; Ast[ak4+1][r] = av.y; Ast[ak4+2][r] = av.z; Ast[ak4+3][r] = av.w;
        }
        *(float4*)&Bs[bk][bc4] = *(const float4*)(B + (size_t)(kb + bk) * N + bn + bc4);
        __syncthreads();
#pragma unroll
        for (int k = 0; k < 16; k++) {
            float4 a0 = *(float4*)&Ast[k][m0];
            float4 a1 = *(float4*)&Ast[k][m0 + 4];
            float4 bv = *(float4*)&Bs[k][n0];
            float am[8] = {a0.x,a0.y,a0.z,a0.w,a1.x,a1.y,a1.z,a1.w};
            float bb[4] = {bv.x,bv.y,bv.z,bv.w};
#pragma unroll
            for (int i = 0; i < 8; i++)
#pragma unroll
                for (int j = 0; j < 4; j++) acc[i][j] += am[i] * bb[j];
        }
        __syncthreads();
    }
#pragma unroll
    for (int i = 0; i < 8; i++)
#pragma unroll
        for (int j = 0; j < 4; j++) {
            float v = acc[i][j] + bias[bn + n0 + j];
            C[(size_t)(bm + m0 + i) * N + bn + n0 + j] = fmaxf(v, 0.f);
        }
}

// ===== fused LN on compact rows =====
__global__ __launch_bounds__(256) void ln_fused_kernel(const float* __restrict__ in0,
                                                       const float* __restrict__ in1,
                                                       const float* __restrict__ res,
                                                       const float* __restrict__ bias,
                                                       const float* __restrict__ g,
                                                       const float* __restrict__ bsh,
                                                       float* __restrict__ out,
                                                       int resGather, int outScatter) {
    int row = blockIdx.x;
    if (row >= g_nact) return;
    int orow = g_idx[row];
    size_t inoff = (size_t)row * DD;
    size_t resoff = (size_t)(resGather ? orow : row) * DD;
    size_t outoff = (size_t)(outScatter ? orow : row) * DD;
    int tid = threadIdx.x;
    float4 v = *(const float4*)&in0[inoff + tid * 4];
    float4 w = *(const float4*)&in1[inoff + tid * 4];
    float4 r = *(const float4*)&res[resoff + tid * 4];
    float4 bv = *(const float4*)&bias[tid * 4];
    v.x += w.x + r.x + bv.x; v.y += w.y + r.y + bv.y;
    v.z += w.z + r.z + bv.z; v.w += w.w + r.w + bv.w;
    __shared__ float red[8];
    __shared__ float stat;
    float s = v.x + v.y + v.z + v.w;
    for (int o = 16; o; o >>= 1) s += __shfl_down_sync(~0u, s, o);
    if ((tid & 31) == 0) red[tid >> 5] = s;
    __syncthreads();
    if (tid == 0) {
        float t = 0.f;
        for (int i = 0; i < 8; i++) t += red[i];
        stat = t * (1.0f / DD);
    }
    __syncthreads();
    float mu = stat;
    float dx = v.x - mu, dy = v.y - mu, dz = v.z - mu, dw = v.w - mu;
    float ss = dx * dx + dy * dy + dz * dz + dw * dw;
    for (int o = 16; o; o >>= 1) ss += __shfl_down_sync(~0u, ss, o);
    __syncthreads();
    if ((tid & 31) == 0) red[tid >> 5] = ss;
    __syncthreads();
    if (tid == 0) {
        float t = 0.f;
        for (int i = 0; i < 8; i++) t += red[i];
        stat = rsqrtf(t * (1.0f / DD) + 1e-5f);
    }
    __syncthreads();
    float rs = stat;
    float4 gg = *(const float4*)&g[tid * 4];
    float4 bb = *(const float4*)&bsh[tid * 4];
    *(float4*)&out[outoff + tid * 4] =
        make_float4(dx * rs * gg.x + bb.x, dy * rs * gg.y + bb.y,
                    dz * rs * gg.z + bb.z, dw * rs * gg.w + bb.w);
}

__global__ __launch_bounds__(256) void router2_kernel(const float* __restrict__ rw2,
                                                      const float* __restrict__ rb2) {
    int w = (blockIdx.x * blockDim.x + threadIdx.x) >> 5;
    int lane = threadIdx.x & 31;
    if (w >= MM) return;
    const float* z = g_zr + (size_t)w * RH;
    float s0 = 0.f, s1 = 0.f, s2 = 0.f;
#pragma unroll
    for (int u = 0; u < 4; u++) {
        int j = lane + 32 * u;
        float zv = z[j];
        s0 += zv * rw2[j * 3 + 0];
        s1 += zv * rw2[j * 3 + 1];
        s2 += zv * rw2[j * 3 + 2];
    }
    for (int o = 16; o; o >>= 1) {
        s0 += __shfl_down_sync(~0u, s0, o);
        s1 += __shfl_down_sync(~0u, s1, o);
        s2 += __shfl_down_sync(~0u, s2, o);
    }
    if (lane == 0) {
        s0 += rb2[0]; s1 += rb2[1]; s2 += rb2[2];
        int a = 0; float best = s0;
        if (s1 > best) { best = s1; a = 1; }
        if (s2 > best) { best = s2; a = 2; }
        g_skip[w] = (a == 0);
        atomicAdd(&g_cnt[a], 1);
    }
}

__global__ void scalars_kernel(float* out) {
    float fs = (float)g_cnt[0], ff = (float)g_cnt[1], fr = (float)g_cnt[2];
    out[(size_t)MM * VOC + 0] = (ff + fr) / (float)MM;
    out[(size_t)MM * VOC + 1] = fs / (float)(MM * NL);
    out[(size_t)MM * VOC + 2] = ff / (float)(MM * NL);
    out[(size_t)MM * VOC + 3] = fr / (float)(MM * NL);
}

extern "C" void kernel_launch(void* const* d_in, const int* in_sizes, int n_in,
                              void* d_out, int out_size) {
    const int*   x    = (const int*)d_in[0];
    const float* emb  = (const float*)d_in[1];
    const float* Wq   = (const float*)d_in[2];
    const float* bq   = (const float*)d_in[3];
    const float* Wk   = (const float*)d_in[4];
    const float* bk   = (const float*)d_in[5];
    const float* Wv   = (const float*)d_in[6];
    const float* bv   = (const float*)d_in[7];
    const float* Wo   = (const float*)d_in[8];
    const float* bo   = (const float*)d_in[9];
    const float* ln1g = (const float*)d_in[10];
    const float* ln1b = (const float*)d_in[11];
    const float* Wf1  = (const float*)d_in[12];
    const float* bf1  = (const float*)d_in[13];
    const float* Wf2  = (const float*)d_in[14];
    const float* bf2  = (const float*)d_in[15];
    const float* ln2g = (const float*)d_in[16];
    const float* ln2b = (const float*)d_in[17];
    const float* rW1  = (const float*)d_in[18];
    const float* rb1  = (const float*)d_in[19];
    const float* rW2  = (const float*)d_in[20];
    const float* rb2  = (const float*)d_in[21];
    const float* Wout = (const float*)d_in[22];
    const float* bout = (const float*)d_in[23];
    float* out = (float*)d_out;

    cudaFuncSetAttribute(tgemm_kernel, cudaFuncAttributeMaxDynamicSharedMemorySize, TGSM);
    cudaFuncSetAttribute(attn_scores_mma_kernel, cudaFuncAttributeMaxDynamicSharedMemorySize, SCSM);
    cudaFuncSetAttribute(attn_av_mma_kernel, cudaFuncAttributeMaxDynamicSharedMemorySize, AVSM);

    float *h, *h1, *t, *t2, *qkv, *a, *f1, *zr;
    float *wqh, *wql, *woh, *wol, *w1h, *w1l, *w2h, *w2l, *wvh, *wvl, *bqkv;
    cudaGetSymbolAddress((void**)&h, g_h);
    cudaGetSymbolAddress((void**)&h1, g_h1);
    cudaGetSymbolAddress((void**)&t, g_t);
    cudaGetSymbolAddress((void**)&t2, g_t2);
    cudaGetSymbolAddress((void**)&qkv, g_qkv);
    cudaGetSymbolAddress((void**)&a, g_a);
    cudaGetSymbolAddress((void**)&f1, g_f1);
    cudaGetSymbolAddress((void**)&zr, g_zr);
    cudaGetSymbolAddress((void**)&wqh, g_wqkv_h);
    cudaGetSymbolAddress((void**)&wql, g_wqkv_l);
    cudaGetSymbolAddress((void**)&woh, g_wo_h);
    cudaGetSymbolAddress((void**)&wol, g_wo_l);
    cudaGetSymbolAddress((void**)&w1h, g_wf1_h);
    cudaGetSymbolAddress((void**)&w1l, g_wf1_l);
    cudaGetSymbolAddress((void**)&w2h, g_wf2_h);
    cudaGetSymbolAddress((void**)&w2l, g_wf2_l);
    cudaGetSymbolAddress((void**)&wvh, g_wout_h);
    cudaGetSymbolAddress((void**)&wvl, g_wout_l);
    cudaGetSymbolAddress((void**)&bqkv, g_bqkv);

    wtrans_kernel<<<dim3(DD/32, DD/32), 256>>>(Wq, wqh, wql, DD, DD);
    wtrans_kernel<<<dim3(DD/32, DD/32), 256>>>(Wk, wqh + (size_t)1024*DD, wql + (size_t)1024*DD, DD, DD);
    wtrans_kernel<<<dim3(DD/32, DD/32), 256>>>(Wv, wqh + (size_t)2048*DD, wql + (size_t)2048*DD, DD, DD);
    wtrans_kernel<<<dim3(DD/32, DD/32), 256>>>(Wo, woh, wol, DD, DD);
    wtrans_kernel<<<dim3(DFF/32, DD/32), 256>>>(Wf1, w1h, w1l, DD, DFF);
    wtrans_kernel<<<dim3(DD/32, DFF/32), 256>>>(Wf2, w2h, w2l, DFF, DD);
    wtrans_kernel<<<dim3(VOC/32, DD/32), 256>>>(Wout, wvh, wvl, DD, VOC);
    bcat_kernel<<<QKVS/256, 256>>>(bq, bk, bv);

    zero_cnt_kernel<<<1, 32>>>();
    embed_kernel<<<MM, 256>>>(x, emb);

    for (int l = 0; l < NL; l++) {
        sgemm_kernel<<<dim3(RH/64, MM/128), 256>>>(h, rW1 + (size_t)l*DD*RH, rb1 + l*RH, zr, MM, RH, DD);
        router2_kernel<<<MM/8, 256>>>(rW2 + (size_t)l*RH*3, rb2 + l*3);
        compact_kernel<<<1, 1024>>>();
        tgemm_kernel<<<dim3(QKVS/128, MM/128, 1), 256, TGSM>>>(
            h, wqh, wql, bqkv, qkv, nullptr, MM, QKVS, DD, DD, 0, 0);
        attn_scores_mma_kernel<<<dim3(36, BHT), 256, SCSM>>>();
        softmax_kernel<<<BHT*SS, 256>>>();
        attn_av_mma_kernel<<<dim3(SS/128, BHT), 256, AVSM>>>();
        tgemm_kernel<<<dim3(DD/128, MM/128, 2), 256, TGSM>>>(
            a, woh, wol, nullptr, t, t2, MM, DD, DD/2, DD, 0, 1);
        ln_fused_kernel<<<MM, 256>>>(t, t2, h, bo, ln1g, ln1b, h1, 1, 0);
        tgemm_kernel<<<dim3(DFF/128, MM/128, 1), 256, TGSM>>>(
            h1, w1h, w1l, bf1, f1, nullptr, MM, DFF, DD, DD, 1, 2);
        tgemm_kernel<<<dim3(DD/128, MM/128, 2), 256, TGSM>>>(
            f1, w2h, w2l, nullptr, t, t2, MM, DD, DFF/2, DFF, 0, 2);
        ln_fused_kernel<<<MM, 256>>>(t, t2, h1, bf2, ln2g, ln2b, h, 0, 1);
    }

    tgemm_kernel<<<dim3(VOC/128, MM/128, 1), 256, TGSM>>>(
        h, wvh, wvl, bout, out, nullptr, MM, VOC, DD, DD, 0, 0);
    scalars_kernel<<<1, 1>>>(out);
}

// round 11
// speedup vs baseline: 1.0719x; 1.0719x over previous
#include <cuda_runtime.h>
#include <math.h>
#include <stdint.h>

#define BB 2
#define SS 1024
#define DD 1024
#define NH 16
#define HD 64
#define NL 12
#define DFF 4096
#define RH 128
#define VOC 32000
#define MM (BB*SS)
#define BHT (BB*NH)
#define QKVS 3072

// ---- static scratch ----
__device__ float g_h [MM*DD];
__device__ float g_h1[MM*DD];
__device__ float g_t [MM*DD];
__device__ float g_t2[MM*DD];
__device__ float g_qkv[MM*QKVS];
__device__ float g_a [MM*DD];
__device__ float g_f1[MM*DFF];
__device__ float g_zr[MM*RH];
__device__ float g_sc[(size_t)BHT*SS*SS];
__device__ unsigned char g_skip[MM];
__device__ int g_idx[MM];
__device__ int g_nact;
__device__ int g_cnt[3];
__device__ float g_wqkv_h[(size_t)QKVS*DD], g_wqkv_l[(size_t)QKVS*DD];
__device__ float g_wo_h[(size_t)DD*DD],     g_wo_l[(size_t)DD*DD];
__device__ float g_wf1_h[(size_t)DFF*DD],   g_wf1_l[(size_t)DFF*DD];
__device__ float g_wf2_h[(size_t)DD*DFF],   g_wf2_l[(size_t)DD*DFF];
__device__ float g_wout_h[(size_t)VOC*DD],  g_wout_l[(size_t)VOC*DD];
__device__ float g_bqkv[QKVS];

static __device__ __forceinline__ unsigned smem_u32(const void* p) {
    unsigned r;
    asm("{ .reg .u64 t; cvta.to.shared.u64 t, %1; cvt.u32.u64 %0, t; }" : "=r"(r) : "l"(p));
    return r;
}
static __device__ __forceinline__ float to_tf32f(float x) {
    float r; asm("cvt.rna.tf32.f32 %0, %1;" : "=f"(r) : "f"(x)); return r;
}
static __device__ __forceinline__ void mma8(float* c, const unsigned* a, const unsigned* b) {
    asm volatile(
        "mma.sync.aligned.m16n8k8.row.col.f32.tf32.tf32.f32 "
        "{%0,%1,%2,%3}, {%4,%5,%6,%7}, {%8,%9}, {%0,%1,%2,%3};"
        : "+f"(c[0]), "+f"(c[1]), "+f"(c[2]), "+f"(c[3])
        : "r"(a[0]), "r"(a[1]), "r"(a[2]), "r"(a[3]), "r"(b[0]), "r"(b[1]));
}
static __device__ __forceinline__ float4 hi4(float4 v) {
    return make_float4(to_tf32f(v.x), to_tf32f(v.y), to_tf32f(v.z), to_tf32f(v.w));
}
static __device__ __forceinline__ float4 lo4(float4 v, float4 h) {
    return make_float4(to_tf32f(v.x - h.x), to_tf32f(v.y - h.y),
                       to_tf32f(v.z - h.z), to_tf32f(v.w - h.w));
}
#define CP16(dst, src) \
    asm volatile("cp.async.cg.shared.global [%0], [%1], 16;" :: "r"(dst), "l"(src))

__global__ void zero_cnt_kernel() { if (threadIdx.x < 3) g_cnt[threadIdx.x] = 0; }

// deterministic compaction of active (non-skip) token indices
__global__ __launch_bounds__(1024) void compact_kernel() {
    __shared__ int ps[1024];
    int tid = threadIdx.x;
    int a0 = g_skip[2 * tid] ? 0 : 1;
    int a1 = g_skip[2 * tid + 1] ? 0 : 1;
    ps[tid] = a0 + a1;
    __syncthreads();
    for (int off = 1; off < 1024; off <<= 1) {
        int v = ps[tid];
        int add = (tid >= off) ? ps[tid - off] : 0;
        __syncthreads();
        ps[tid] = v + add;
        __syncthreads();
    }
    int base = ps[tid] - (a0 + a1);
    if (a0) g_idx[base] = 2 * tid;
    if (a1) g_idx[base + a0] = 2 * tid + 1;
    if (tid == 1023) g_nact = ps[1023];
}

// W[K][N] -> Th/Tl [N][K] with tf32 hi/lo split
__global__ __launch_bounds__(256) void wtrans_kernel(const float* __restrict__ W,
                                                     float* __restrict__ Th,
                                                     float* __restrict__ Tl, int K, int N) {
    __shared__ float tile[32][33];
    int n0 = blockIdx.x * 32, k0 = blockIdx.y * 32;
    int tx = threadIdx.x & 31, ty = threadIdx.x >> 5;
    for (int i = ty; i < 32; i += 8) tile[i][tx] = W[(size_t)(k0 + i) * N + n0 + tx];
    __syncthreads();
    for (int i = ty; i < 32; i += 8) {
        float v = tile[tx][i];
        float hv = to_tf32f(v);
        float lv = to_tf32f(v - hv);
        size_t o = (size_t)(n0 + i) * K + k0 + tx;
        Th[o] = hv; Tl[o] = lv;
    }
}

__global__ void bcat_kernel(const float* __restrict__ bq, const float* __restrict__ bk,
                            const float* __restrict__ bv) {
    int i = blockIdx.x * 256 + threadIdx.x;
    g_bqkv[i] = (i < 1024) ? bq[i] : (i < 2048) ? bk[i - 1024] : bv[i - 2048];
}

__global__ __launch_bounds__(256) void embed_kernel(const int* __restrict__ x,
                                                    const float* __restrict__ emb) {
    int tok = blockIdx.x, s = tok % SS, id = x[tok];
    int d0 = threadIdx.x * 4;
    float4 ev = *(const float4*)(emb + (size_t)id * DD + d0);
    float o[4] = {ev.x, ev.y, ev.z, ev.w};
#pragma unroll
    for (int j = 0; j < 4; j++) {
        int d = d0 + j;
        float ang = (float)s * expf((float)(d & ~1) * (-9.210340371976184f / 1024.0f));
        o[j] = o[j] * 32.0f + ((d & 1) ? cosf(ang) : sinf(ang));
    }
    *(float4*)(g_h + (size_t)tok * DD + d0) = make_float4(o[0], o[1], o[2], o[3]);
}

// ===== mma.sync 3xTF32 GEMM, split-K + row compaction =====
#define KCH 16
#define ROWW 20
#define MATB (128*ROWW*4)
#define STGB (3*MATB)
#define TGSM (3*STGB)

__global__ __launch_bounds__(256, 2)
void tgemm_kernel(const float* __restrict__ A, const float* __restrict__ Bh,
                  const float* __restrict__ Bl, const float* __restrict__ bias,
                  float* __restrict__ C0, float* __restrict__ C1,
                  int M, int N, int Ksub, int ldk, int relu, int mode) {
    extern __shared__ char smem[];
    unsigned sb = smem_u32(smem);
    int bm = blockIdx.y * 128, bn = blockIdx.x * 128;
    int Meff = M;
    if (mode) {
        Meff = g_nact;
        if (bm >= Meff) return;
    }
    int z = blockIdx.z;
    A  += (size_t)z * Ksub;
    Bh += (size_t)z * Ksub;
    Bl += (size_t)z * Ksub;
    float* C = z ? C1 : C0;
    int tid = threadIdx.x, wid = tid >> 5, lane = tid & 31;
    int grp = lane >> 2, qid = lane & 3;
    int wm0 = (wid & 3) * 32, wn0 = (wid >> 2) * 64;

    float acc[2][8][4];
#pragma unroll
    for (int mt = 0; mt < 2; mt++)
#pragma unroll
        for (int nt = 0; nt < 8; nt++)
#pragma unroll
            for (int e = 0; e < 4; e++) acc[mt][nt][e] = 0.f;

    int nchunks = Ksub / KCH;
    int r0 = tid >> 2, kc0 = (tid & 3) * 16;
    int r1 = (tid + 256) >> 2, kc1 = ((tid + 256) & 3) * 16;

    const float *Ar0, *Ar1;
    {
        int rr0 = bm + r0, rr1 = bm + r1;
        if (mode == 1) {
            rr0 = g_idx[rr0 < Meff ? rr0 : Meff - 1];
            rr1 = g_idx[rr1 < Meff ? rr1 : Meff - 1];
        }
        Ar0 = A + (size_t)rr0 * ldk;
        Ar1 = A + (size_t)rr1 * ldk;
    }

#pragma unroll
    for (int c = 0; c < 2; c++) {
        int kb = c * KCH;
        unsigned st = sb + (c % 3) * STGB;
        CP16(st + r0 * 80 + kc0, Ar0 + kb + kc0 / 4);
        CP16(st + r1 * 80 + kc1, Ar1 + kb + kc1 / 4);
        CP16(st + MATB + r0 * 80 + kc0, Bh + (size_t)(bn + r0) * ldk + kb + kc0 / 4);
        CP16(st + MATB + r1 * 80 + kc1, Bh + (size_t)(bn + r1) * ldk + kb + kc1 / 4);
        CP16(st + 2 * MATB + r0 * 80 + kc0, Bl + (size_t)(bn + r0) * ldk + kb + kc0 / 4);
        CP16(st + 2 * MATB + r1 * 80 + kc1, Bl + (size_t)(bn + r1) * ldk + kb + kc1 / 4);
        asm volatile("cp.async.commit_group;");
    }

    for (int c = 0; c < nchunks; c++) {
        if (c + 2 < nchunks) asm volatile("cp.async.wait_group 1;");
        else                 asm volatile("cp.async.wait_group 0;");
        __syncthreads();
        const float* As  = (const float*)(smem + (c % 3) * STGB);
        const float* Bhs = As + 128 * ROWW;
        const float* Bls = Bhs + 128 * ROWW;
#pragma unroll
        for (int s8 = 0; s8 < 2; s8++) {
            int k8 = s8 * 8;
            unsigned Ah[2][4], Al[2][4];
#pragma unroll
            for (int mt = 0; mt < 2; mt++) {
                int ra = wm0 + mt * 16 + grp;
                float x0 = As[ra * ROWW + k8 + qid];
                float x1 = As[(ra + 8) * ROWW + k8 + qid];
                float x2 = As[ra * ROWW + k8 + qid + 4];
                float x3 = As[(ra + 8) * ROWW + k8 + qid + 4];
                float h0 = to_tf32f(x0), h1 = to_tf32f(x1), h2 = to_tf32f(x2), h3 = to_tf32f(x3);
                Ah[mt][0] = __float_as_uint(h0); Ah[mt][1] = __float_as_uint(h1);
                Ah[mt][2] = __float_as_uint(h2); Ah[mt][3] = __float_as_uint(h3);
                Al[mt][0] = __float_as_uint(to_tf32f(x0 - h0));
                Al[mt][1] = __float_as_uint(to_tf32f(x1 - h1));
                Al[mt][2] = __float_as_uint(to_tf32f(x2 - h2));
                Al[mt][3] = __float_as_uint(to_tf32f(x3 - h3));
            }
#pragma unroll
            for (int nt = 0; nt < 8; nt++) {
                int nr = wn0 + nt * 8 + grp;
                unsigned bh[2], bl[2];
                bh[0] = __float_as_uint(Bhs[nr * ROWW + k8 + qid]);
                bh[1] = __float_as_uint(Bhs[nr * ROWW + k8 + qid + 4]);
                bl[0] = __float_as_uint(Bls[nr * ROWW + k8 + qid]);
                bl[1] = __float_as_uint(Bls[nr * ROWW + k8 + qid + 4]);
#pragma unroll
                for (int mt = 0; mt < 2; mt++) {
                    mma8(acc[mt][nt], Ah[mt], bh);
                    mma8(acc[mt][nt], Ah[mt], bl);
                    mma8(acc[mt][nt], Al[mt], bh);
                }
            }
        }
        __syncthreads();
        if (c + 2 < nchunks) {
            int kb = (c + 2) * KCH;
            unsigned st = sb + ((c + 2) % 3) * STGB;
            CP16(st + r0 * 80 + kc0, Ar0 + kb + kc0 / 4);
            CP16(st + r1 * 80 + kc1, Ar1 + kb + kc1 / 4);
            CP16(st + MATB + r0 * 80 + kc0, Bh + (size_t)(bn + r0) * ldk + kb + kc0 / 4);
            CP16(st + MATB + r1 * 80 + kc1, Bh + (size_t)(bn + r1) * ldk + kb + kc1 / 4);
            CP16(st + 2 * MATB + r0 * 80 + kc0, Bl + (size_t)(bn + r0) * ldk + kb + kc0 / 4);
            CP16(st + 2 * MATB + r1 * 80 + kc1, Bl + (size_t)(bn + r1) * ldk + kb + kc1 / 4);
            asm volatile("cp.async.commit_group;");
        }
    }

#pragma unroll
    for (int mt = 0; mt < 2; mt++) {
#pragma unroll
        for (int nt = 0; nt < 8; nt++) {
            int row0 = bm + wm0 + mt * 16 + grp;
            int col = bn + wn0 + nt * 8 + 2 * qid;
            float2 v0 = make_float2(acc[mt][nt][0], acc[mt][nt][1]);
            float2 v1 = make_float2(acc[mt][nt][2], acc[mt][nt][3]);
            if (bias) {
                float2 bv = *(const float2*)(bias + col);
                v0.x += bv.x; v0.y += bv.y; v1.x += bv.x; v1.y += bv.y;
            }
            if (relu) {
                v0.x = fmaxf(v0.x, 0.f); v0.y = fmaxf(v0.y, 0.f);
                v1.x = fmaxf(v1.x, 0.f); v1.y = fmaxf(v1.y, 0.f);
            }
            if (row0 < Meff)
                *(float2*)(C + (size_t)row0 * N + col) = v0;
            if (row0 + 8 < Meff)
                *(float2*)(C + (size_t)(row0 + 8) * N + col) = v1;
        }
    }
}

// ===== tensor-core attention scores (Q pre-scaled by 1/8 at staging) =====
#define ASTR 68
#define SCSM (4*128*ASTR*4)

__global__ __launch_bounds__(256)
void attn_scores_mma_kernel() {
    int t = blockIdx.x;
    int qt = (int)((sqrtf(8.f * t + 1.f) - 1.f) * 0.5f);
    while ((qt + 1) * (qt + 2) / 2 <= t) qt++;
    while (qt * (qt + 1) / 2 > t) qt--;
    int kt = t - qt * (qt + 1) / 2;
    int bh = blockIdx.y;
    int b = bh >> 4, hh = bh & 15;

    extern __shared__ float sm[];
    float* QH = sm;
    float* QL = QH + 128 * ASTR;
    float* KH = QL + 128 * ASTR;
    float* KL = KH + 128 * ASTR;

    int tid = threadIdx.x, wid = tid >> 5, lane = tid & 31;
    int grp = lane >> 2, qid = lane & 3;
    int wm0 = (wid & 3) * 32, wn0 = (wid >> 2) * 64;

    const float* qb = g_qkv + ((size_t)(b * SS + qt * 128)) * QKVS + hh * HD;
    const float* kb = g_qkv + ((size_t)(b * SS + kt * 128)) * QKVS + 1024 + hh * HD;
    for (int i = tid; i < 128 * 16; i += 256) {
        int row = i >> 4, c4 = (i & 15) * 4;
        float4 v = *(const float4*)(qb + (size_t)row * QKVS + c4);
        v.x *= 0.125f; v.y *= 0.125f; v.z *= 0.125f; v.w *= 0.125f;  // exact pow2
        float4 h = hi4(v);
        *(float4*)(QH + row * ASTR + c4) = h;
        *(float4*)(QL + row * ASTR + c4) = lo4(v, h);
        float4 w = *(const float4*)(kb + (size_t)row * QKVS + c4);
        float4 wh = hi4(w);
        *(float4*)(KH + row * ASTR + c4) = wh;
        *(float4*)(KL + row * ASTR + c4) = lo4(w, wh);
    }
    __syncthreads();

    float acc[2][8][4];
#pragma unroll
    for (int mt = 0; mt < 2; mt++)
#pragma unroll
        for (int nt = 0; nt < 8; nt++)
#pragma unroll
            for (int e = 0; e < 4; e++) acc[mt][nt][e] = 0.f;

#pragma unroll
    for (int s = 0; s < 8; s++) {
        int k8 = s * 8;
        unsigned Ah[2][4], Al[2][4];
#pragma unroll
        for (int mt = 0; mt < 2; mt++) {
            int ra = wm0 + mt * 16 + grp;
            Ah[mt][0] = __float_as_uint(QH[ra * ASTR + k8 + qid]);
            Ah[mt][1] = __float_as_uint(QH[(ra + 8) * ASTR + k8 + qid]);
            Ah[mt][2] = __float_as_uint(QH[ra * ASTR + k8 + qid + 4]);
            Ah[mt][3] = __float_as_uint(QH[(ra + 8) * ASTR + k8 + qid + 4]);
            Al[mt][0] = __float_as_uint(QL[ra * ASTR + k8 + qid]);
            Al[mt][1] = __float_as_uint(QL[(ra + 8) * ASTR + k8 + qid]);
            Al[mt][2] = __float_as_uint(QL[ra * ASTR + k8 + qid + 4]);
            Al[mt][3] = __float_as_uint(QL[(ra + 8) * ASTR + k8 + qid + 4]);
        }
#pragma unroll
        for (int nt = 0; nt < 8; nt++) {
            int nr = wn0 + nt * 8 + grp;
            unsigned bh2[2], bl2[2];
            bh2[0] = __float_as_uint(KH[nr * ASTR + k8 + qid]);
            bh2[1] = __float_as_uint(KH[nr * ASTR + k8 + qid + 4]);
            bl2[0] = __float_as_uint(KL[nr * ASTR + k8 + qid]);
            bl2[1] = __float_as_uint(KL[nr * ASTR + k8 + qid + 4]);
#pragma unroll
            for (int mt = 0; mt < 2; mt++) {
                mma8(acc[mt][nt], Ah[mt], bh2);
                mma8(acc[mt][nt], Ah[mt], bl2);
                mma8(acc[mt][nt], Al[mt], bh2);
            }
        }
    }

    bool diag = (kt == qt);
#pragma unroll
    for (int mt = 0; mt < 2; mt++) {
#pragma unroll
        for (int nt = 0; nt < 8; nt++) {
            int r0 = qt * 128 + wm0 + mt * 16 + grp;
            int c0 = kt * 128 + wn0 + nt * 8 + 2 * qid;
            float v0 = acc[mt][nt][0], v1 = acc[mt][nt][1];
            float v2 = acc[mt][nt][2], v3 = acc[mt][nt][3];
            if (diag) {
                if (c0 > r0)     v0 = -1e30f;
                if (c0 + 1 > r0) v1 = -1e30f;
                if (c0 > r0 + 8)     v2 = -1e30f;
                if (c0 + 1 > r0 + 8) v3 = -1e30f;
            }
            float* p0 = g_sc + ((size_t)bh * SS + r0) * SS + c0;
            *(float2*)p0 = make_float2(v0, v1);
            *(float2*)(p0 + 8 * SS) = make_float2(v2, v3);
        }
    }
}

// ===== prefix softmax =====
__global__ __launch_bounds__(256) void softmax_kernel() {
    int row = blockIdx.x;
    int qr = row & (SS - 1);
    int L = ((qr >> 7) + 1) << 7;
    float* sc = g_sc + (size_t)row * SS;
    int tid = threadIdx.x;
    bool valid = (tid * 4 < L);
    float4 v = valid ? *(float4*)&sc[tid * 4] : make_float4(-1e30f, -1e30f, -1e30f, -1e30f);
    __shared__ float red[8];
    __shared__ float stat;
    float m = fmaxf(fmaxf(v.x, v.y), fmaxf(v.z, v.w));
    for (int o = 16; o; o >>= 1) m = fmaxf(m, __shfl_down_sync(~0u, m, o));
    if ((tid & 31) == 0) red[tid >> 5] = m;
    __syncthreads();
    if (tid == 0) {
        float t = red[0];
        for (int i = 1; i < 8; i++) t = fmaxf(t, red[i]);
        stat = t;
    }
    __syncthreads();
    float mx = stat;
    float e0 = expf(v.x - mx), e1 = expf(v.y - mx), e2 = expf(v.z - mx), e3 = expf(v.w - mx);
    float s = e0 + e1 + e2 + e3;
    for (int o = 16; o; o >>= 1) s += __shfl_down_sync(~0u, s, o);
    __syncthreads();
    if ((tid & 31) == 0) red[tid >> 5] = s;
    __syncthreads();
    if (tid == 0) {
        float t = 0.f;
        for (int i = 0; i < 8; i++) t += red[i];
        stat = t;
    }
    __syncthreads();
    float inv = 1.0f / stat;
    if (valid) *(float4*)&sc[tid * 4] = make_float4(e0 * inv, e1 * inv, e2 * inv, e3 * inv);
}

// ===== tensor-core AV: raw double-buffered cp.async staging, register hi/lo split ====
#define PSTR 68
#define VSTR 72
#define PBYT (128*PSTR*4)
#define VBYT (64*VSTR*4)
#define AVSTG (PBYT + VBYT)
#define AVSM (2*AVSTG)

__global__ __launch_bounds__(256)
void attn_av_mma_kernel() {
    int qt = blockIdx.x, bh = blockIdx.y;
    int b = bh >> 4, hh = bh & 15;

    extern __shared__ char smc[];
    unsigned sb = smem_u32(smc);

    int tid = threadIdx.x, wid = tid >> 5, lane = tid & 31;
    int grp = lane >> 2, qid = lane & 3;
    int wm0 = (wid & 3) * 32, wn0 = (wid >> 2) * 32;

    float acc[2][4][4];
#pragma unroll
    for (int mt = 0; mt < 2; mt++)
#pragma unroll
        for (int nt = 0; nt < 4; nt++)
#pragma unroll
            for (int e = 0; e < 4; e++) acc[mt][nt][e] = 0.f;

    int nchunks = (qt + 1) * 2;
    const float* pbase = g_sc + ((size_t)bh * SS + qt * 128) * SS;
    const float* vbase = g_qkv + ((size_t)(b * SS)) * QKVS + 2048 + hh * HD;

    // prologue: stage chunk 0 into buffer 0
    {
        unsigned stP = sb;
        unsigned stV = sb + PBYT;
        const float* pb = pbase;
        const float* vb = vbase;
#pragma unroll
        for (int it = 0; it < 8; it++) {
            int idx = tid + it * 256;
            int row = idx >> 4, c4 = (idx & 15) * 4;
            CP16(stP + (row * PSTR + c4) * 4, pb + (size_t)row * SS + c4);
        }
#pragma unroll
        for (int it = 0; it < 4; it++) {
            int idx = tid + it * 256;
            int tok = idx >> 4, d4 = (idx & 15) * 4;
            CP16(stV + (tok * VSTR + d4) * 4, vb + (size_t)tok * QKVS + d4);
        }
        asm volatile("cp.async.commit_group;");
    }

    for (int kc = 0; kc < nchunks; kc++) {
        if (kc + 1 < nchunks) {
            unsigned st = sb + ((kc + 1) & 1) * AVSTG;
            unsigned stP = st, stV = st + PBYT;
            const float* pb = pbase + (kc + 1) * 64;
            const float* vb = vbase + (size_t)(kc + 1) * 64 * QKVS;
#pragma unroll
            for (int it = 0; it < 8; it++) {
                int idx = tid + it * 256;
                int row = idx >> 4, c4 = (idx & 15) * 4;
                CP16(stP + (row * PSTR + c4) * 4, pb + (size_t)row * SS + c4);
            }
#pragma unroll
            for (int it = 0; it < 4; it++) {
                int idx = tid + it * 256;
                int tok = idx >> 4, d4 = (idx & 15) * 4;
                CP16(stV + (tok * VSTR + d4) * 4, vb + (size_t)tok * QKVS + d4);
            }
            asm volatile("cp.async.commit_group;");
            asm volatile("cp.async.wait_group 1;");
        } else {
            asm volatile("cp.async.wait_group 0;");
        }
        __syncthreads();

        const float* Pr = (const float*)(smc + (kc & 1) * AVSTG);
        const float* Vr = Pr + 128 * PSTR;

#pragma unroll
        for (int s = 0; s < 8; s++) {
            int k8 = s * 8;
            unsigned Ah[2][4], Al[2][4];
#pragma unroll
            for (int mt = 0; mt < 2; mt++) {
                int ra = wm0 + mt * 16 + grp;
                float x0 = Pr[ra * PSTR + k8 + qid];
                float x1 = Pr[(ra + 8) * PSTR + k8 + qid];
                float x2 = Pr[ra * PSTR + k8 + qid + 4];
                float x3 = Pr[(ra + 8) * PSTR + k8 + qid + 4];
                float h0 = to_tf32f(x0), h1 = to_tf32f(x1), h2 = to_tf32f(x2), h3 = to_tf32f(x3);
                Ah[mt][0] = __float_as_uint(h0); Ah[mt][1] = __float_as_uint(h1);
                Ah[mt][2] = __float_as_uint(h2); Ah[mt][3] = __float_as_uint(h3);
                Al[mt][0] = __float_as_uint(to_tf32f(x0 - h0));
                Al[mt][1] = __float_as_uint(to_tf32f(x1 - h1));
                Al[mt][2] = __float_as_uint(to_tf32f(x2 - h2));
                Al[mt][3] = __float_as_uint(to_tf32f(x3 - h3));
            }
#pragma unroll
            for (int nt = 0; nt < 4; nt++) {
                int nr = wn0 + nt * 8 + grp;
                float y0 = Vr[(k8 + qid) * VSTR + nr];
                float y1 = Vr[(k8 + qid + 4) * VSTR + nr];
                float g0 = to_tf32f(y0), g1 = to_tf32f(y1);
                unsigned bh2[2] = {__float_as_uint(g0), __float_as_uint(g1)};
                unsigned bl2[2] = {__float_as_uint(to_tf32f(y0 - g0)),
                                   __float_as_uint(to_tf32f(y1 - g1))};
#pragma unroll
                for (int mt = 0; mt < 2; mt++) {
                    mma8(acc[mt][nt], Ah[mt], bh2);
                    mma8(acc[mt][nt], Ah[mt], bl2);
                    mma8(acc[mt][nt], Al[mt], bh2);
                }
            }
        }
        __syncthreads();
    }

#pragma unroll
    for (int mt = 0; mt < 2; mt++) {
#pragma unroll
        for (int nt = 0; nt < 4; nt++) {
            int r0 = qt * 128 + wm0 + mt * 16 + grp;
            int c0 = hh * HD + wn0 + nt * 8 + 2 * qid;
            float* p0 = g_a + ((size_t)(b * SS) + r0) * DD + c0;
            *(float2*)p0 = make_float2(acc[mt][nt][0], acc[mt][nt][1]);
            *(float2*)(p0 + 8 * DD) = make_float2(acc[mt][nt][2], acc[mt][nt][3]);
        }
    }
}

// ===== SIMT SGEMM (router GEMM1) =====
__global__ __launch_bounds__(256) void sgemm_kernel(const float* __restrict__ A,
                                                    const float* __restrict__ B,
                                                    const float* __restrict__ bias,
                                                    float* __restrict__ C,
                                                    int M, int N, int K) {
    __shared__ float Ast[16][128];
    __shared__ float Bs[16][64];
    int tid = threadIdx.x;
    int bm = blockIdx.y * 128, bn = blockIdx.x * 64;
    int tx = tid & 15, ty = tid >> 4;
    int m0 = ty * 8, n0 = tx * 4;
    float acc[8][4];
#pragma unroll
    for (int i = 0; i < 8; i++)
#pragma unroll
        for (int j = 0; j < 4; j++) acc[i][j] = 0.f;
    int arow = tid >> 2, ak4 = (tid & 3) * 4, bk = tid >> 4, bc4 = (tid & 15) * 4;
    for (int kb = 0; kb < K; kb += 16) {
#pragma unroll
        for (int p = 0; p < 2; p++) {
            int r = arow + p * 64;
            float4 av = *(const float4*)(A + (size_t)(bm + r) * K + kb + ak4);
            Ast[ak4+0][r] = av.x; Ast[ak4+1][r] = av.y; Ast[ak4+2][r] = av.z; Ast[ak4+3][r] = av.w;
        }
        *(float4*)&Bs[bk][bc4] = *(const float4*)(B + (size_t)(kb + bk) * N + bn + bc4);
        __syncthreads();
#pragma unroll
        for (int k = 0; k < 16; k++) {
            float4 a0 = *(float4*)&Ast[k][m0];
            float4 a1 = *(float4*)&Ast[k][m0 + 4];
            float4 bv = *(float4*)&Bs[k][n0];
            float am[8] = {a0.x,a0.y,a0.z,a0.w,a1.x,a1.y,a1.z,a1.w};
            float bb[4] = {bv.x,bv.y,bv.z,bv.w};
#pragma unroll
            for (int i = 0; i < 8; i++)
#pragma unroll
                for (int j = 0; j < 4; j++) acc[i][j] += am[i] * bb[j];
        }
        __syncthreads();
    }
#pragma unroll
    for (int i = 0; i < 8; i++)
#pragma unroll
        for (int j = 0; j < 4; j++) {
            float v = acc[i][j] + bias[bn + n0 + j];
            C[(size_t)(bm + m0 + i) * N + bn + n0 + j] = fmaxf(v, 0.f);
        }
}

// ===== fused LN on compact rows =====
__global__ __launch_bounds__(256) void ln_fused_kernel(const float* __restrict__ in0,
                                                       const float* __restrict__ in1,
                                                       const float* __restrict__ res,
                                                       const float* __restrict__ bias,
                                                       const float* __restrict__ g,
                                                       const float* __restrict__ bsh,
                                                       float* __restrict__ out,
                                                       int resGather, int outScatter) {
    int row = blockIdx.x;
    if (row >= g_nact) return;
    int orow = g_idx[row];
    size_t inoff = (size_t)row * DD;
    size_t resoff = (size_t)(resGather ? orow : row) * DD;
    size_t outoff = (size_t)(outScatter ? orow : row) * DD;
    int tid = threadIdx.x;
    float4 v = *(const float4*)&in0[inoff + tid * 4];
    float4 w = *(const float4*)&in1[inoff + tid * 4];
    float4 r = *(const float4*)&res[resoff + tid * 4];
    float4 bv = *(const float4*)&bias[tid * 4];
    v.x += w.x + r.x + bv.x; v.y += w.y + r.y + bv.y;
    v.z += w.z + r.z + bv.z; v.w += w.w + r.w + bv.w;
    __shared__ float red[8];
    __shared__ float stat;
    float s = v.x + v.y + v.z + v.w;
    for (int o = 16; o; o >>= 1) s += __shfl_down_sync(~0u, s, o);
    if ((tid & 31) == 0) red[tid >> 5] = s;
    __syncthreads();
    if (tid == 0) {
        float t = 0.f;
        for (int i = 0; i < 8; i++) t += red[i];
        stat = t * (1.0f / DD);
    }
    __syncthreads();
    float mu = stat;
    float dx = v.x - mu, dy = v.y - mu, dz = v.z - mu, dw = v.w - mu;
    float ss = dx * dx + dy * dy + dz * dz + dw * dw;
    for (int o = 16; o; o >>= 1) ss += __shfl_down_sync(~0u, ss, o);
    __syncthreads();
    if ((tid & 31) == 0) red[tid >> 5] = ss;
    __syncthreads();
    if (tid == 0) {
        float t = 0.f;
        for (int i = 0; i < 8; i++) t += red[i];
        stat = rsqrtf(t * (1.0f / DD) + 1e-5f);
    }
    __syncthreads();
    float rs = stat;
    float4 gg = *(const float4*)&g[tid * 4];
    float4 bb = *(const float4*)&bsh[tid * 4];
    *(float4*)&out[outoff + tid * 4] =
        make_float4(dx * rs * gg.x + bb.x, dy * rs * gg.y + bb.y,
                    dz * rs * gg.z + bb.z, dw * rs * gg.w + bb.w);
}

__global__ __launch_bounds__(256) void router2_kernel(const float* __restrict__ rw2,
                                                      const float* __restrict__ rb2) {
    int w = (blockIdx.x * blockDim.x + threadIdx.x) >> 5;
    int lane = threadIdx.x & 31;
    if (w >= MM) return;
    const float* z = g_zr + (size_t)w * RH;
    float s0 = 0.f, s1 = 0.f, s2 = 0.f;
#pragma unroll
    for (int u = 0; u < 4; u++) {
        int j = lane + 32 * u;
        float zv = z[j];
        s0 += zv * rw2[j * 3 + 0];
        s1 += zv * rw2[j * 3 + 1];
        s2 += zv * rw2[j * 3 + 2];
    }
    for (int o = 16; o; o >>= 1) {
        s0 += __shfl_down_sync(~0u, s0, o);
        s1 += __shfl_down_sync(~0u, s1, o);
        s2 += __shfl_down_sync(~0u, s2, o);
    }
    if (lane == 0) {
        s0 += rb2[0]; s1 += rb2[1]; s2 += rb2[2];
        int a = 0; float best = s0;
        if (s1 > best) { best = s1; a = 1; }
        if (s2 > best) { best = s2; a = 2; }
        g_skip[w] = (a == 0);
        atomicAdd(&g_cnt[a], 1);
    }
}

__global__ void scalars_kernel(float* out) {
    float fs = (float)g_cnt[0], ff = (float)g_cnt[1], fr = (float)g_cnt[2];
    out[(size_t)MM * VOC + 0] = (ff + fr) / (float)MM;
    out[(size_t)MM * VOC + 1] = fs / (float)(MM * NL);
    out[(size_t)MM * VOC + 2] = ff / (float)(MM * NL);
    out[(size_t)MM * VOC + 3] = fr / (float)(MM * NL);
}

extern "C" void kernel_launch(void* const* d_in, const int* in_sizes, int n_in,
                              void* d_out, int out_size) {
    const int*   x    = (const int*)d_in[0];
    const float* emb  = (const float*)d_in[1];
    const float* Wq   = (const float*)d_in[2];
    const float* bq   = (const float*)d_in[3];
    const float* Wk   = (const float*)d_in[4];
    const float* bk   = (const float*)d_in[5];
    const float* Wv   = (const float*)d_in[6];
    const float* bv   = (const float*)d_in[7];
    const float* Wo   = (const float*)d_in[8];
    const float* bo   = (const float*)d_in[9];
    const float* ln1g = (const float*)d_in[10];
    const float* ln1b = (const float*)d_in[11];
    const float* Wf1  = (const float*)d_in[12];
    const float* bf1  = (const float*)d_in[13];
    const float* Wf2  = (const float*)d_in[14];
    const float* bf2  = (const float*)d_in[15];
    const float* ln2g = (const float*)d_in[16];
    const float* ln2b = (const float*)d_in[17];
    const float* rW1  = (const float*)d_in[18];
    const float* rb1  = (const float*)d_in[19];
    const float* rW2  = (const float*)d_in[20];
    const float* rb2  = (const float*)d_in[21];
    const float* Wout = (const float*)d_in[22];
    const float* bout = (const float*)d_in[23];
    float* out = (float*)d_out;

    cudaFuncSetAttribute(tgemm_kernel, cudaFuncAttributeMaxDynamicSharedMemorySize, TGSM);
    cudaFuncSetAttribute(attn_scores_mma_kernel, cudaFuncAttributeMaxDynamicSharedMemorySize, SCSM);
    cudaFuncSetAttribute(attn_av_mma_kernel, cudaFuncAttributeMaxDynamicSharedMemorySize, AVSM);

    float *h, *h1, *t, *t2, *qkv, *a, *f1, *zr;
    float *wqh, *wql, *woh, *wol, *w1h, *w1l, *w2h, *w2l, *wvh, *wvl, *bqkv;
    cudaGetSymbolAddress((void**)&h, g_h);
    cudaGetSymbolAddress((void**)&h1, g_h1);
    cudaGetSymbolAddress((void**)&t, g_t);
    cudaGetSymbolAddress((void**)&t2, g_t2);
    cudaGetSymbolAddress((void**)&qkv, g_qkv);
    cudaGetSymbolAddress((void**)&a, g_a);
    cudaGetSymbolAddress((void**)&f1, g_f1);
    cudaGetSymbolAddress((void**)&zr, g_zr);
    cudaGetSymbolAddress((void**)&wqh, g_wqkv_h);
    cudaGetSymbolAddress((void**)&wql, g_wqkv_l);
    cudaGetSymbolAddress((void**)&woh, g_wo_h);
    cudaGetSymbolAddress((void**)&wol, g_wo_l);
    cudaGetSymbolAddress((void**)&w1h, g_wf1_h);
    cudaGetSymbolAddress((void**)&w1l, g_wf1_l);
    cudaGetSymbolAddress((void**)&w2h, g_wf2_h);
    cudaGetSymbolAddress((void**)&w2l, g_wf2_l);
    cudaGetSymbolAddress((void**)&wvh, g_wout_h);
    cudaGetSymbolAddress((void**)&wvl, g_wout_l);
    cudaGetSymbolAddress((void**)&bqkv, g_bqkv);

    wtrans_kernel<<<dim3(DD/32, DD/32), 256>>>(Wq, wqh, wql, DD, DD);
    wtrans_kernel<<<dim3(DD/32, DD/32), 256>>>(Wk, wqh + (size_t)1024*DD, wql + (size_t)1024*DD, DD, DD);
    wtrans_kernel<<<dim3(DD/32, DD/32), 256>>>(Wv, wqh + (size_t)2048*DD, wql + (size_t)2048*DD, DD, DD);
    wtrans_kernel<<<dim3(DD/32, DD/32), 256>>>(Wo, woh, wol, DD, DD);
    wtrans_kernel<<<dim3(DFF/32, DD/32), 256>>>(Wf1, w1h, w1l, DD, DFF);
    wtrans_kernel<<<dim3(DD/32, DFF/32), 256>>>(Wf2, w2h, w2l, DFF, DD);
    wtrans_kernel<<<dim3(VOC/32, DD/32), 256>>>(Wout, wvh, wvl, DD, VOC);
    bcat_kernel<<<QKVS/256, 256>>>(bq, bk, bv);

    zero_cnt_kernel<<<1, 32>>>();
    embed_kernel<<<MM, 256>>>(x, emb);

    for (int l = 0; l < NL; l++) {
        sgemm_kernel<<<dim3(RH/64, MM/128), 256>>>(h, rW1 + (size_t)l*DD*RH, rb1 + l*RH, zr, MM, RH, DD);
        router2_kernel<<<MM/8, 256>>>(rW2 + (size_t)l*RH*3, rb2 + l*3);
        compact_kernel<<<1, 1024>>>();
        tgemm_kernel<<<dim3(QKVS/128, MM/128, 1), 256, TGSM>>>(
            h, wqh, wql, bqkv, qkv, nullptr, MM, QKVS, DD, DD, 0, 0);
        attn_scores_mma_kernel<<<dim3(36, BHT), 256, SCSM>>>();
        softmax_kernel<<<BHT*SS, 256>>>();
        attn_av_mma_kernel<<<dim3(SS/128, BHT), 256, AVSM>>>();
        tgemm_kernel<<<dim3(DD/128, MM/128, 2), 256, TGSM>>>(
            a, woh, wol, nullptr, t, t2, MM, DD, DD/2, DD, 0, 1);
        ln_fused_kernel<<<MM, 256>>>(t, t2, h, bo, ln1g, ln1b, h1, 1, 0);
        tgemm_kernel<<<dim3(DFF/128, MM/128, 1), 256, TGSM>>>(
            h1, w1h, w1l, bf1, f1, nullptr, MM, DFF, DD, DD, 1, 2);
        tgemm_kernel<<<dim3(DD/128, MM/128, 2), 256, TGSM>>>(
            f1, w2h, w2l, nullptr, t, t2, MM, DD, DFF/2, DFF, 0, 2);
        ln_fused_kernel<<<MM, 256>>>(t, t2, h1, bf2, ln2g, ln2b, h, 0, 1);
    }

    tgemm_kernel<<<dim3(VOC/128, MM/128, 1), 256, TGSM>>>(
        h, wvh, wvl, bout, out, nullptr, MM, VOC, DD, DD, 0, 0);
    scalars_kernel<<<1, 1>>>(out);
}

// round 12
// speedup vs baseline: 1.0763x; 1.0041x over previous
#include <cuda_runtime.h>
#include <math.h>
#include <stdint.h>

#define BB 2
#define SS 1024
#define DD 1024
#define NH 16
#define HD 64
#define NL 12
#define DFF 4096
#define RH 128
#define VOC 32000
#define MM (BB*SS)
#define BHT (BB*NH)
#define QKVS 3072
#define NPERS 296          // persistent grid = 148 SMs x occ 2

// ---- static scratch ----
__device__ float g_h [MM*DD];
__device__ float g_h1[MM*DD];
__device__ float g_tp[4*MM*DD];          // split-K partials (4 planes)
__device__ float g_qkv[MM*QKVS];
__device__ float g_a [MM*DD];
__device__ float g_f1[MM*DFF];
__device__ float g_zr[MM*RH];
__device__ float g_sc[(size_t)BHT*SS*SS];
__device__ unsigned char g_skip[MM];
__device__ int g_idx[MM];
__device__ int g_nact;
__device__ int g_cnt[3];
__device__ float g_wqkv_h[(size_t)QKVS*DD], g_wqkv_l[(size_t)QKVS*DD];
__device__ float g_wo_h[(size_t)DD*DD],     g_wo_l[(size_t)DD*DD];
__device__ float g_wf1_h[(size_t)DFF*DD],   g_wf1_l[(size_t)DFF*DD];
__device__ float g_wf2_h[(size_t)DD*DFF],   g_wf2_l[(size_t)DD*DFF];
__device__ float g_wout_h[(size_t)VOC*DD],  g_wout_l[(size_t)VOC*DD];
__device__ float g_bqkv[QKVS];

static __device__ __forceinline__ unsigned smem_u32(const void* p) {
    unsigned r;
    asm("{ .reg .u64 t; cvta.to.shared.u64 t, %1; cvt.u32.u64 %0, t; }" : "=r"(r) : "l"(p));
    return r;
}
static __device__ __forceinline__ float to_tf32f(float x) {
    float r; asm("cvt.rna.tf32.f32 %0, %1;" : "=f"(r) : "f"(x)); return r;
}
static __device__ __forceinline__ void mma8(float* c, const unsigned* a, const unsigned* b) {
    asm volatile(
        "mma.sync.aligned.m16n8k8.row.col.f32.tf32.tf32.f32 "
        "{%0,%1,%2,%3}, {%4,%5,%6,%7}, {%8,%9}, {%0,%1,%2,%3};"
        : "+f"(c[0]), "+f"(c[1]), "+f"(c[2]), "+f"(c[3])
        : "r"(a[0]), "r"(a[1]), "r"(a[2]), "r"(a[3]), "r"(b[0]), "r"(b[1]));
}
static __device__ __forceinline__ float4 hi4(float4 v) {
    return make_float4(to_tf32f(v.x), to_tf32f(v.y), to_tf32f(v.z), to_tf32f(v.w));
}
static __device__ __forceinline__ float4 lo4(float4 v, float4 h) {
    return make_float4(to_tf32f(v.x - h.x), to_tf32f(v.y - h.y),
                       to_tf32f(v.z - h.z), to_tf32f(v.w - h.w));
}
#define CP16(dst, src) \
    asm volatile("cp.async.cg.shared.global [%0], [%1], 16;" :: "r"(dst), "l"(src))

__global__ void zero_cnt_kernel() { if (threadIdx.x < 3) g_cnt[threadIdx.x] = 0; }

// deterministic compaction of active (non-skip) token indices
__global__ __launch_bounds__(1024) void compact_kernel() {
    __shared__ int ps[1024];
    int tid = threadIdx.x;
    int a0 = g_skip[2 * tid] ? 0 : 1;
    int a1 = g_skip[2 * tid + 1] ? 0 : 1;
    ps[tid] = a0 + a1;
    __syncthreads();
    for (int off = 1; off < 1024; off <<= 1) {
        int v = ps[tid];
        int add = (tid >= off) ? ps[tid - off] : 0;
        __syncthreads();
        ps[tid] = v + add;
        __syncthreads();
    }
    int base = ps[tid] - (a0 + a1);
    if (a0) g_idx[base] = 2 * tid;
    if (a1) g_idx[base + a0] = 2 * tid + 1;
    if (tid == 1023) g_nact = ps[1023];
}

// W[K][N] -> Th/Tl [N][K] with tf32 hi/lo split
__global__ __launch_bounds__(256) void wtrans_kernel(const float* __restrict__ W,
                                                     float* __restrict__ Th,
                                                     float* __restrict__ Tl, int K, int N) {
    __shared__ float tile[32][33];
    int n0 = blockIdx.x * 32, k0 = blockIdx.y * 32;
    int tx = threadIdx.x & 31, ty = threadIdx.x >> 5;
    for (int i = ty; i < 32; i += 8) tile[i][tx] = W[(size_t)(k0 + i) * N + n0 + tx];
    __syncthreads();
    for (int i = ty; i < 32; i += 8) {
        float v = tile[tx][i];
        float hv = to_tf32f(v);
        float lv = to_tf32f(v - hv);
        size_t o = (size_t)(n0 + i) * K + k0 + tx;
        Th[o] = hv; Tl[o] = lv;
    }
}

__global__ void bcat_kernel(const float* __restrict__ bq, const float* __restrict__ bk,
                            const float* __restrict__ bv) {
    int i = blockIdx.x * 256 + threadIdx.x;
    g_bqkv[i] = (i < 1024) ? bq[i] : (i < 2048) ? bk[i - 1024] : bv[i - 2048];
}

__global__ __launch_bounds__(256) void embed_kernel(const int* __restrict__ x,
                                                    const float* __restrict__ emb) {
    int tok = blockIdx.x, s = tok % SS, id = x[tok];
    int d0 = threadIdx.x * 4;
    float4 ev = *(const float4*)(emb + (size_t)id * DD + d0);
    float o[4] = {ev.x, ev.y, ev.z, ev.w};
#pragma unroll
    for (int j = 0; j < 4; j++) {
        int d = d0 + j;
        float ang = (float)s * expf((float)(d & ~1) * (-9.210340371976184f / 1024.0f));
        o[j] = o[j] * 32.0f + ((d & 1) ? cosf(ang) : sinf(ang));
    }
    *(float4*)(g_h + (size_t)tok * DD + d0) = make_float4(o[0], o[1], o[2], o[3]);
}

// ===== persistent mma.sync 3xTF32 GEMM, split-K (nzt planes) + row compaction =====
#define KCH 16
#define ROWW 20
#define MATB (128*ROWW*4)
#define STGB (3*MATB)
#define TGSM (3*STGB)

__global__ __launch_bounds__(256, 2)
void tgemm_kernel(const float* __restrict__ Ab, const float* __restrict__ Bhb,
                  const float* __restrict__ Blb, const float* __restrict__ bias,
                  float* __restrict__ Cb, int zstride,
                  int M, int N, int Ksub, int ldk, int relu, int mode,
                  int nxt, int nyt, int nzt) {
    extern __shared__ char smem[];
    unsigned sb = smem_u32(smem);
    int tid = threadIdx.x, wid = tid >> 5, lane = tid & 31;
    int grp = lane >> 2, qid = lane & 3;
    int wm0 = (wid & 3) * 32, wn0 = (wid >> 2) * 64;
    int r0 = tid >> 2, kc0 = (tid & 3) * 16;
    int r1 = (tid + 256) >> 2, kc1 = ((tid + 256) & 3) * 16;
    int total = nxt * nyt * nzt;

    for (int ti = blockIdx.x; ti < total; ti += NPERS) {
        int bx = ti % nxt;
        int rem = ti / nxt;
        int by = rem % nyt;
        int z = rem / nyt;
        int bm = by * 128, bn = bx * 128;
        int Meff = M;
        if (mode) {
            Meff = g_nact;
            if (bm >= Meff) continue;
        }
        const float* A  = Ab  + (size_t)z * Ksub;
        const float* Bh = Bhb + (size_t)z * Ksub;
        const float* Bl = Blb + (size_t)z * Ksub;
        float* C = Cb + (size_t)z * zstride;

        float acc[2][8][4];
#pragma unroll
        for (int mt = 0; mt < 2; mt++)
#pragma unroll
            for (int nt = 0; nt < 8; nt++)
#pragma unroll
                for (int e = 0; e < 4; e++) acc[mt][nt][e] = 0.f;

        int nchunks = Ksub / KCH;
        const float *Ar0, *Ar1;
        {
            int rr0 = bm + r0, rr1 = bm + r1;
            if (mode == 1) {
                rr0 = g_idx[rr0 < Meff ? rr0 : Meff - 1];
                rr1 = g_idx[rr1 < Meff ? rr1 : Meff - 1];
            }
            Ar0 = A + (size_t)rr0 * ldk;
            Ar1 = A + (size_t)rr1 * ldk;
        }

#pragma unroll
        for (int c = 0; c < 2; c++) {
            int kb = c * KCH;
            unsigned st = sb + (c % 3) * STGB;
            CP16(st + r0 * 80 + kc0, Ar0 + kb + kc0 / 4);
            CP16(st + r1 * 80 + kc1, Ar1 + kb + kc1 / 4);
            CP16(st + MATB + r0 * 80 + kc0, Bh + (size_t)(bn + r0) * ldk + kb + kc0 / 4);
            CP16(st + MATB + r1 * 80 + kc1, Bh + (size_t)(bn + r1) * ldk + kb + kc1 / 4);
            CP16(st + 2 * MATB + r0 * 80 + kc0, Bl + (size_t)(bn + r0) * ldk + kb + kc0 / 4);
            CP16(st + 2 * MATB + r1 * 80 + kc1, Bl + (size_t)(bn + r1) * ldk + kb + kc1 / 4);
            asm volatile("cp.async.commit_group;");
        }

        for (int c = 0; c < nchunks; c++) {
            if (c + 2 < nchunks) asm volatile("cp.async.wait_group 1;");
            else                 asm volatile("cp.async.wait_group 0;");
            __syncthreads();
            const float* As  = (const float*)(smem + (c % 3) * STGB);
            const float* Bhs = As + 128 * ROWW;
            const float* Bls = Bhs + 128 * ROWW;
#pragma unroll
            for (int s8 = 0; s8 < 2; s8++) {
                int k8 = s8 * 8;
                unsigned Ah[2][4], Al[2][4];
#pragma unroll
                for (int mt = 0; mt < 2; mt++) {
                    int ra = wm0 + mt * 16 + grp;
                    float x0 = As[ra * ROWW + k8 + qid];
                    float x1 = As[(ra + 8) * ROWW + k8 + qid];
                    float x2 = As[ra * ROWW + k8 + qid + 4];
                    float x3 = As[(ra + 8) * ROWW + k8 + qid + 4];
                    float h0 = to_tf32f(x0), h1 = to_tf32f(x1), h2 = to_tf32f(x2), h3 = to_tf32f(x3);
                    Ah[mt][0] = __float_as_uint(h0); Ah[mt][1] = __float_as_uint(h1);
                    Ah[mt][2] = __float_as_uint(h2); Ah[mt][3] = __float_as_uint(h3);
                    Al[mt][0] = __float_as_uint(to_tf32f(x0 - h0));
                    Al[mt][1] = __float_as_uint(to_tf32f(x1 - h1));
                    Al[mt][2] = __float_as_uint(to_tf32f(x2 - h2));
                    Al[mt][3] = __float_as_uint(to_tf32f(x3 - h3));
                }
#pragma unroll
                for (int nt = 0; nt < 8; nt++) {
                    int nr = wn0 + nt * 8 + grp;
                    unsigned bh[2], bl[2];
                    bh[0] = __float_as_uint(Bhs[nr * ROWW + k8 + qid]);
                    bh[1] = __float_as_uint(Bhs[nr * ROWW + k8 + qid + 4]);
                    bl[0] = __float_as_uint(Bls[nr * ROWW + k8 + qid]);
                    bl[1] = __float_as_uint(Bls[nr * ROWW + k8 + qid + 4]);
#pragma unroll
                    for (int mt = 0; mt < 2; mt++) {
                        mma8(acc[mt][nt], Ah[mt], bh);
                        mma8(acc[mt][nt], Ah[mt], bl);
                        mma8(acc[mt][nt], Al[mt], bh);
                    }
                }
            }
            __syncthreads();
            if (c + 2 < nchunks) {
                int kb = (c + 2) * KCH;
                unsigned st = sb + ((c + 2) % 3) * STGB;
                CP16(st + r0 * 80 + kc0, Ar0 + kb + kc0 / 4);
                CP16(st + r1 * 80 + kc1, Ar1 + kb + kc1 / 4);
                CP16(st + MATB + r0 * 80 + kc0, Bh + (size_t)(bn + r0) * ldk + kb + kc0 / 4);
                CP16(st + MATB + r1 * 80 + kc1, Bh + (size_t)(bn + r1) * ldk + kb + kc1 / 4);
                CP16(st + 2 * MATB + r0 * 80 + kc0, Bl + (size_t)(bn + r0) * ldk + kb + kc0 / 4);
                CP16(st + 2 * MATB + r1 * 80 + kc1, Bl + (size_t)(bn + r1) * ldk + kb + kc1 / 4);
                asm volatile("cp.async.commit_group;");
            }
        }

#pragma unroll
        for (int mt = 0; mt < 2; mt++) {
#pragma unroll
            for (int nt = 0; nt < 8; nt++) {
                int row0 = bm + wm0 + mt * 16 + grp;
                int col = bn + wn0 + nt * 8 + 2 * qid;
                float2 v0 = make_float2(acc[mt][nt][0], acc[mt][nt][1]);
                float2 v1 = make_float2(acc[mt][nt][2], acc[mt][nt][3]);
                if (bias) {
                    float2 bv = *(const float2*)(bias + col);
                    v0.x += bv.x; v0.y += bv.y; v1.x += bv.x; v1.y += bv.y;
                }
                if (relu) {
                    v0.x = fmaxf(v0.x, 0.f); v0.y = fmaxf(v0.y, 0.f);
                    v1.x = fmaxf(v1.x, 0.f); v1.y = fmaxf(v1.y, 0.f);
                }
                if (row0 < Meff)
                    *(float2*)(C + (size_t)row0 * N + col) = v0;
                if (row0 + 8 < Meff)
                    *(float2*)(C + (size_t)(row0 + 8) * N + col) = v1;
            }
        }
        __syncthreads();
    }
}

// ===== tensor-core attention scores (Q pre-scaled by 1/8 at staging) =====
#define ASTR 68
#define SCSM (4*128*ASTR*4)

__global__ __launch_bounds__(256)
void attn_scores_mma_kernel() {
    int t = blockIdx.x;
    int qt = (int)((sqrtf(8.f * t + 1.f) - 1.f) * 0.5f);
    while ((qt + 1) * (qt + 2) / 2 <= t) qt++;
    while (qt * (qt + 1) / 2 > t) qt--;
    int kt = t - qt * (qt + 1) / 2;
    int bh = blockIdx.y;
    int b = bh >> 4, hh = bh & 15;

    extern __shared__ float sm[];
    float* QH = sm;
    float* QL = QH + 128 * ASTR;
    float* KH = QL + 128 * ASTR;
    float* KL = KH + 128 * ASTR;

    int tid = threadIdx.x, wid = tid >> 5, lane = tid & 31;
    int grp = lane >> 2, qid = lane & 3;
    int wm0 = (wid & 3) * 32, wn0 = (wid >> 2) * 64;

    const float* qb = g_qkv + ((size_t)(b * SS + qt * 128)) * QKVS + hh * HD;
    const float* kb = g_qkv + ((size_t)(b * SS + kt * 128)) * QKVS + 1024 + hh * HD;
    for (int i = tid; i < 128 * 16; i += 256) {
        int row = i >> 4, c4 = (i & 15) * 4;
        float4 v = *(const float4*)(qb + (size_t)row * QKVS + c4);
        v.x *= 0.125f; v.y *= 0.125f; v.z *= 0.125f; v.w *= 0.125f;
        float4 h = hi4(v);
        *(float4*)(QH + row * ASTR + c4) = h;
        *(float4*)(QL + row * ASTR + c4) = lo4(v, h);
        float4 w = *(const float4*)(kb + (size_t)row * QKVS + c4);
        float4 wh = hi4(w);
        *(float4*)(KH + row * ASTR + c4) = wh;
        *(float4*)(KL + row * ASTR + c4) = lo4(w, wh);
    }
    __syncthreads();

    float acc[2][8][4];
#pragma unroll
    for (int mt = 0; mt < 2; mt++)
#pragma unroll
        for (int nt = 0; nt < 8; nt++)
#pragma unroll
            for (int e = 0; e < 4; e++) acc[mt][nt][e] = 0.f;

#pragma unroll
    for (int s = 0; s < 8; s++) {
        int k8 = s * 8;
        unsigned Ah[2][4], Al[2][4];
#pragma unroll
        for (int mt = 0; mt < 2; mt++) {
            int ra = wm0 + mt * 16 + grp;
            Ah[mt][0] = __float_as_uint(QH[ra * ASTR + k8 + qid]);
            Ah[mt][1] = __float_as_uint(QH[(ra + 8) * ASTR + k8 + qid]);
            Ah[mt][2] = __float_as_uint(QH[ra * ASTR + k8 + qid + 4]);
            Ah[mt][3] = __float_as_uint(QH[(ra + 8) * ASTR + k8 + qid + 4]);
            Al[mt][0] = __float_as_uint(QL[ra * ASTR + k8 + qid]);
            Al[mt][1] = __float_as_uint(QL[(ra + 8) * ASTR + k8 + qid]);
            Al[mt][2] = __float_as_uint(QL[ra * ASTR + k8 + qid + 4]);
            Al[mt][3] = __float_as_uint(QL[(ra + 8) * ASTR + k8 + qid + 4]);
        }
#pragma unroll
        for (int nt = 0; nt < 8; nt++) {
            int nr = wn0 + nt * 8 + grp;
            unsigned bh2[2], bl2[2];
            bh2[0] = __float_as_uint(KH[nr * ASTR + k8 + qid]);
            bh2[1] = __float_as_uint(KH[nr * ASTR + k8 + qid + 4]);
            bl2[0] = __float_as_uint(KL[nr * ASTR + k8 + qid]);
            bl2[1] = __float_as_uint(KL[nr * ASTR + k8 + qid + 4]);
#pragma unroll
            for (int mt = 0; mt < 2; mt++) {
                mma8(acc[mt][nt], Ah[mt], bh2);
                mma8(acc[mt][nt], Ah[mt], bl2);
                mma8(acc[mt][nt], Al[mt], bh2);
            }
        }
    }

    bool diag = (kt == qt);
#pragma unroll
    for (int mt = 0; mt < 2; mt++) {
#pragma unroll
        for (int nt = 0; nt < 8; nt++) {
            int r0 = qt * 128 + wm0 + mt * 16 + grp;
            int c0 = kt * 128 + wn0 + nt * 8 + 2 * qid;
            float v0 = acc[mt][nt][0], v1 = acc[mt][nt][1];
            float v2 = acc[mt][nt][2], v3 = acc[mt][nt][3];
            if (diag) {
                if (c0 > r0)     v0 = -1e30f;
                if (c0 + 1 > r0) v1 = -1e30f;
                if (c0 > r0 + 8)     v2 = -1e30f;
                if (c0 + 1 > r0 + 8) v3 = -1e30f;
            }
            float* p0 = g_sc + ((size_t)bh * SS + r0) * SS + c0;
            *(float2*)p0 = make_float2(v0, v1);
            *(float2*)(p0 + 8 * SS) = make_float2(v2, v3);
        }
    }
}

// ===== prefix softmax =====
__global__ __launch_bounds__(256) void softmax_kernel() {
    int row = blockIdx.x;
    int qr = row & (SS - 1);
    int L = ((qr >> 7) + 1) << 7;
    float* sc = g_sc + (size_t)row * SS;
    int tid = threadIdx.x;
    bool valid = (tid * 4 < L);
    float4 v = valid ? *(float4*)&sc[tid * 4] : make_float4(-1e30f, -1e30f, -1e30f, -1e30f);
    __shared__ float red[8];
    __shared__ float stat;
    float m = fmaxf(fmaxf(v.x, v.y), fmaxf(v.z, v.w));
    for (int o = 16; o; o >>= 1) m = fmaxf(m, __shfl_down_sync(~0u, m, o));
    if ((tid & 31) == 0) red[tid >> 5] = m;
    __syncthreads();
    if (tid == 0) {
        float t = red[0];
        for (int i = 1; i < 8; i++) t = fmaxf(t, red[i]);
        stat = t;
    }
    __syncthreads();
    float mx = stat;
    float e0 = expf(v.x - mx), e1 = expf(v.y - mx), e2 = expf(v.z - mx), e3 = expf(v.w - mx);
    float s = e0 + e1 + e2 + e3;
    for (int o = 16; o; o >>= 1) s += __shfl_down_sync(~0u, s, o);
    __syncthreads();
    if ((tid & 31) == 0) red[tid >> 5] = s;
    __syncthreads();
    if (tid == 0) {
        float t = 0.f;
        for (int i = 0; i < 8; i++) t += red[i];
        stat = t;
    }
    __syncthreads();
    float inv = 1.0f / stat;
    if (valid) *(float4*)&sc[tid * 4] = make_float4(e0 * inv, e1 * inv, e2 * inv, e3 * inv);
}

// ===== tensor-core AV: raw double-buffered cp.async staging, register hi/lo split ====
#define PSTR 68
#define VSTR 72
#define PBYT (128*PSTR*4)
#define VBYT (64*VSTR*4)
#define AVSTG (PBYT + VBYT)
#define AVSM (2*AVSTG)

__global__ __launch_bounds__(256)
void attn_av_mma_kernel() {
    int qt = blockIdx.x, bh = blockIdx.y;
    int b = bh >> 4, hh = bh & 15;

    extern __shared__ char smc[];
    unsigned sb = smem_u32(smc);

    int tid = threadIdx.x, wid = tid >> 5, lane = tid & 31;
    int grp = lane >> 2, qid = lane & 3;
    int wm0 = (wid & 3) * 32, wn0 = (wid >> 2) * 32;

    float acc[2][4][4];
#pragma unroll
    for (int mt = 0; mt < 2; mt++)
#pragma unroll
        for (int nt = 0; nt < 4; nt++)
#pragma unroll
            for (int e = 0; e < 4; e++) acc[mt][nt][e] = 0.f;

    int nchunks = (qt + 1) * 2;
    const float* pbase = g_sc + ((size_t)bh * SS + qt * 128) * SS;
    const float* vbase = g_qkv + ((size_t)(b * SS)) * QKVS + 2048 + hh * HD;

    {
        unsigned stP = sb;
        unsigned stV = sb + PBYT;
#pragma unroll
        for (int it = 0; it < 8; it++) {
            int idx = tid + it * 256;
            int row = idx >> 4, c4 = (idx & 15) * 4;
            CP16(stP + (row * PSTR + c4) * 4, pbase + (size_t)row * SS + c4);
        }
#pragma unroll
        for (int it = 0; it < 4; it++) {
            int idx = tid + it * 256;
            int tok = idx >> 4, d4 = (idx & 15) * 4;
            CP16(stV + (tok * VSTR + d4) * 4, vbase + (size_t)tok * QKVS + d4);
        }
        asm volatile("cp.async.commit_group;");
    }

    for (int kc = 0; kc < nchunks; kc++) {
        if (kc + 1 < nchunks) {
            unsigned st = sb + ((kc + 1) & 1) * AVSTG;
            unsigned stP = st, stV = st + PBYT;
            const float* pb = pbase + (kc + 1) * 64;
            const float* vb = vbase + (size_t)(kc + 1) * 64 * QKVS;
#pragma unroll
            for (int it = 0; it < 8; it++) {
                int idx = tid + it * 256;
                int row = idx >> 4, c4 = (idx & 15) * 4;
                CP16(stP + (row * PSTR + c4) * 4, pb + (size_t)row * SS + c4);
            }
#pragma unroll
            for (int it = 0; it < 4; it++) {
                int idx = tid + it * 256;
                int tok = idx >> 4, d4 = (idx & 15) * 4;
                CP16(stV + (tok * VSTR + d4) * 4, vb + (size_t)tok * QKVS + d4);
            }
            asm volatile("cp.async.commit_group;");
            asm volatile("cp.async.wait_group 1;");
        } else {
            asm volatile("cp.async.wait_group 0;");
        }
        __syncthreads();

        const float* Pr = (const float*)(smc + (kc & 1) * AVSTG);
        const float* Vr = Pr + 128 * PSTR;

#pragma unroll
        for (int s = 0; s < 8; s++) {
            int k8 = s * 8;
            unsigned Ah[2][4], Al[2][4];
#pragma unroll
            for (int mt = 0; mt < 2; mt++) {
                int ra = wm0 + mt * 16 + grp;
                float x0 = Pr[ra * PSTR + k8 + qid];
                float x1 = Pr[(ra + 8) * PSTR + k8 + qid];
                float x2 = Pr[ra * PSTR + k8 + qid + 4];
                float x3 = Pr[(ra + 8) * PSTR + k8 + qid + 4];
                float h0 = to_tf32f(x0), h1 = to_tf32f(x1), h2 = to_tf32f(x2), h3 = to_tf32f(x3);
                Ah[mt][0] = __float_as_uint(h0); Ah[mt][1] = __float_as_uint(h1);
                Ah[mt][2] = __float_as_uint(h2); Ah[mt][3] = __float_as_uint(h3);
                Al[mt][0] = __float_as_uint(to_tf32f(x0 - h0));
                Al[mt][1] = __float_as_uint(to_tf32f(x1 - h1));
                Al[mt][2] = __float_as_uint(to_tf32f(x2 - h2));
                Al[mt][3] = __float_as_uint(to_tf32f(x3 - h3));
            }
#pragma unroll
            for (int nt = 0; nt < 4; nt++) {
                int nr = wn0 + nt * 8 + grp;
                float y0 = Vr[(k8 + qid) * VSTR + nr];
                float y1 = Vr[(k8 + qid + 4) * VSTR + nr];
                float g0 = to_tf32f(y0), g1 = to_tf32f(y1);
                unsigned bh2[2] = {__float_as_uint(g0), __float_as_uint(g1)};
                unsigned bl2[2] = {__float_as_uint(to_tf32f(y0 - g0)),
                                   __float_as_uint(to_tf32f(y1 - g1))};
#pragma unroll
                for (int mt = 0; mt < 2; mt++) {
                    mma8(acc[mt][nt], Ah[mt], bh2);
                    mma8(acc[mt][nt], Ah[mt], bl2);
                    mma8(acc[mt][nt], Al[mt], bh2);
                }
            }
        }
        __syncthreads();
    }

#pragma unroll
    for (int mt = 0; mt < 2; mt++) {
#pragma unroll
        for (int nt = 0; nt < 4; nt++) {
            int r0 = qt * 128 + wm0 + mt * 16 + grp;
            int c0 = hh * HD + wn0 + nt * 8 + 2 * qid;
            float* p0 = g_a + ((size_t)(b * SS) + r0) * DD + c0;
            *(float2*)p0 = make_float2(acc[mt][nt][0], acc[mt][nt][1]);
            *(float2*)(p0 + 8 * DD) = make_float2(acc[mt][nt][2], acc[mt][nt][3]);
        }
    }
}

// ===== SIMT SGEMM (router GEMM1) =====
__global__ __launch_bounds__(256) void sgemm_kernel(const float* __restrict__ A,
                                                    const float* __restrict__ B,
                                                    const float* __restrict__ bias,
                                                    float* __restrict__ C,
                                                    int M, int N, int K) {
    __shared__ float Ast[16][128];
    __shared__ float Bs[16][64];
    int tid = threadIdx.x;
    int bm = blockIdx.y * 128, bn = blockIdx.x * 64;
    int tx = tid & 15, ty = tid >> 4;
    int m0 = ty * 8, n0 = tx * 4;
    float acc[8][4];
#pragma unroll
    for (int i = 0; i < 8; i++)
#pragma unroll
        for (int j = 0; j < 4; j++) acc[i][j] = 0.f;
    int arow = tid >> 2, ak4 = (tid & 3) * 4, bk = tid >> 4, bc4 = (tid & 15) * 4;
    for (int kb = 0; kb < K; kb += 16) {
#pragma unroll
        for (int p = 0; p < 2; p++) {
            int r = arow + p * 64;
            float4 av = *(const float4*)(A + (size_t)(bm + r) * K + kb + ak4);
            Ast[ak4+0][r] = av.x; Ast[ak4+1][r] = av.y; Ast[ak4+2][r] = av.z; Ast[ak4+3][r] = av.w;
        }
        *(float4*)&Bs[bk][bc4] = *(const float4*)(B + (size_t)(kb + bk) * N + bn + bc4);
        __syncthreads();
#pragma unroll
        for (int k = 0; k < 16; k++) {
            float4 a0 = *(float4*)&Ast[k][m0];
            float4 a1 = *(float4*)&Ast[k][m0 + 4];
            float4 bv = *(float4*)&Bs[k][n0];
            float am[8] = {a0.x,a0.y,a0.z,a0.w,a1.x,a1.y,a1.z,a1.w};
            float bb[4] = {bv.x,bv.y,bv.z,bv.w};
#pragma unroll
            for (int i = 0; i < 8; i++)
#pragma unroll
                for (int j = 0; j < 4; j++) acc[i][j] += am[i] * bb[j];
        }
        __syncthreads();
    }
#pragma unroll
    for (int i = 0; i < 8; i++)
#pragma unroll
        for (int j = 0; j < 4; j++) {
            float v = acc[i][j] + bias[bn + n0 + j];
            C[(size_t)(bm + m0 + i) * N + bn + n0 + j] = fmaxf(v, 0.f);
        }
}

// ===== fused LN on compact rows: out = LN(sum_{p<nparts} in[p] + res + bias) =====
__global__ __launch_bounds__(256) void ln_fused_kernel(const float* __restrict__ inb,
                                                       int nparts,
                                                       const float* __restrict__ res,
                                                       const float* __restrict__ bias,
                                                       const float* __restrict__ g,
                                                       const float* __restrict__ bsh,
                                                       float* __restrict__ out,
                                                       int resGather, int outScatter) {
    int row = blockIdx.x;
    if (row >= g_nact) return;
    int orow = g_idx[row];
    size_t inoff = (size_t)row * DD;
    size_t resoff = (size_t)(resGather ? orow : row) * DD;
    size_t outoff = (size_t)(outScatter ? orow : row) * DD;
    int tid = threadIdx.x;
    float4 v = *(const float4*)&inb[inoff + tid * 4];
    for (int p = 1; p < nparts; p++) {
        float4 w = *(const float4*)&inb[(size_t)p * MM * DD + inoff + tid * 4];
        v.x += w.x; v.y += w.y; v.z += w.z; v.w += w.w;
    }
    float4 r = *(const float4*)&res[resoff + tid * 4];
    float4 bv = *(const float4*)&bias[tid * 4];
    v.x += r.x + bv.x; v.y += r.y + bv.y;
    v.z += r.z + bv.z; v.w += r.w + bv.w;
    __shared__ float red[8];
    __shared__ float stat;
    float s = v.x + v.y + v.z + v.w;
    for (int o = 16; o; o >>= 1) s += __shfl_down_sync(~0u, s, o);
    if ((tid & 31) == 0) red[tid >> 5] = s;
    __syncthreads();
    if (tid == 0) {
        float t = 0.f;
        for (int i = 0; i < 8; i++) t += red[i];
        stat = t * (1.0f / DD);
    }
    __syncthreads();
    float mu = stat;
    float dx = v.x - mu, dy = v.y - mu, dz = v.z - mu, dw = v.w - mu;
    float ss = dx * dx + dy * dy + dz * dz + dw * dw;
    for (int o = 16; o; o >>= 1) ss += __shfl_down_sync(~0u, ss, o);
    __syncthreads();
    if ((tid & 31) == 0) red[tid >> 5] = ss;
    __syncthreads();
    if (tid == 0) {
        float t = 0.f;
        for (int i = 0; i < 8; i++) t += red[i];
        stat = rsqrtf(t * (1.0f / DD) + 1e-5f);
    }
    __syncthreads();
    float rs = stat;
    float4 gg = *(const float4*)&g[tid * 4];
    float4 bb = *(const float4*)&bsh[tid * 4];
    *(float4*)&out[outoff + tid * 4] =
        make_float4(dx * rs * gg.x + bb.x, dy * rs * gg.y + bb.y,
                    dz * rs * gg.z + bb.z, dw * rs * gg.w + bb.w);
}

__global__ __launch_bounds__(256) void router2_kernel(const float* __restrict__ rw2,
                                                      const float* __restrict__ rb2) {
    int w = (blockIdx.x * blockDim.x + threadIdx.x) >> 5;
    int lane = threadIdx.x & 31;
    if (w >= MM) return;
    const float* z = g_zr + (size_t)w * RH;
    float s0 = 0.f, s1 = 0.f, s2 = 0.f;
#pragma unroll
    for (int u = 0; u < 4; u++) {
        int j = lane + 32 * u;
        float zv = z[j];
        s0 += zv * rw2[j * 3 + 0];
        s1 += zv * rw2[j * 3 + 1];
        s2 += zv * rw2[j * 3 + 2];
    }
    for (int o = 16; o; o >>= 1) {
        s0 += __shfl_down_sync(~0u, s0, o);
        s1 += __shfl_down_sync(~0u, s1, o);
        s2 += __shfl_down_sync(~0u, s2, o);
    }
    if (lane == 0) {
        s0 += rb2[0]; s1 += rb2[1]; s2 += rb2[2];
        int a = 0; float best = s0;
        if (s1 > best) { best = s1; a = 1; }
        if (s2 > best) { best = s2; a = 2; }
        g_skip[w] = (a == 0);
        atomicAdd(&g_cnt[a], 1);
    }
}

__global__ void scalars_kernel(float* out) {
    float fs = (float)g_cnt[0], ff = (float)g_cnt[1], fr = (float)g_cnt[2];
    out[(size_t)MM * VOC + 0] = (ff + fr) / (float)MM;
    out[(size_t)MM * VOC + 1] = fs / (float)(MM * NL);
    out[(size_t)MM * VOC + 2] = ff / (float)(MM * NL);
    out[(size_t)MM * VOC + 3] = fr / (float)(MM * NL);
}

extern "C" void kernel_launch(void* const* d_in, const int* in_sizes, int n_in,
                              void* d_out, int out_size) {
    const int*   x    = (const int*)d_in[0];
    const float* emb  = (const float*)d_in[1];
    const float* Wq   = (const float*)d_in[2];
    const float* bq   = (const float*)d_in[3];
    const float* Wk   = (const float*)d_in[4];
    const float* bk   = (const float*)d_in[5];
    const float* Wv   = (const float*)d_in[6];
    const float* bv   = (const float*)d_in[7];
    const float* Wo   = (const float*)d_in[8];
    const float* bo   = (const float*)d_in[9];
    const float* ln1g = (const float*)d_in[10];
    const float* ln1b = (const float*)d_in[11];
    const float* Wf1  = (const float*)d_in[12];
    const float* bf1  = (const float*)d_in[13];
    const float* Wf2  = (const float*)d_in[14];
    const float* bf2  = (const float*)d_in[15];
    const float* ln2g = (const float*)d_in[16];
    const float* ln2b = (const float*)d_in[17];
    const float* rW1  = (const float*)d_in[18];
    const float* rb1  = (const float*)d_in[19];
    const float* rW2  = (const float*)d_in[20];
    const float* rb2  = (const float*)d_in[21];
    const float* Wout = (const float*)d_in[22];
    const float* bout = (const float*)d_in[23];
    float* out = (float*)d_out;

    cudaFuncSetAttribute(tgemm_kernel, cudaFuncAttributeMaxDynamicSharedMemorySize, TGSM);
    cudaFuncSetAttribute(attn_scores_mma_kernel, cudaFuncAttributeMaxDynamicSharedMemorySize, SCSM);
    cudaFuncSetAttribute(attn_av_mma_kernel, cudaFuncAttributeMaxDynamicSharedMemorySize, AVSM);

    float *h, *h1, *tp, *qkv, *a, *f1, *zr;
    float *wqh, *wql, *woh, *wol, *w1h, *w1l, *w2h, *w2l, *wvh, *wvl, *bqkv;
    cudaGetSymbolAddress((void**)&h, g_h);
    cudaGetSymbolAddress((void**)&h1, g_h1);
    cudaGetSymbolAddress((void**)&tp, g_tp);
    cudaGetSymbolAddress((void**)&qkv, g_qkv);
    cudaGetSymbolAddress((void**)&a, g_a);
    cudaGetSymbolAddress((void**)&f1, g_f1);
    cudaGetSymbolAddress((void**)&zr, g_zr);
    cudaGetSymbolAddress((void**)&wqh, g_wqkv_h);
    cudaGetSymbolAddress((void**)&wql, g_wqkv_l);
    cudaGetSymbolAddress((void**)&woh, g_wo_h);
    cudaGetSymbolAddress((void**)&wol, g_wo_l);
    cudaGetSymbolAddress((void**)&w1h, g_wf1_h);
    cudaGetSymbolAddress((void**)&w1l, g_wf1_l);
    cudaGetSymbolAddress((void**)&w2h, g_wf2_h);
    cudaGetSymbolAddress((void**)&w2l, g_wf2_l);
    cudaGetSymbolAddress((void**)&wvh, g_wout_h);
    cudaGetSymbolAddress((void**)&wvl, g_wout_l);
    cudaGetSymbolAddress((void**)&bqkv, g_bqkv);

    wtrans_kernel<<<dim3(DD/32, DD/32), 256>>>(Wq, wqh, wql, DD, DD);
    wtrans_kernel<<<dim3(DD/32, DD/32), 256>>>(Wk, wqh + (size_t)1024*DD, wql + (size_t)1024*DD, DD, DD);
    wtrans_kernel<<<dim3(DD/32, DD/32), 256>>>(Wv, wqh + (size_t)2048*DD, wql + (size_t)2048*DD, DD, DD);
    wtrans_kernel<<<dim3(DD/32, DD/32), 256>>>(Wo, woh, wol, DD, DD);
    wtrans_kernel<<<dim3(DFF/32, DD/32), 256>>>(Wf1, w1h, w1l, DD, DFF);
    wtrans_kernel<<<dim3(DD/32, DFF/32), 256>>>(Wf2, w2h, w2l, DFF, DD);
    wtrans_kernel<<<dim3(VOC/32, DD/32), 256>>>(Wout, wvh, wvl, DD, VOC);
    bcat_kernel<<<QKVS/256, 256>>>(bq, bk, bv);

    zero_cnt_kernel<<<1, 32>>>();
    embed_kernel<<<MM, 256>>>(x, emb);

    const int ZST = MM * DD;
    for (int l = 0; l < NL; l++) {
        sgemm_kernel<<<dim3(RH/64, MM/128), 256>>>(h, rW1 + (size_t)l*DD*RH, rb1 + l*RH, zr, MM, RH, DD);
        router2_kernel<<<MM/8, 256>>>(rW2 + (size_t)l*RH*3, rb2 + l*3);
        compact_kernel<<<1, 1024>>>();
        // QKV (dense)
        tgemm_kernel<<<NPERS, 256, TGSM>>>(
            h, wqh, wql, bqkv, qkv, 0, MM, QKVS, DD, DD, 0, 0, QKVS/128, MM/128, 1);
        attn_scores_mma_kernel<<<dim3(36, BHT), 256, SCSM>>>();
        softmax_kernel<<<BHT*SS, 256>>>();
        attn_av_mma_kernel<<<dim3(SS/128, BHT), 256, AVSM>>>();
        // O-proj: gather active rows, split-K x4 -> g_tp planes
        tgemm_kernel<<<NPERS, 256, TGSM>>>(
            a, woh, wol, nullptr, tp, ZST, MM, DD, DD/4, DD, 0, 1, DD/128, MM/128, 4);
        ln_fused_kernel<<<MM, 256>>>(tp, 4, h, bo, ln1g, ln1b, h1, 1, 0);
        // FF1 compact
        tgemm_kernel<<<NPERS, 256, TGSM>>>(
            h1, w1h, w1l, bf1, f1, 0, MM, DFF, DD, DD, 1, 2, DFF/128, MM/128, 1);
        // FF2 compact, split-K x4
        tgemm_kernel<<<NPERS, 256, TGSM>>>(
            f1, w2h, w2l, nullptr, tp, ZST, MM, DD, DFF/4, DFF, 0, 2, DD/128, MM/128, 4);
        ln_fused_kernel<<<MM, 256>>>(tp, 4, h1, bf2, ln2g, ln2b, h, 0, 1);
    }

    tgemm_kernel<<<NPERS, 256, TGSM>>>(
        h, wvh, wvl, bout, out, 0, MM, VOC, DD, DD, 0, 0, VOC/128, MM/128, 1);
    scalars_kernel<<<1, 1>>>(out);
}

// round 13
// speedup vs baseline: 1.1298x; 1.0497x over previous
#include <cuda_runtime.h>
#include <math.h>
#include <stdint.h>

#define BB 2
#define SS 1024
#define DD 1024
#define NH 16
#define HD 64
#define NL 12
#define DFF 4096
#define RH 128
#define VOC 32000
#define MM (BB*SS)
#define BHT (BB*NH)
#define QKVS 3072
#define NPERS 296

// ---- static scratch ----
__device__ float g_h [MM*DD];
__device__ float g_h1[MM*DD];
__device__ float g_tp[4*MM*DD];
__device__ float g_qkv[MM*QKVS];
__device__ float g_a [MM*DD];
__device__ float g_f1[MM*DFF];
__device__ float g_zr[MM*RH];
__device__ float g_sc[(size_t)BHT*SS*SS];
__device__ unsigned char g_skip[MM];
__device__ int g_idx[MM];
__device__ int g_nact;
__device__ int g_cnt[3];
__device__ float g_wqkv_h[(size_t)QKVS*DD], g_wqkv_l[(size_t)QKVS*DD];
__device__ float g_wo_h[(size_t)DD*DD],     g_wo_l[(size_t)DD*DD];
__device__ float g_wf1_h[(size_t)DFF*DD],   g_wf1_l[(size_t)DFF*DD];
__device__ float g_wf2_h[(size_t)DD*DFF],   g_wf2_l[(size_t)DD*DFF];
__device__ float g_wout_h[(size_t)VOC*DD],  g_wout_l[(size_t)VOC*DD];
__device__ float g_bqkv[QKVS];

static __device__ __forceinline__ unsigned smem_u32(const void* p) {
    unsigned r;
    asm("{ .reg .u64 t; cvta.to.shared.u64 t, %1; cvt.u32.u64 %0, t; }" : "=r"(r) : "l"(p));
    return r;
}
static __device__ __forceinline__ float to_tf32f(float x) {
    float r; asm("cvt.rna.tf32.f32 %0, %1;" : "=f"(r) : "f"(x)); return r;
}
static __device__ __forceinline__ void mma8(float* c, const unsigned* a, const unsigned* b) {
    asm volatile(
        "mma.sync.aligned.m16n8k8.row.col.f32.tf32.tf32.f32 "
        "{%0,%1,%2,%3}, {%4,%5,%6,%7}, {%8,%9}, {%0,%1,%2,%3};"
        : "+f"(c[0]), "+f"(c[1]), "+f"(c[2]), "+f"(c[3])
        : "r"(a[0]), "r"(a[1]), "r"(a[2]), "r"(a[3]), "r"(b[0]), "r"(b[1]));
}
#define CP16(dst, src) \
    asm volatile("cp.async.cg.shared.global [%0], [%1], 16;" :: "r"(dst), "l"(src))

__global__ void zero_cnt_kernel() { if (threadIdx.x < 3) g_cnt[threadIdx.x] = 0; }

__global__ __launch_bounds__(1024) void compact_kernel() {
    __shared__ int ps[1024];
    int tid = threadIdx.x;
    int a0 = g_skip[2 * tid] ? 0 : 1;
    int a1 = g_skip[2 * tid + 1] ? 0 : 1;
    ps[tid] = a0 + a1;
    __syncthreads();
    for (int off = 1; off < 1024; off <<= 1) {
        int v = ps[tid];
        int add = (tid >= off) ? ps[tid - off] : 0;
        __syncthreads();
        ps[tid] = v + add;
        __syncthreads();
    }
    int base = ps[tid] - (a0 + a1);
    if (a0) g_idx[base] = 2 * tid;
    if (a1) g_idx[base + a0] = 2 * tid + 1;
    if (tid == 1023) g_nact = ps[1023];
}

// W[K][N] -> Th/Tl [N][K] with tf32 hi/lo split
__global__ __launch_bounds__(256) void wtrans_kernel(const float* __restrict__ W,
                                                     float* __restrict__ Th,
                                                     float* __restrict__ Tl, int K, int N) {
    __shared__ float tile[32][33];
    int n0 = blockIdx.x * 32, k0 = blockIdx.y * 32;
    int tx = threadIdx.x & 31, ty = threadIdx.x >> 5;
    for (int i = ty; i < 32; i += 8) tile[i][tx] = W[(size_t)(k0 + i) * N + n0 + tx];
    __syncthreads();
    for (int i = ty; i < 32; i += 8) {
        float v = tile[tx][i];
        float hv = to_tf32f(v);
        float lv = to_tf32f(v - hv);
        size_t o = (size_t)(n0 + i) * K + k0 + tx;
        Th[o] = hv; Tl[o] = lv;
    }
}

__global__ void bcat_kernel(const float* __restrict__ bq, const float* __restrict__ bk,
                            const float* __restrict__ bv) {
    int i = blockIdx.x * 256 + threadIdx.x;
    g_bqkv[i] = (i < 1024) ? bq[i] : (i < 2048) ? bk[i - 1024] : bv[i - 2048];
}

__global__ __launch_bounds__(256) void embed_kernel(const int* __restrict__ x,
                                                    const float* __restrict__ emb) {
    int tok = blockIdx.x, s = tok % SS, id = x[tok];
    int d0 = threadIdx.x * 4;
    float4 ev = *(const float4*)(emb + (size_t)id * DD + d0);
    float o[4] = {ev.x, ev.y, ev.z, ev.w};
#pragma unroll
    for (int j = 0; j < 4; j++) {
        int d = d0 + j;
        float ang = (float)s * expf((float)(d & ~1) * (-9.210340371976184f / 1024.0f));
        o[j] = o[j] * 32.0f + ((d & 1) ? cosf(ang) : sinf(ang));
    }
    *(float4*)(g_h + (size_t)tok * DD + d0) = make_float4(o[0], o[1], o[2], o[3]);
}

// ===== persistent mma.sync TF32 GEMM (3- or 2-term), split-K + row compaction =====
#define KCH 16
#define ROWW 20
#define MATB (128*ROWW*4)
#define STGB (3*MATB)
#define TGSM (3*STGB)

__global__ __launch_bounds__(256, 2)
void tgemm_kernel(const float* __restrict__ Ab, const float* __restrict__ Bhb,
                  const float* __restrict__ Blb, const float* __restrict__ bias,
                  float* __restrict__ Cb, int zstride,
                  int M, int N, int Ksub, int ldk, int relu, int mode,
                  int nxt, int nyt, int nzt, int full) {
    extern __shared__ char smem[];
    unsigned sb = smem_u32(smem);
    int tid = threadIdx.x, wid = tid >> 5, lane = tid & 31;
    int grp = lane >> 2, qid = lane & 3;
    int wm0 = (wid & 3) * 32, wn0 = (wid >> 2) * 64;
    int r0 = tid >> 2, kc0 = (tid & 3) * 16;
    int r1 = (tid + 256) >> 2, kc1 = ((tid + 256) & 3) * 16;
    int total = nxt * nyt * nzt;

    for (int ti = blockIdx.x; ti < total; ti += NPERS) {
        int bx = ti % nxt;
        int rem = ti / nxt;
        int by = rem % nyt;
        int z = rem / nyt;
        int bm = by * 128, bn = bx * 128;
        int Meff = M;
        if (mode) {
            Meff = g_nact;
            if (bm >= Meff) continue;
        }
        const float* A  = Ab  + (size_t)z * Ksub;
        const float* Bh = Bhb + (size_t)z * Ksub;
        const float* Bl = Blb + (size_t)z * Ksub;
        float* C = Cb + (size_t)z * zstride;

        float acc[2][8][4];
#pragma unroll
        for (int mt = 0; mt < 2; mt++)
#pragma unroll
            for (int nt = 0; nt < 8; nt++)
#pragma unroll
                for (int e = 0; e < 4; e++) acc[mt][nt][e] = 0.f;

        int nchunks = Ksub / KCH;
        const float *Ar0, *Ar1;
        {
            int rr0 = bm + r0, rr1 = bm + r1;
            if (mode == 1) {
                rr0 = g_idx[rr0 < Meff ? rr0 : Meff - 1];
                rr1 = g_idx[rr1 < Meff ? rr1 : Meff - 1];
            }
            Ar0 = A + (size_t)rr0 * ldk;
            Ar1 = A + (size_t)rr1 * ldk;
        }

#pragma unroll
        for (int c = 0; c < 2; c++) {
            int kb = c * KCH;
            unsigned st = sb + (c % 3) * STGB;
            CP16(st + r0 * 80 + kc0, Ar0 + kb + kc0 / 4);
            CP16(st + r1 * 80 + kc1, Ar1 + kb + kc1 / 4);
            CP16(st + MATB + r0 * 80 + kc0, Bh + (size_t)(bn + r0) * ldk + kb + kc0 / 4);
            CP16(st + MATB + r1 * 80 + kc1, Bh + (size_t)(bn + r1) * ldk + kb + kc1 / 4);
            CP16(st + 2 * MATB + r0 * 80 + kc0, Bl + (size_t)(bn + r0) * ldk + kb + kc0 / 4);
            CP16(st + 2 * MATB + r1 * 80 + kc1, Bl + (size_t)(bn + r1) * ldk + kb + kc1 / 4);
            asm volatile("cp.async.commit_group;");
        }

        for (int c = 0; c < nchunks; c++) {
            if (c + 2 < nchunks) asm volatile("cp.async.wait_group 1;");
            else                 asm volatile("cp.async.wait_group 0;");
            __syncthreads();
            const float* As  = (const float*)(smem + (c % 3) * STGB);
            const float* Bhs = As + 128 * ROWW;
            const float* Bls = Bhs + 128 * ROWW;
#pragma unroll
            for (int s8 = 0; s8 < 2; s8++) {
                int k8 = s8 * 8;
                unsigned Ah[2][4], Al[2][4];
#pragma unroll
                for (int mt = 0; mt < 2; mt++) {
                    int ra = wm0 + mt * 16 + grp;
                    float x0 = As[ra * ROWW + k8 + qid];
                    float x1 = As[(ra + 8) * ROWW + k8 + qid];
                    float x2 = As[ra * ROWW + k8 + qid + 4];
                    float x3 = As[(ra + 8) * ROWW + k8 + qid + 4];
                    float h0 = to_tf32f(x0), h1 = to_tf32f(x1), h2 = to_tf32f(x2), h3 = to_tf32f(x3);
                    Ah[mt][0] = __float_as_uint(h0); Ah[mt][1] = __float_as_uint(h1);
                    Ah[mt][2] = __float_as_uint(h2); Ah[mt][3] = __float_as_uint(h3);
                    Al[mt][0] = __float_as_uint(to_tf32f(x0 - h0));
                    Al[mt][1] = __float_as_uint(to_tf32f(x1 - h1));
                    Al[mt][2] = __float_as_uint(to_tf32f(x2 - h2));
                    Al[mt][3] = __float_as_uint(to_tf32f(x3 - h3));
                }
#pragma unroll
                for (int nt = 0; nt < 8; nt++) {
                    int nr = wn0 + nt * 8 + grp;
                    unsigned bh[2], bl[2];
                    bh[0] = __float_as_uint(Bhs[nr * ROWW + k8 + qid]);
                    bh[1] = __float_as_uint(Bhs[nr * ROWW + k8 + qid + 4]);
                    bl[0] = __float_as_uint(Bls[nr * ROWW + k8 + qid]);
                    bl[1] = __float_as_uint(Bls[nr * ROWW + k8 + qid + 4]);
#pragma unroll
                    for (int mt = 0; mt < 2; mt++) {
                        mma8(acc[mt][nt], Ah[mt], bh);
                        mma8(acc[mt][nt], Ah[mt], bl);
                        if (full) mma8(acc[mt][nt], Al[mt], bh);
                    }
                }
            }
            __syncthreads();
            if (c + 2 < nchunks) {
                int kb = (c + 2) * KCH;
                unsigned st = sb + ((c + 2) % 3) * STGB;
                CP16(st + r0 * 80 + kc0, Ar0 + kb + kc0 / 4);
                CP16(st + r1 * 80 + kc1, Ar1 + kb + kc1 / 4);
                CP16(st + MATB + r0 * 80 + kc0, Bh + (size_t)(bn + r0) * ldk + kb + kc0 / 4);
                CP16(st + MATB + r1 * 80 + kc1, Bh + (size_t)(bn + r1) * ldk + kb + kc1 / 4);
                CP16(st + 2 * MATB + r0 * 80 + kc0, Bl + (size_t)(bn + r0) * ldk + kb + kc0 / 4);
                CP16(st + 2 * MATB + r1 * 80 + kc1, Bl + (size_t)(bn + r1) * ldk + kb + kc1 / 4);
                asm volatile("cp.async.commit_group;");
            }
        }

#pragma unroll
        for (int mt = 0; mt < 2; mt++) {
#pragma unroll
            for (int nt = 0; nt < 8; nt++) {
                int row0 = bm + wm0 + mt * 16 + grp;
                int col = bn + wn0 + nt * 8 + 2 * qid;
                float2 v0 = make_float2(acc[mt][nt][0], acc[mt][nt][1]);
                float2 v1 = make_float2(acc[mt][nt][2], acc[mt][nt][3]);
                if (bias) {
                    float2 bv = *(const float2*)(bias + col);
                    v0.x += bv.x; v0.y += bv.y; v1.x += bv.x; v1.y += bv.y;
                }
                if (relu) {
                    v0.x = fmaxf(v0.x, 0.f); v0.y = fmaxf(v0.y, 0.f);
                    v1.x = fmaxf(v1.x, 0.f); v1.y = fmaxf(v1.y, 0.f);
                }
                if (row0 < Meff)
                    *(float2*)(C + (size_t)row0 * N + col) = v0;
                if (row0 + 8 < Meff)
                    *(float2*)(C + (size_t)(row0 + 8) * N + col) = v1;
            }
        }
        __syncthreads();
    }
}

// ===== attention scores: raw Q/K staging (occ 2), register hi/lo split =====
#define ASTR 68
#define SCSM (2*128*ASTR*4)

__global__ __launch_bounds__(256, 2)
void attn_scores_mma_kernel() {
    int t = blockIdx.x;
    int qt = (int)((sqrtf(8.f * t + 1.f) - 1.f) * 0.5f);
    while ((qt + 1) * (qt + 2) / 2 <= t) qt++;
    while (qt * (qt + 1) / 2 > t) qt--;
    int kt = t - qt * (qt + 1) / 2;
    int bh = blockIdx.y;
    int b = bh >> 4, hh = bh & 15;

    extern __shared__ float sm[];
    float* Qs = sm;
    float* Ks = Qs + 128 * ASTR;

    int tid = threadIdx.x, wid = tid >> 5, lane = tid & 31;
    int grp = lane >> 2, qid = lane & 3;
    int wm0 = (wid & 3) * 32, wn0 = (wid >> 2) * 64;

    const float* qb = g_qkv + ((size_t)(b * SS + qt * 128)) * QKVS + hh * HD;
    const float* kb = g_qkv + ((size_t)(b * SS + kt * 128)) * QKVS + 1024 + hh * HD;
    for (int i = tid; i < 128 * 16; i += 256) {
        int row = i >> 4, c4 = (i & 15) * 4;
        float4 v = *(const float4*)(qb + (size_t)row * QKVS + c4);
        v.x *= 0.125f; v.y *= 0.125f; v.z *= 0.125f; v.w *= 0.125f;
        *(float4*)(Qs + row * ASTR + c4) = v;
        *(float4*)(Ks + row * ASTR + c4) = *(const float4*)(kb + (size_t)row * QKVS + c4);
    }
    __syncthreads();

    float acc[2][8][4];
#pragma unroll
    for (int mt = 0; mt < 2; mt++)
#pragma unroll
        for (int nt = 0; nt < 8; nt++)
#pragma unroll
            for (int e = 0; e < 4; e++) acc[mt][nt][e] = 0.f;

#pragma unroll
    for (int s = 0; s < 8; s++) {
        int k8 = s * 8;
        unsigned Ah[2][4], Al[2][4];
#pragma unroll
        for (int mt = 0; mt < 2; mt++) {
            int ra = wm0 + mt * 16 + grp;
            float x0 = Qs[ra * ASTR + k8 + qid];
            float x1 = Qs[(ra + 8) * ASTR + k8 + qid];
            float x2 = Qs[ra * ASTR + k8 + qid + 4];
            float x3 = Qs[(ra + 8) * ASTR + k8 + qid + 4];
            float h0 = to_tf32f(x0), h1 = to_tf32f(x1), h2 = to_tf32f(x2), h3 = to_tf32f(x3);
            Ah[mt][0] = __float_as_uint(h0); Ah[mt][1] = __float_as_uint(h1);
            Ah[mt][2] = __float_as_uint(h2); Ah[mt][3] = __float_as_uint(h3);
            Al[mt][0] = __float_as_uint(to_tf32f(x0 - h0));
            Al[mt][1] = __float_as_uint(to_tf32f(x1 - h1));
            Al[mt][2] = __float_as_uint(to_tf32f(x2 - h2));
            Al[mt][3] = __float_as_uint(to_tf32f(x3 - h3));
        }
#pragma unroll
        for (int nt = 0; nt < 8; nt++) {
            int nr = wn0 + nt * 8 + grp;
            float y0 = Ks[nr * ASTR + k8 + qid];
            float y1 = Ks[nr * ASTR + k8 + qid + 4];
            float g0 = to_tf32f(y0), g1 = to_tf32f(y1);
            unsigned bh2[2] = {__float_as_uint(g0), __float_as_uint(g1)};
            unsigned bl2[2] = {__float_as_uint(to_tf32f(y0 - g0)),
                               __float_as_uint(to_tf32f(y1 - g1))};
#pragma unroll
            for (int mt = 0; mt < 2; mt++) {
                mma8(acc[mt][nt], Ah[mt], bh2);
                mma8(acc[mt][nt], Ah[mt], bl2);
                mma8(acc[mt][nt], Al[mt], bh2);
            }
        }
    }

    bool diag = (kt == qt);
#pragma unroll
    for (int mt = 0; mt < 2; mt++) {
#pragma unroll
        for (int nt = 0; nt < 8; nt++) {
            int r0 = qt * 128 + wm0 + mt * 16 + grp;
            int c0 = kt * 128 + wn0 + nt * 8 + 2 * qid;
            float v0 = acc[mt][nt][0], v1 = acc[mt][nt][1];
            float v2 = acc[mt][nt][2], v3 = acc[mt][nt][3];
            if (diag) {
                if (c0 > r0)     v0 = -1e30f;
                if (c0 + 1 > r0) v1 = -1e30f;
                if (c0 > r0 + 8)     v2 = -1e30f;
                if (c0 + 1 > r0 + 8) v3 = -1e30f;
            }
            float* p0 = g_sc + ((size_t)bh * SS + r0) * SS + c0;
            *(float2*)p0 = make_float2(v0, v1);
            *(float2*)(p0 + 8 * SS) = make_float2(v2, v3);
        }
    }
}

// ===== prefix softmax =====
__global__ __launch_bounds__(256) void softmax_kernel() {
    int row = blockIdx.x;
    int qr = row & (SS - 1);
    int L = ((qr >> 7) + 1) << 7;
    float* sc = g_sc + (size_t)row * SS;
    int tid = threadIdx.x;
    bool valid = (tid * 4 < L);
    float4 v = valid ? *(float4*)&sc[tid * 4] : make_float4(-1e30f, -1e30f, -1e30f, -1e30f);
    __shared__ float red[8];
    __shared__ float stat;
    float m = fmaxf(fmaxf(v.x, v.y), fmaxf(v.z, v.w));
    for (int o = 16; o; o >>= 1) m = fmaxf(m, __shfl_down_sync(~0u, m, o));
    if ((tid & 31) == 0) red[tid >> 5] = m;
    __syncthreads();
    if (tid == 0) {
        float t = red[0];
        for (int i = 1; i < 8; i++) t = fmaxf(t, red[i]);
        stat = t;
    }
    __syncthreads();
    float mx = stat;
    float e0 = expf(v.x - mx), e1 = expf(v.y - mx), e2 = expf(v.z - mx), e3 = expf(v.w - mx);
    float s = e0 + e1 + e2 + e3;
    for (int o = 16; o; o >>= 1) s += __shfl_down_sync(~0u, s, o);
    __syncthreads();
    if ((tid & 31) == 0) red[tid >> 5] = s;
    __syncthreads();
    if (tid == 0) {
        float t = 0.f;
        for (int i = 0; i < 8; i++) t += red[i];
        stat = t;
    }
    __syncthreads();
    float inv = 1.0f / stat;
    if (valid) *(float4*)&sc[tid * 4] = make_float4(e0 * inv, e1 * inv, e2 * inv, e3 * inv);
}

// ===== tensor-core AV: raw double-buffered cp.async staging, register hi/lo split ====
#define PSTR 68
#define VSTR 72
#define PBYT (128*PSTR*4)
#define VBYT (64*VSTR*4)
#define AVSTG (PBYT + VBYT)
#define AVSM (2*AVSTG)

__global__ __launch_bounds__(256, 2)
void attn_av_mma_kernel() {
    int qt = blockIdx.x, bh = blockIdx.y;
    int b = bh >> 4, hh = bh & 15;

    extern __shared__ char smc[];
    unsigned sb = smem_u32(smc);

    int tid = threadIdx.x, wid = tid >> 5, lane = tid & 31;
    int grp = lane >> 2, qid = lane & 3;
    int wm0 = (wid & 3) * 32, wn0 = (wid >> 2) * 32;

    float acc[2][4][4];
#pragma unroll
    for (int mt = 0; mt < 2; mt++)
#pragma unroll
        for (int nt = 0; nt < 4; nt++)
#pragma unroll
            for (int e = 0; e < 4; e++) acc[mt][nt][e] = 0.f;

    int nchunks = (qt + 1) * 2;
    const float* pbase = g_sc + ((size_t)bh * SS + qt * 128) * SS;
    const float* vbase = g_qkv + ((size_t)(b * SS)) * QKVS + 2048 + hh * HD;

    {
        unsigned stP = sb;
        unsigned stV = sb + PBYT;
#pragma unroll
        for (int it = 0; it < 8; it++) {
            int idx = tid + it * 256;
            int row = idx >> 4, c4 = (idx & 15) * 4;
            CP16(stP + (row * PSTR + c4) * 4, pbase + (size_t)row * SS + c4);
        }
#pragma unroll
        for (int it = 0; it < 4; it++) {
            int idx = tid + it * 256;
            int tok = idx >> 4, d4 = (idx & 15) * 4;
            CP16(stV + (tok * VSTR + d4) * 4, vbase + (size_t)tok * QKVS + d4);
        }
        asm volatile("cp.async.commit_group;");
    }

    for (int kc = 0; kc < nchunks; kc++) {
        if (kc + 1 < nchunks) {
            unsigned st = sb + ((kc + 1) & 1) * AVSTG;
            unsigned stP = st, stV = st + PBYT;
            const float* pb = pbase + (kc + 1) * 64;
            const float* vb = vbase + (size_t)(kc + 1) * 64 * QKVS;
#pragma unroll
            for (int it = 0; it < 8; it++) {
                int idx = tid + it * 256;
                int row = idx >> 4, c4 = (idx & 15) * 4;
                CP16(stP + (row * PSTR + c4) * 4, pb + (size_t)row * SS + c4);
            }
#pragma unroll
            for (int it = 0; it < 4; it++) {
                int idx = tid + it * 256;
                int tok = idx >> 4, d4 = (idx & 15) * 4;
                CP16(stV + (tok * VSTR + d4) * 4, vb + (size_t)tok * QKVS + d4);
            }
            asm volatile("cp.async.commit_group;");
            asm volatile("cp.async.wait_group 1;");
        } else {
            asm volatile("cp.async.wait_group 0;");
        }
        __syncthreads();

        const float* Pr = (const float*)(smc + (kc & 1) * AVSTG);
        const float* Vr = Pr + 128 * PSTR;

#pragma unroll
        for (int s = 0; s < 8; s++) {
            int k8 = s * 8;
            unsigned Ah[2][4], Al[2][4];
#pragma unroll
            for (int mt = 0; mt < 2; mt++) {
                int ra = wm0 + mt * 16 + grp;
                float x0 = Pr[ra * PSTR + k8 + qid];
                float x1 = Pr[(ra + 8) * PSTR + k8 + qid];
                float x2 = Pr[ra * PSTR + k8 + qid + 4];
                float x3 = Pr[(ra + 8) * PSTR + k8 + qid + 4];
                float h0 = to_tf32f(x0), h1 = to_tf32f(x1), h2 = to_tf32f(x2), h3 = to_tf32f(x3);
                Ah[mt][0] = __float_as_uint(h0); Ah[mt][1] = __float_as_uint(h1);
                Ah[mt][2] = __float_as_uint(h2); Ah[mt][3] = __float_as_uint(h3);
                Al[mt][0] = __float_as_uint(to_tf32f(x0 - h0));
                Al[mt][1] = __float_as_uint(to_tf32f(x1 - h1));
                Al[mt][2] = __float_as_uint(to_tf32f(x2 - h2));
                Al[mt][3] = __float_as_uint(to_tf32f(x3 - h3));
            }
#pragma unroll
            for (int nt = 0; nt < 4; nt++) {
                int nr = wn0 + nt * 8 + grp;
                float y0 = Vr[(k8 + qid) * VSTR + nr];
                float y1 = Vr[(k8 + qid + 4) * VSTR + nr];
                float g0 = to_tf32f(y0), g1 = to_tf32f(y1);
                unsigned bh2[2] = {__float_as_uint(g0), __float_as_uint(g1)};
                unsigned bl2[2] = {__float_as_uint(to_tf32f(y0 - g0)),
                                   __float_as_uint(to_tf32f(y1 - g1))};
#pragma unroll
                for (int mt = 0; mt < 2; mt++) {
                    mma8(acc[mt][nt], Ah[mt], bh2);
                    mma8(acc[mt][nt], Ah[mt], bl2);
                    mma8(acc[mt][nt], Al[mt], bh2);
                }
            }
        }
        __syncthreads();
    }

#pragma unroll
    for (int mt = 0; mt < 2; mt++) {
#pragma unroll
        for (int nt = 0; nt < 4; nt++) {
            int r0 = qt * 128 + wm0 + mt * 16 + grp;
            int c0 = hh * HD + wn0 + nt * 8 + 2 * qid;
            float* p0 = g_a + ((size_t)(b * SS) + r0) * DD + c0;
            *(float2*)p0 = make_float2(acc[mt][nt][0], acc[mt][nt][1]);
            *(float2*)(p0 + 8 * DD) = make_float2(acc[mt][nt][2], acc[mt][nt][3]);
        }
    }
}

// ===== SIMT SGEMM (router GEMM1) =====
__global__ __launch_bounds__(256) void sgemm_kernel(const float* __restrict__ A,
                                                    const float* __restrict__ B,
                                                    const float* __restrict__ bias,
                                                    float* __restrict__ C,
                                                    int M, int N, int K) {
    __shared__ float Ast[16][128];
    __shared__ float Bs[16][64];
    int tid = threadIdx.x;
    int bm = blockIdx.y * 128, bn = blockIdx.x * 64;
    int tx = tid & 15, ty = tid >> 4;
    int m0 = ty * 8, n0 = tx * 4;
    float acc[8][4];
#pragma unroll
    for (int i = 0; i < 8; i++)
#pragma unroll
        for (int j = 0; j < 4; j++) acc[i][j] = 0.f;
    int arow = tid >> 2, ak4 = (tid & 3) * 4, bk = tid >> 4, bc4 = (tid & 15) * 4;
    for (int kb = 0; kb < K; kb += 16) {
#pragma unroll
        for (int p = 0; p < 2; p++) {
            int r = arow + p * 64;
            float4 av = *(const float4*)(A + (size_t)(bm + r) * K + kb + ak4);
            Ast[ak4+0][r] = av.x; Ast[ak4+1][r] = av.y; Ast[ak4+2][r] = av.z; Ast[ak4+3][r] = av.w;
        }
        *(float4*)&Bs[bk][bc4] = *(const float4*)(B + (size_t)(kb + bk) * N + bn + bc4);
        __syncthreads();
#pragma unroll
        for (int k = 0; k < 16; k++) {
            float4 a0 = *(float4*)&Ast[k][m0];
            float4 a1 = *(float4*)&Ast[k][m0 + 4];
            float4 bv = *(float4*)&Bs[k][n0];
            float am[8] = {a0.x,a0.y,a0.z,a0.w,a1.x,a1.y,a1.z,a1.w};
            float bb[4] = {bv.x,bv.y,bv.z,bv.w};
#pragma unroll
            for (int i = 0; i < 8; i++)
#pragma unroll
                for (int j = 0; j < 4; j++) acc[i][j] += am[i] * bb[j];
        }
        __syncthreads();
    }
#pragma unroll
    for (int i = 0; i < 8; i++)
#pragma unroll
        for (int j = 0; j < 4; j++) {
            float v = acc[i][j] + bias[bn + n0 + j];
            C[(size_t)(bm + m0 + i) * N + bn + n0 + j] = fmaxf(v, 0.f);
        }
}

// ===== fused LN on compact rows: out = LN(sum planes + res + bias) =====
__global__ __launch_bounds__(256) void ln_fused_kernel(const float* __restrict__ inb,
                                                       int nparts,
                                                       const float* __restrict__ res,
                                                       const float* __restrict__ bias,
                                                       const float* __restrict__ g,
                                                       const float* __restrict__ bsh,
                                                       float* __restrict__ out,
                                                       int resGather, int outScatter) {
    int row = blockIdx.x;
    if (row >= g_nact) return;
    int orow = g_idx[row];
    size_t inoff = (size_t)row * DD;
    size_t resoff = (size_t)(resGather ? orow : row) * DD;
    size_t outoff = (size_t)(outScatter ? orow : row) * DD;
    int tid = threadIdx.x;
    float4 v = *(const float4*)&inb[inoff + tid * 4];
    for (int p = 1; p < nparts; p++) {
        float4 w = *(const float4*)&inb[(size_t)p * MM * DD + inoff + tid * 4];
        v.x += w.x; v.y += w.y; v.z += w.z; v.w += w.w;
    }
    float4 r = *(const float4*)&res[resoff + tid * 4];
    float4 bv = *(const float4*)&bias[tid * 4];
    v.x += r.x + bv.x; v.y += r.y + bv.y;
    v.z += r.z + bv.z; v.w += r.w + bv.w;
    __shared__ float red[8];
    __shared__ float stat;
    float s = v.x + v.y + v.z + v.w;
    for (int o = 16; o; o >>= 1) s += __shfl_down_sync(~0u, s, o);
    if ((tid & 31) == 0) red[tid >> 5] = s;
    __syncthreads();
    if (tid == 0) {
        float t = 0.f;
        for (int i = 0; i < 8; i++) t += red[i];
        stat = t * (1.0f / DD);
    }
    __syncthreads();
    float mu = stat;
    float dx = v.x - mu, dy = v.y - mu, dz = v.z - mu, dw = v.w - mu;
    float ss = dx * dx + dy * dy + dz * dz + dw * dw;
    for (int o = 16; o; o >>= 1) ss += __shfl_down_sync(~0u, ss, o);
    __syncthreads();
    if ((tid & 31) == 0) red[tid >> 5] = ss;
    __syncthreads();
    if (tid == 0) {
        float t = 0.f;
        for (int i = 0; i < 8; i++) t += red[i];
        stat = rsqrtf(t * (1.0f / DD) + 1e-5f);
    }
    __syncthreads();
    float rs = stat;
    float4 gg = *(const float4*)&g[tid * 4];
    float4 bb = *(const float4*)&bsh[tid * 4];
    *(float4*)&out[outoff + tid * 4] =
        make_float4(dx * rs * gg.x + bb.x, dy * rs * gg.y + bb.y,
                    dz * rs * gg.z + bb.z, dw * rs * gg.w + bb.w);
}

__global__ __launch_bounds__(256) void router2_kernel(const float* __restrict__ rw2,
                                                      const float* __restrict__ rb2) {
    int w = (blockIdx.x * blockDim.x + threadIdx.x) >> 5;
    int lane = threadIdx.x & 31;
    if (w >= MM) return;
    const float* z = g_zr + (size_t)w * RH;
    float s0 = 0.f, s1 = 0.f, s2 = 0.f;
#pragma unroll
    for (int u = 0; u < 4; u++) {
        int j = lane + 32 * u;
        float zv = z[j];
        s0 += zv * rw2[j * 3 + 0];
        s1 += zv * rw2[j * 3 + 1];
        s2 += zv * rw2[j * 3 + 2];
    }
    for (int o = 16; o; o >>= 1) {
        s0 += __shfl_down_sync(~0u, s0, o);
        s1 += __shfl_down_sync(~0u, s1, o);
        s2 += __shfl_down_sync(~0u, s2, o);
    }
    if (lane == 0) {
        s0 += rb2[0]; s1 += rb2[1]; s2 += rb2[2];
        int a = 0; float best = s0;
        if (s1 > best) { best = s1; a = 1; }
        if (s2 > best) { best = s2; a = 2; }
        g_skip[w] = (a == 0);
        atomicAdd(&g_cnt[a], 1);
    }
}

__global__ void scalars_kernel(float* out) {
    float fs = (float)g_cnt[0], ff = (float)g_cnt[1], fr = (float)g_cnt[2];
    out[(size_t)MM * VOC + 0] = (ff + fr) / (float)MM;
    out[(size_t)MM * VOC + 1] = fs / (float)(MM * NL);
    out[(size_t)MM * VOC + 2] = ff / (float)(MM * NL);
    out[(size_t)MM * VOC + 3] = fr / (float)(MM * NL);
}

extern "C" void kernel_launch(void* const* d_in, const int* in_sizes, int n_in,
                              void* d_out, int out_size) {
    const int*   x    = (const int*)d_in[0];
    const float* emb  = (const float*)d_in[1];
    const float* Wq   = (const float*)d_in[2];
    const float* bq   = (const float*)d_in[3];
    const float* Wk   = (const float*)d_in[4];
    const float* bk   = (const float*)d_in[5];
    const float* Wv   = (const float*)d_in[6];
    const float* bv   = (const float*)d_in[7];
    const float* Wo   = (const float*)d_in[8];
    const float* bo   = (const float*)d_in[9];
    const float* ln1g = (const float*)d_in[10];
    const float* ln1b = (const float*)d_in[11];
    const float* Wf1  = (const float*)d_in[12];
    const float* bf1  = (const float*)d_in[13];
    const float* Wf2  = (const float*)d_in[14];
    const float* bf2  = (const float*)d_in[15];
    const float* ln2g = (const float*)d_in[16];
    const float* ln2b = (const float*)d_in[17];
    const float* rW1  = (const float*)d_in[18];
    const float* rb1  = (const float*)d_in[19];
    const float* rW2  = (const float*)d_in[20];
    const float* rb2  = (const float*)d_in[21];
    const float* Wout = (const float*)d_in[22];
    const float* bout = (const float*)d_in[23];
    float* out = (float*)d_out;

    cudaFuncSetAttribute(tgemm_kernel, cudaFuncAttributeMaxDynamicSharedMemorySize, TGSM);
    cudaFuncSetAttribute(attn_scores_mma_kernel, cudaFuncAttributeMaxDynamicSharedMemorySize, SCSM);
    cudaFuncSetAttribute(attn_av_mma_kernel, cudaFuncAttributeMaxDynamicSharedMemorySize, AVSM);

    float *h, *h1, *tp, *qkv, *a, *f1, *zr;
    float *wqh, *wql, *woh, *wol, *w1h, *w1l, *w2h, *w2l, *wvh, *wvl, *bqkv;
    cudaGetSymbolAddress((void**)&h, g_h);
    cudaGetSymbolAddress((void**)&h1, g_h1);
    cudaGetSymbolAddress((void**)&tp, g_tp);
    cudaGetSymbolAddress((void**)&qkv, g_qkv);
    cudaGetSymbolAddress((void**)&a, g_a);
    cudaGetSymbolAddress((void**)&f1, g_f1);
    cudaGetSymbolAddress((void**)&zr, g_zr);
    cudaGetSymbolAddress((void**)&wqh, g_wqkv_h);
    cudaGetSymbolAddress((void**)&wql, g_wqkv_l);
    cudaGetSymbolAddress((void**)&woh, g_wo_h);
    cudaGetSymbolAddress((void**)&wol, g_wo_l);
    cudaGetSymbolAddress((void**)&w1h, g_wf1_h);
    cudaGetSymbolAddress((void**)&w1l, g_wf1_l);
    cudaGetSymbolAddress((void**)&w2h, g_wf2_h);
    cudaGetSymbolAddress((void**)&w2l, g_wf2_l);
    cudaGetSymbolAddress((void**)&wvh, g_wout_h);
    cudaGetSymbolAddress((void**)&wvl, g_wout_l);
    cudaGetSymbolAddress((void**)&bqkv, g_bqkv);

    wtrans_kernel<<<dim3(DD/32, DD/32), 256>>>(Wq, wqh, wql, DD, DD);
    wtrans_kernel<<<dim3(DD/32, DD/32), 256>>>(Wk, wqh + (size_t)1024*DD, wql + (size_t)1024*DD, DD, DD);
    wtrans_kernel<<<dim3(DD/32, DD/32), 256>>>(Wv, wqh + (size_t)2048*DD, wql + (size_t)2048*DD, DD, DD);
    wtrans_kernel<<<dim3(DD/32, DD/32), 256>>>(Wo, woh, wol, DD, DD);
    wtrans_kernel<<<dim3(DFF/32, DD/32), 256>>>(Wf1, w1h, w1l, DD, DFF);
    wtrans_kernel<<<dim3(DD/32, DFF/32), 256>>>(Wf2, w2h, w2l, DFF, DD);
    wtrans_kernel<<<dim3(VOC/32, DD/32), 256>>>(Wout, wvh, wvl, DD, VOC);
    bcat_kernel<<<QKVS/256, 256>>>(bq, bk, bv);

    zero_cnt_kernel<<<1, 32>>>();
    embed_kernel<<<MM, 256>>>(x, emb);

    const int ZST = MM * DD;
    for (int l = 0; l < NL; l++) {
        sgemm_kernel<<<dim3(RH/64, MM/128), 256>>>(h, rW1 + (size_t)l*DD*RH, rb1 + l*RH, zr, MM, RH, DD);
        router2_kernel<<<MM/8, 256>>>(rW2 + (size_t)l*RH*3, rb2 + l*3);
        compact_kernel<<<1, 1024>>>();
        tgemm_kernel<<<NPERS, 256, TGSM>>>(
            h, wqh, wql, bqkv, qkv, 0, MM, QKVS, DD, DD, 0, 0, QKVS/128, MM/128, 1, 1);
        attn_scores_mma_kernel<<<dim3(36, BHT), 256, SCSM>>>();
        softmax_kernel<<<BHT*SS, 256>>>();
        attn_av_mma_kernel<<<dim3(SS/128, BHT), 256, AVSM>>>();
        tgemm_kernel<<<NPERS, 256, TGSM>>>(
            a, woh, wol, nullptr, tp, ZST, MM, DD, DD/4, DD, 0, 1, DD/128, MM/128, 4, 1);
        ln_fused_kernel<<<MM, 256>>>(tp, 4, h, bo, ln1g, ln1b, h1, 1, 0);
        tgemm_kernel<<<NPERS, 256, TGSM>>>(
            h1, w1h, w1l, bf1, f1, 0, MM, DFF, DD, DD, 1, 2, DFF/128, MM/128, 1, 1);
        tgemm_kernel<<<NPERS, 256, TGSM>>>(
            f1, w2h, w2l, nullptr, tp, ZST, MM, DD, DFF/4, DFF, 0, 2, DD/128, MM/128, 4, 1);
        ln_fused_kernel<<<MM, 256>>>(tp, 4, h1, bf2, ln2g, ln2b, h, 0, 1);
    }

    // logits: 2xTF32 (output-only, no feedback; error ~2.4e-4 << 1e-3)
    tgemm_kernel<<<NPERS, 256, TGSM>>>(
        h, wvh, wvl, bout, out, 0, MM, VOC, DD, DD, 0, 0, VOC/128, MM/128, 1, 0);
    scalars_kernel<<<1, 1>>>(out);
}

// round 14
// speedup vs baseline: 1.2512x; 1.1075x over previous
#include <cuda_runtime.h>
#include <math.h>
#include <stdint.h>

#define BB 2
#define SS 1024
#define DD 1024
#define NH 16
#define HD 64
#define NL 12
#define DFF 4096
#define RH 128
#define VOC 32000
#define MM (BB*SS)
#define BHT (BB*NH)
#define QKVS 3072
#define NPERS 296

// ---- static scratch ----
__device__ float g_h [MM*DD];
__device__ float g_h1[MM*DD];
__device__ float g_tp[4*MM*DD];
__device__ float g_qkv[MM*QKVS];
__device__ float g_a [MM*DD];
__device__ float g_f1[MM*DFF];
__device__ float g_sc[(size_t)BHT*SS*SS];
__device__ unsigned char g_skip[MM];
__device__ int g_idx[MM];
__device__ int g_nact;
__device__ int g_cnt[3];
__device__ float g_wqkv_h[(size_t)QKVS*DD], g_wqkv_l[(size_t)QKVS*DD];
__device__ float g_wo_h[(size_t)DD*DD],     g_wo_l[(size_t)DD*DD];
__device__ float g_wf1_h[(size_t)DFF*DD],   g_wf1_l[(size_t)DFF*DD];
__device__ float g_wf2_h[(size_t)DD*DFF],   g_wf2_l[(size_t)DD*DFF];
__device__ float g_wout_h[(size_t)VOC*DD],  g_wout_l[(size_t)VOC*DD];
__device__ float g_rw1t_h[(size_t)NL*RH*DD], g_rw1t_l[(size_t)NL*RH*DD];
__device__ float g_bqkv[QKVS];

static __device__ __forceinline__ unsigned smem_u32(const void* p) {
    unsigned r;
    asm("{ .reg .u64 t; cvta.to.shared.u64 t, %1; cvt.u32.u64 %0, t; }" : "=r"(r) : "l"(p));
    return r;
}
static __device__ __forceinline__ float to_tf32f(float x) {
    float r; asm("cvt.rna.tf32.f32 %0, %1;" : "=f"(r) : "f"(x)); return r;
}
static __device__ __forceinline__ void mma8(float* c, const unsigned* a, const unsigned* b) {
    asm volatile(
        "mma.sync.aligned.m16n8k8.row.col.f32.tf32.tf32.f32 "
        "{%0,%1,%2,%3}, {%4,%5,%6,%7}, {%8,%9}, {%0,%1,%2,%3};"
        : "+f"(c[0]), "+f"(c[1]), "+f"(c[2]), "+f"(c[3])
        : "r"(a[0]), "r"(a[1]), "r"(a[2]), "r"(a[3]), "r"(b[0]), "r"(b[1]));
}
#define CP16(dst, src) \
    asm volatile("cp.async.cg.shared.global [%0], [%1], 16;" :: "r"(dst), "l"(src))

__global__ void zero_cnt_kernel() { if (threadIdx.x < 3) g_cnt[threadIdx.x] = 0; }

__global__ __launch_bounds__(1024) void compact_kernel() {
    __shared__ int ps[1024];
    int tid = threadIdx.x;
    int a0 = g_skip[2 * tid] ? 0 : 1;
    int a1 = g_skip[2 * tid + 1] ? 0 : 1;
    ps[tid] = a0 + a1;
    __syncthreads();
    for (int off = 1; off < 1024; off <<= 1) {
        int v = ps[tid];
        int add = (tid >= off) ? ps[tid - off] : 0;
        __syncthreads();
        ps[tid] = v + add;
        __syncthreads();
    }
    int base = ps[tid] - (a0 + a1);
    if (a0) g_idx[base] = 2 * tid;
    if (a1) g_idx[base + a0] = 2 * tid + 1;
    if (tid == 1023) g_nact = ps[1023];
}

// W[K][N] -> Th/Tl [N][K] with tf32 hi/lo split
__global__ __launch_bounds__(256) void wtrans_kernel(const float* __restrict__ W,
                                                     float* __restrict__ Th,
                                                     float* __restrict__ Tl, int K, int N) {
    __shared__ float tile[32][33];
    int n0 = blockIdx.x * 32, k0 = blockIdx.y * 32;
    int tx = threadIdx.x & 31, ty = threadIdx.x >> 5;
    for (int i = ty; i < 32; i += 8) tile[i][tx] = W[(size_t)(k0 + i) * N + n0 + tx];
    __syncthreads();
    for (int i = ty; i < 32; i += 8) {
        float v = tile[tx][i];
        float hv = to_tf32f(v);
        float lv = to_tf32f(v - hv);
        size_t o = (size_t)(n0 + i) * K + k0 + tx;
        Th[o] = hv; Tl[o] = lv;
    }
}

__global__ void bcat_kernel(const float* __restrict__ bq, const float* __restrict__ bk,
                            const float* __restrict__ bv) {
    int i = blockIdx.x * 256 + threadIdx.x;
    g_bqkv[i] = (i < 1024) ? bq[i] : (i < 2048) ? bk[i - 1024] : bv[i - 2048];
}

__global__ __launch_bounds__(256) void embed_kernel(const int* __restrict__ x,
                                                    const float* __restrict__ emb) {
    int tok = blockIdx.x, s = tok % SS, id = x[tok];
    int d0 = threadIdx.x * 4;
    float4 ev = *(const float4*)(emb + (size_t)id * DD + d0);
    float o[4] = {ev.x, ev.y, ev.z, ev.w};
#pragma unroll
    for (int j = 0; j < 4; j++) {
        int d = d0 + j;
        float ang = (float)s * expf((float)(d & ~1) * (-9.210340371976184f / 1024.0f));
        o[j] = o[j] * 32.0f + ((d & 1) ? cosf(ang) : sinf(ang));
    }
    *(float4*)(g_h + (size_t)tok * DD + d0) = make_float4(o[0], o[1], o[2], o[3]);
}

// ===== persistent mma.sync TF32 GEMM (3- or 2-term), KCH=32, 2-stage, split-K, compaction =====
#define KCH 32
#define ROWW 36
#define MATB (128*ROWW*4)      // 18432
#define STGB (3*MATB)          // 55296
#define TGSM (2*STGB)          // 110592

__global__ __launch_bounds__(256, 2)
void tgemm_kernel(const float* __restrict__ Ab, const float* __restrict__ Bhb,
                  const float* __restrict__ Blb, const float* __restrict__ bias,
                  float* __restrict__ Cb, int zstride,
                  int M, int N, int Ksub, int ldk, int relu, int mode,
                  int nxt, int nyt, int nzt, int full) {
    extern __shared__ char smem[];
    unsigned sb = smem_u32(smem);
    int tid = threadIdx.x, wid = tid >> 5, lane = tid & 31;
    int grp = lane >> 2, qid = lane & 3;
    int wm0 = (wid & 3) * 32, wn0 = (wid >> 2) * 64;
    int crow = tid >> 3, cq4 = (tid & 7) * 4;   // staging coords: 128 rows x 8 chunks, 4 it/mat
    int total = nxt * nyt * nzt;

    for (int ti = blockIdx.x; ti < total; ti += NPERS) {
        int bx = ti % nxt;
        int rem = ti / nxt;
        int by = rem % nyt;
        int z = rem / nyt;
        int bm = by * 128, bn = bx * 128;
        int Meff = M;
        if (mode) {
            Meff = g_nact;
            if (bm >= Meff) continue;
        }
        const float* A  = Ab  + (size_t)z * Ksub;
        const float* Bh = Bhb + (size_t)z * Ksub;
        const float* Bl = Blb + (size_t)z * Ksub;
        float* C = Cb + (size_t)z * zstride;

        float acc[2][8][4];
#pragma unroll
        for (int mt = 0; mt < 2; mt++)
#pragma unroll
            for (int nt = 0; nt < 8; nt++)
#pragma unroll
                for (int e = 0; e < 4; e++) acc[mt][nt][e] = 0.f;

        int nchunks = Ksub / KCH;
        const float* Arow;   // this thread's A source row (gather-aware), row = crow
        {
            int rr = bm + crow;
            if (mode == 1) rr = g_idx[rr < Meff ? rr : Meff - 1];
            Arow = A + (size_t)rr * ldk;
        }
        const float* Bhrow = Bh + (size_t)(bn + crow) * ldk;
        const float* Blrow = Bl + (size_t)(bn + crow) * ldk;

        // prologue: stage chunk 0 -> buf 0
        {
            unsigned st = sb;
#pragma unroll
            for (int it = 0; it < 4; it++) {
                int q4 = cq4 + it * 32 - ((it & 1) ? 0 : 0);  // pattern below instead
                (void)q4;
            }
            // 8 chunks per row of 32 floats; each thread does 1 chunk per matrix per "quarter"
            // simpler: 4 iterations, idx covers 1024 chunks per matrix
#pragma unroll
            for (int it = 0; it < 4; it++) {
                int idx = tid + it * 256;
                int row = idx >> 3, q4 = (idx & 7) * 4;
                int rr = bm + row;
                const float* As = A;
                if (mode == 1) rr = g_idx[rr < Meff ? rr : Meff - 1];
                CP16(st + (row * ROWW + q4) * 4, As + (size_t)rr * ldk + q4);
                CP16(st + MATB + (row * ROWW + q4) * 4, Bh + (size_t)(bn + row) * ldk + q4);
                CP16(st + 2 * MATB + (row * ROWW + q4) * 4, Bl + (size_t)(bn + row) * ldk + q4);
            }
            asm volatile("cp.async.commit_group;");
        }

        for (int c = 0; c < nchunks; c++) {
            if (c + 1 < nchunks) {
                int kb = (c + 1) * KCH;
                unsigned st = sb + ((c + 1) & 1) * STGB;
#pragma unroll
                for (int it = 0; it < 4; it++) {
                    int idx = tid + it * 256;
                    int row = idx >> 3, q4 = (idx & 7) * 4;
                    int rr = bm + row;
                    if (mode == 1) rr = g_idx[rr < Meff ? rr : Meff - 1];
                    CP16(st + (row * ROWW + q4) * 4, A + (size_t)rr * ldk + kb + q4);
                    CP16(st + MATB + (row * ROWW + q4) * 4, Bh + (size_t)(bn + row) * ldk + kb + q4);
                    CP16(st + 2 * MATB + (row * ROWW + q4) * 4, Bl + (size_t)(bn + row) * ldk + kb + q4);
                }
                asm volatile("cp.async.commit_group;");
                asm volatile("cp.async.wait_group 1;");
            } else {
                asm volatile("cp.async.wait_group 0;");
            }
            __syncthreads();
            const float* As  = (const float*)(smem + (c & 1) * STGB);
            const float* Bhs = As + 128 * ROWW;
            const float* Bls = Bhs + 128 * ROWW;
#pragma unroll
            for (int s8 = 0; s8 < 4; s8++) {
                int k8 = s8 * 8;
                unsigned Ah[2][4], Al[2][4];
#pragma unroll
                for (int mt = 0; mt < 2; mt++) {
                    int ra = wm0 + mt * 16 + grp;
                    float x0 = As[ra * ROWW + k8 + qid];
                    float x1 = As[(ra + 8) * ROWW + k8 + qid];
                    float x2 = As[ra * ROWW + k8 + qid + 4];
                    float x3 = As[(ra + 8) * ROWW + k8 + qid + 4];
                    float h0 = to_tf32f(x0), h1 = to_tf32f(x1), h2 = to_tf32f(x2), h3 = to_tf32f(x3);
                    Ah[mt][0] = __float_as_uint(h0); Ah[mt][1] = __float_as_uint(h1);
                    Ah[mt][2] = __float_as_uint(h2); Ah[mt][3] = __float_as_uint(h3);
                    Al[mt][0] = __float_as_uint(to_tf32f(x0 - h0));
                    Al[mt][1] = __float_as_uint(to_tf32f(x1 - h1));
                    Al[mt][2] = __float_as_uint(to_tf32f(x2 - h2));
                    Al[mt][3] = __float_as_uint(to_tf32f(x3 - h3));
                }
#pragma unroll
                for (int nt = 0; nt < 8; nt++) {
                    int nr = wn0 + nt * 8 + grp;
                    unsigned bh[2], bl[2];
                    bh[0] = __float_as_uint(Bhs[nr * ROWW + k8 + qid]);
                    bh[1] = __float_as_uint(Bhs[nr * ROWW + k8 + qid + 4]);
                    bl[0] = __float_as_uint(Bls[nr * ROWW + k8 + qid]);
                    bl[1] = __float_as_uint(Bls[nr * ROWW + k8 + qid + 4]);
#pragma unroll
                    for (int mt = 0; mt < 2; mt++) {
                        mma8(acc[mt][nt], Ah[mt], bh);
                        mma8(acc[mt][nt], Ah[mt], bl);
                        if (full) mma8(acc[mt][nt], Al[mt], bh);
                    }
                }
            }
            __syncthreads();
        }

#pragma unroll
        for (int mt = 0; mt < 2; mt++) {
#pragma unroll
            for (int nt = 0; nt < 8; nt++) {
                int row0 = bm + wm0 + mt * 16 + grp;
                int col = bn + wn0 + nt * 8 + 2 * qid;
                float2 v0 = make_float2(acc[mt][nt][0], acc[mt][nt][1]);
                float2 v1 = make_float2(acc[mt][nt][2], acc[mt][nt][3]);
                if (bias) {
                    float2 bv = *(const float2*)(bias + col);
                    v0.x += bv.x; v0.y += bv.y; v1.x += bv.x; v1.y += bv.y;
                }
                if (relu) {
                    v0.x = fmaxf(v0.x, 0.f); v0.y = fmaxf(v0.y, 0.f);
                    v1.x = fmaxf(v1.x, 0.f); v1.y = fmaxf(v1.y, 0.f);
                }
                if (row0 < Meff)
                    *(float2*)(C + (size_t)row0 * N + col) = v0;
                if (row0 + 8 < Meff)
                    *(float2*)(C + (size_t)(row0 + 8) * N + col) = v1;
            }
        }
        __syncthreads();
    }
}

// ===== attention scores: raw Q/K staging (occ 2), register hi/lo split =====
#define ASTR 68
#define SCSM (2*128*ASTR*4)

__global__ __launch_bounds__(256, 2)
void attn_scores_mma_kernel() {
    int t = blockIdx.x;
    int qt = (int)((sqrtf(8.f * t + 1.f) - 1.f) * 0.5f);
    while ((qt + 1) * (qt + 2) / 2 <= t) qt++;
    while (qt * (qt + 1) / 2 > t) qt--;
    int kt = t - qt * (qt + 1) / 2;
    int bh = blockIdx.y;
    int b = bh >> 4, hh = bh & 15;

    extern __shared__ float sm[];
    float* Qs = sm;
    float* Ks = Qs + 128 * ASTR;

    int tid = threadIdx.x, wid = tid >> 5, lane = tid & 31;
    int grp = lane >> 2, qid = lane & 3;
    int wm0 = (wid & 3) * 32, wn0 = (wid >> 2) * 64;

    const float* qb = g_qkv + ((size_t)(b * SS + qt * 128)) * QKVS + hh * HD;
    const float* kb = g_qkv + ((size_t)(b * SS + kt * 128)) * QKVS + 1024 + hh * HD;
    for (int i = tid; i < 128 * 16; i += 256) {
        int row = i >> 4, c4 = (i & 15) * 4;
        float4 v = *(const float4*)(qb + (size_t)row * QKVS + c4);
        v.x *= 0.125f; v.y *= 0.125f; v.z *= 0.125f; v.w *= 0.125f;
        *(float4*)(Qs + row * ASTR + c4) = v;
        *(float4*)(Ks + row * ASTR + c4) = *(const float4*)(kb + (size_t)row * QKVS + c4);
    }
    __syncthreads();

    float acc[2][8][4];
#pragma unroll
    for (int mt = 0; mt < 2; mt++)
#pragma unroll
        for (int nt = 0; nt < 8; nt++)
#pragma unroll
            for (int e = 0; e < 4; e++) acc[mt][nt][e] = 0.f;

#pragma unroll
    for (int s = 0; s < 8; s++) {
        int k8 = s * 8;
        unsigned Ah[2][4], Al[2][4];
#pragma unroll
        for (int mt = 0; mt < 2; mt++) {
            int ra = wm0 + mt * 16 + grp;
            float x0 = Qs[ra * ASTR + k8 + qid];
            float x1 = Qs[(ra + 8) * ASTR + k8 + qid];
            float x2 = Qs[ra * ASTR + k8 + qid + 4];
            float x3 = Qs[(ra + 8) * ASTR + k8 + qid + 4];
            float h0 = to_tf32f(x0), h1 = to_tf32f(x1), h2 = to_tf32f(x2), h3 = to_tf32f(x3);
            Ah[mt][0] = __float_as_uint(h0); Ah[mt][1] = __float_as_uint(h1);
            Ah[mt][2] = __float_as_uint(h2); Ah[mt][3] = __float_as_uint(h3);
            Al[mt][0] = __float_as_uint(to_tf32f(x0 - h0));
            Al[mt][1] = __float_as_uint(to_tf32f(x1 - h1));
            Al[mt][2] = __float_as_uint(to_tf32f(x2 - h2));
            Al[mt][3] = __float_as_uint(to_tf32f(x3 - h3));
        }
#pragma unroll
        for (int nt = 0; nt < 8; nt++) {
            int nr = wn0 + nt * 8 + grp;
            float y0 = Ks[nr * ASTR + k8 + qid];
            float y1 = Ks[nr * ASTR + k8 + qid + 4];
            float g0 = to_tf32f(y0), g1 = to_tf32f(y1);
            unsigned bh2[2] = {__float_as_uint(g0), __float_as_uint(g1)};
            unsigned bl2[2] = {__float_as_uint(to_tf32f(y0 - g0)),
                               __float_as_uint(to_tf32f(y1 - g1))};
#pragma unroll
            for (int mt = 0; mt < 2; mt++) {
                mma8(acc[mt][nt], Ah[mt], bh2);
                mma8(acc[mt][nt], Ah[mt], bl2);
                mma8(acc[mt][nt], Al[mt], bh2);
            }
        }
    }

    bool diag = (kt == qt);
#pragma unroll
    for (int mt = 0; mt < 2; mt++) {
#pragma unroll
        for (int nt = 0; nt < 8; nt++) {
            int r0 = qt * 128 + wm0 + mt * 16 + grp;
            int c0 = kt * 128 + wn0 + nt * 8 + 2 * qid;
            float v0 = acc[mt][nt][0], v1 = acc[mt][nt][1];
            float v2 = acc[mt][nt][2], v3 = acc[mt][nt][3];
            if (diag) {
                if (c0 > r0)     v0 = -1e30f;
                if (c0 + 1 > r0) v1 = -1e30f;
                if (c0 > r0 + 8)     v2 = -1e30f;
                if (c0 + 1 > r0 + 8) v3 = -1e30f;
            }
            float* p0 = g_sc + ((size_t)bh * SS + r0) * SS + c0;
            *(float2*)p0 = make_float2(v0, v1);
            *(float2*)(p0 + 8 * SS) = make_float2(v2, v3);
        }
    }
}

// ===== prefix softmax =====
__global__ __launch_bounds__(256) void softmax_kernel() {
    int row = blockIdx.x;
    int qr = row & (SS - 1);
    int L = ((qr >> 7) + 1) << 7;
    float* sc = g_sc + (size_t)row * SS;
    int tid = threadIdx.x;
    bool valid = (tid * 4 < L);
    float4 v = valid ? *(float4*)&sc[tid * 4] : make_float4(-1e30f, -1e30f, -1e30f, -1e30f);
    __shared__ float red[8];
    __shared__ float stat;
    float m = fmaxf(fmaxf(v.x, v.y), fmaxf(v.z, v.w));
    for (int o = 16; o; o >>= 1) m = fmaxf(m, __shfl_down_sync(~0u, m, o));
    if ((tid & 31) == 0) red[tid >> 5] = m;
    __syncthreads();
    if (tid == 0) {
        float t = red[0];
        for (int i = 1; i < 8; i++) t = fmaxf(t, red[i]);
        stat = t;
    }
    __syncthreads();
    float mx = stat;
    float e0 = expf(v.x - mx), e1 = expf(v.y - mx), e2 = expf(v.z - mx), e3 = expf(v.w - mx);
    float s = e0 + e1 + e2 + e3;
    for (int o = 16; o; o >>= 1) s += __shfl_down_sync(~0u, s, o);
    __syncthreads();
    if ((tid & 31) == 0) red[tid >> 5] = s;
    __syncthreads();
    if (tid == 0) {
        float t = 0.f;
        for (int i = 0; i < 8; i++) t += red[i];
        stat = t;
    }
    __syncthreads();
    float inv = 1.0f / stat;
    if (valid) *(float4*)&sc[tid * 4] = make_float4(e0 * inv, e1 * inv, e2 * inv, e3 * inv);
}

// ===== tensor-core AV: raw double-buffered cp.async staging (LPT order) ====
#define PSTR 68
#define VSTR 72
#define PBYT (128*PSTR*4)
#define VBYT (64*VSTR*4)
#define AVSTG (PBYT + VBYT)
#define AVSM (2*AVSTG)

__global__ __launch_bounds__(256, 2)
void attn_av_mma_kernel() {
    int qt = gridDim.x - 1 - blockIdx.x;   // heaviest tiles first
    int bh = blockIdx.y;
    int b = bh >> 4, hh = bh & 15;

    extern __shared__ char smc[];
    unsigned sb = smem_u32(smc);

    int tid = threadIdx.x, wid = tid >> 5, lane = tid & 31;
    int grp = lane >> 2, qid = lane & 3;
    int wm0 = (wid & 3) * 32, wn0 = (wid >> 2) * 32;

    float acc[2][4][4];
#pragma unroll
    for (int mt = 0; mt < 2; mt++)
#pragma unroll
        for (int nt = 0; nt < 4; nt++)
#pragma unroll
            for (int e = 0; e < 4; e++) acc[mt][nt][e] = 0.f;

    int nchunks = (qt + 1) * 2;
    const float* pbase = g_sc + ((size_t)bh * SS + qt * 128) * SS;
    const float* vbase = g_qkv + ((size_t)(b * SS)) * QKVS + 2048 + hh * HD;

    {
        unsigned stP = sb;
        unsigned stV = sb + PBYT;
#pragma unroll
        for (int it = 0; it < 8; it++) {
            int idx = tid + it * 256;
            int row = idx >> 4, c4 = (idx & 15) * 4;
            CP16(stP + (row * PSTR + c4) * 4, pbase + (size_t)row * SS + c4);
        }
#pragma unroll
        for (int it = 0; it < 4; it++) {
            int idx = tid + it * 256;
            int tok = idx >> 4, d4 = (idx & 15) * 4;
            CP16(stV + (tok * VSTR + d4) * 4, vbase + (size_t)tok * QKVS + d4);
        }
        asm volatile("cp.async.commit_group;");
    }

    for (int kc = 0; kc < nchunks; kc++) {
        if (kc + 1 < nchunks) {
            unsigned st = sb + ((kc + 1) & 1) * AVSTG;
            unsigned stP = st, stV = st + PBYT;
            const float* pb = pbase + (kc + 1) * 64;
            const float* vb = vbase + (size_t)(kc + 1) * 64 * QKVS;
#pragma unroll
            for (int it = 0; it < 8; it++) {
                int idx = tid + it * 256;
                int row = idx >> 4, c4 = (idx & 15) * 4;
                CP16(stP + (row * PSTR + c4) * 4, pb + (size_t)row * SS + c4);
            }
#pragma unroll
            for (int it = 0; it < 4; it++) {
                int idx = tid + it * 256;
                int tok = idx >> 4, d4 = (idx & 15) * 4;
                CP16(stV + (tok * VSTR + d4) * 4, vb + (size_t)tok * QKVS + d4);
            }
            asm volatile("cp.async.commit_group;");
            asm volatile("cp.async.wait_group 1;");
        } else {
            asm volatile("cp.async.wait_group 0;");
        }
        __syncthreads();

        const float* Pr = (const float*)(smc + (kc & 1) * AVSTG);
        const float* Vr = Pr + 128 * PSTR;

#pragma unroll
        for (int s = 0; s < 8; s++) {
            int k8 = s * 8;
            unsigned Ah[2][4], Al[2][4];
#pragma unroll
            for (int mt = 0; mt < 2; mt++) {
                int ra = wm0 + mt * 16 + grp;
                float x0 = Pr[ra * PSTR + k8 + qid];
                float x1 = Pr[(ra + 8) * PSTR + k8 + qid];
                float x2 = Pr[ra * PSTR + k8 + qid + 4];
                float x3 = Pr[(ra + 8) * PSTR + k8 + qid + 4];
                float h0 = to_tf32f(x0), h1 = to_tf32f(x1), h2 = to_tf32f(x2), h3 = to_tf32f(x3);
                Ah[mt][0] = __float_as_uint(h0); Ah[mt][1] = __float_as_uint(h1);
                Ah[mt][2] = __float_as_uint(h2); Ah[mt][3] = __float_as_uint(h3);
                Al[mt][0] = __float_as_uint(to_tf32f(x0 - h0));
                Al[mt][1] = __float_as_uint(to_tf32f(x1 - h1));
                Al[mt][2] = __float_as_uint(to_tf32f(x2 - h2));
                Al[mt][3] = __float_as_uint(to_tf32f(x3 - h3));
            }
#pragma unroll
            for (int nt = 0; nt < 4; nt++) {
                int nr = wn0 + nt * 8 + grp;
                float y0 = Vr[(k8 + qid) * VSTR + nr];
                float y1 = Vr[(k8 + qid + 4) * VSTR + nr];
                float g0 = to_tf32f(y0), g1 = to_tf32f(y1);
                unsigned bh2[2] = {__float_as_uint(g0), __float_as_uint(g1)};
                unsigned bl2[2] = {__float_as_uint(to_tf32f(y0 - g0)),
                                   __float_as_uint(to_tf32f(y1 - g1))};
#pragma unroll
                for (int mt = 0; mt < 2; mt++) {
                    mma8(acc[mt][nt], Ah[mt], bh2);
                    mma8(acc[mt][nt], Ah[mt], bl2);
                    mma8(acc[mt][nt], Al[mt], bh2);
                }
            }
        }
        __syncthreads();
    }

#pragma unroll
    for (int mt = 0; mt < 2; mt++) {
#pragma unroll
        for (int nt = 0; nt < 4; nt++) {
            int r0 = qt * 128 + wm0 + mt * 16 + grp;
            int c0 = hh * HD + wn0 + nt * 8 + 2 * qid;
            float* p0 = g_a + ((size_t)(b * SS) + r0) * DD + c0;
            *(float2*)p0 = make_float2(acc[mt][nt][0], acc[mt][nt][1]);
            *(float2*)(p0 + 8 * DD) = make_float2(acc[mt][nt][2], acc[mt][nt][3]);
        }
    }
}

// ===== fused LN on compact rows: out = LN(sum planes + res + bias) =====
__global__ __launch_bounds__(256) void ln_fused_kernel(const float* __restrict__ inb,
                                                       int nparts,
                                                       const float* __restrict__ res,
                                                       const float* __restrict__ bias,
                                                       const float* __restrict__ g,
                                                       const float* __restrict__ bsh,
                                                       float* __restrict__ out,
                                                       int resGather, int outScatter) {
    int row = blockIdx.x;
    if (row >= g_nact) return;
    int orow = g_idx[row];
    size_t inoff = (size_t)row * DD;
    size_t resoff = (size_t)(resGather ? orow : row) * DD;
    size_t outoff = (size_t)(outScatter ? orow : row) * DD;
    int tid = threadIdx.x;
    float4 v = *(const float4*)&inb[inoff + tid * 4];
    for (int p = 1; p < nparts; p++) {
        float4 w = *(const float4*)&inb[(size_t)p * MM * DD + inoff + tid * 4];
        v.x += w.x; v.y += w.y; v.z += w.z; v.w += w.w;
    }
    float4 r = *(const float4*)&res[resoff + tid * 4];
    float4 bv = *(const float4*)&bias[tid * 4];
    v.x += r.x + bv.x; v.y += r.y + bv.y;
    v.z += r.z + bv.z; v.w += r.w + bv.w;
    __shared__ float red[8];
    __shared__ float stat;
    float s = v.x + v.y + v.z + v.w;
    for (int o = 16; o; o >>= 1) s += __shfl_down_sync(~0u, s, o);
    if ((tid & 31) == 0) red[tid >> 5] = s;
    __syncthreads();
    if (tid == 0) {
        float t = 0.f;
        for (int i = 0; i < 8; i++) t += red[i];
        stat = t * (1.0f / DD);
    }
    __syncthreads();
    float mu = stat;
    float dx = v.x - mu, dy = v.y - mu, dz = v.z - mu, dw = v.w - mu;
    float ss = dx * dx + dy * dy + dz * dz + dw * dw;
    for (int o = 16; o; o >>= 1) ss += __shfl_down_sync(~0u, ss, o);
    __syncthreads();
    if ((tid & 31) == 0) red[tid >> 5] = ss;
    __syncthreads();
    if (tid == 0) {
        float t = 0.f;
        for (int i = 0; i < 8; i++) t += red[i];
        stat = rsqrtf(t * (1.0f / DD) + 1e-5f);
    }
    __syncthreads();
    float rs = stat;
    float4 gg = *(const float4*)&g[tid * 4];
    float4 bb = *(const float4*)&bsh[tid * 4];
    *(float4*)&out[outoff + tid * 4] =
        make_float4(dx * rs * gg.x + bb.x, dy * rs * gg.y + bb.y,
                    dz * rs * gg.z + bb.z, dw * rs * gg.w + bb.w);
}

// ===== router head: zr = relu(sum of 4 tp planes + rb1); logits; argmax; counters ====
__global__ __launch_bounds__(256) void router2_kernel(const float* __restrict__ rb1,
                                                      const float* __restrict__ rw2,
                                                      const float* __restrict__ rb2) {
    int w = (blockIdx.x * blockDim.x + threadIdx.x) >> 5;
    int lane = threadIdx.x & 31;
    if (w >= MM) return;
    float s0 = 0.f, s1 = 0.f, s2 = 0.f;
#pragma unroll
    for (int u = 0; u < 4; u++) {
        int j = lane + 32 * u;
        size_t o = (size_t)w * RH + j;
        float zv = g_tp[o] + g_tp[(size_t)MM * RH + o]
                 + g_tp[2 * (size_t)MM * RH + o] + g_tp[3 * (size_t)MM * RH + o] + rb1[j];
        zv = fmaxf(zv, 0.f);
        s0 += zv * rw2[j * 3 + 0];
        s1 += zv * rw2[j * 3 + 1];
        s2 += zv * rw2[j * 3 + 2];
    }
    for (int o = 16; o; o >>= 1) {
        s0 += __shfl_down_sync(~0u, s0, o);
        s1 += __shfl_down_sync(~0u, s1, o);
        s2 += __shfl_down_sync(~0u, s2, o);
    }
    if (lane == 0) {
        s0 += rb2[0]; s1 += rb2[1]; s2 += rb2[2];
        int a = 0; float best = s0;
        if (s1 > best) { best = s1; a = 1; }
        if (s2 > best) { best = s2; a = 2; }
        g_skip[w] = (a == 0);
        atomicAdd(&g_cnt[a], 1);
    }
}

__global__ void scalars_kernel(float* out) {
    float fs = (float)g_cnt[0], ff = (float)g_cnt[1], fr = (float)g_cnt[2];
    out[(size_t)MM * VOC + 0] = (ff + fr) / (float)MM;
    out[(size_t)MM * VOC + 1] = fs / (float)(MM * NL);
    out[(size_t)MM * VOC + 2] = ff / (float)(MM * NL);
    out[(size_t)MM * VOC + 3] = fr / (float)(MM * NL);
}

extern "C" void kernel_launch(void* const* d_in, const int* in_sizes, int n_in,
                              void* d_out, int out_size) {
    const int*   x    = (const int*)d_in[0];
    const float* emb  = (const float*)d_in[1];
    const float* Wq   = (const float*)d_in[2];
    const float* bq   = (const float*)d_in[3];
    const float* Wk   = (const float*)d_in[4];
    const float* bk   = (const float*)d_in[5];
    const float* Wv   = (const float*)d_in[6];
    const float* bv   = (const float*)d_in[7];
    const float* Wo   = (const float*)d_in[8];
    const float* bo   = (const float*)d_in[9];
    const float* ln1g = (const float*)d_in[10];
    const float* ln1b = (const float*)d_in[11];
    const float* Wf1  = (const float*)d_in[12];
    const float* bf1  = (const float*)d_in[13];
    const float* Wf2  = (const float*)d_in[14];
    const float* bf2  = (const float*)d_in[15];
    const float* ln2g = (const float*)d_in[16];
    const float* ln2b = (const float*)d_in[17];
    const float* rW1  = (const float*)d_in[18];
    const float* rb1  = (const float*)d_in[19];
    const float* rW2  = (const float*)d_in[20];
    const float* rb2  = (const float*)d_in[21];
    const float* Wout = (const float*)d_in[22];
    const float* bout = (const float*)d_in[23];
    float* out = (float*)d_out;

    cudaFuncSetAttribute(tgemm_kernel, cudaFuncAttributeMaxDynamicSharedMemorySize, TGSM);
    cudaFuncSetAttribute(attn_scores_mma_kernel, cudaFuncAttributeMaxDynamicSharedMemorySize, SCSM);
    cudaFuncSetAttribute(attn_av_mma_kernel, cudaFuncAttributeMaxDynamicSharedMemorySize, AVSM);

    float *h, *h1, *tp, *qkv, *a, *f1;
    float *wqh, *wql, *woh, *wol, *w1h, *w1l, *w2h, *w2l, *wvh, *wvl, *r1h, *r1l, *bqkv;
    cudaGetSymbolAddress((void**)&h, g_h);
    cudaGetSymbolAddress((void**)&h1, g_h1);
    cudaGetSymbolAddress((void**)&tp, g_tp);
    cudaGetSymbolAddress((void**)&qkv, g_qkv);
    cudaGetSymbolAddress((void**)&a, g_a);
    cudaGetSymbolAddress((void**)&f1, g_f1);
    cudaGetSymbolAddress((void**)&wqh, g_wqkv_h);
    cudaGetSymbolAddress((void**)&wql, g_wqkv_l);
    cudaGetSymbolAddress((void**)&woh, g_wo_h);
    cudaGetSymbolAddress((void**)&wol, g_wo_l);
    cudaGetSymbolAddress((void**)&w1h, g_wf1_h);
    cudaGetSymbolAddress((void**)&w1l, g_wf1_l);
    cudaGetSymbolAddress((void**)&w2h, g_wf2_h);
    cudaGetSymbolAddress((void**)&w2l, g_wf2_l);
    cudaGetSymbolAddress((void**)&wvh, g_wout_h);
    cudaGetSymbolAddress((void**)&wvl, g_wout_l);
    cudaGetSymbolAddress((void**)&r1h, g_rw1t_h);
    cudaGetSymbolAddress((void**)&r1l, g_rw1t_l);
    cudaGetSymbolAddress((void**)&bqkv, g_bqkv);

    wtrans_kernel<<<dim3(DD/32, DD/32), 256>>>(Wq, wqh, wql, DD, DD);
    wtrans_kernel<<<dim3(DD/32, DD/32), 256>>>(Wk, wqh + (size_t)1024*DD, wql + (size_t)1024*DD, DD, DD);
    wtrans_kernel<<<dim3(DD/32, DD/32), 256>>>(Wv, wqh + (size_t)2048*DD, wql + (size_t)2048*DD, DD, DD);
    wtrans_kernel<<<dim3(DD/32, DD/32), 256>>>(Wo, woh, wol, DD, DD);
    wtrans_kernel<<<dim3(DFF/32, DD/32), 256>>>(Wf1, w1h, w1l, DD, DFF);
    wtrans_kernel<<<dim3(DD/32, DFF/32), 256>>>(Wf2, w2h, w2l, DFF, DD);
    wtrans_kernel<<<dim3(VOC/32, DD/32), 256>>>(Wout, wvh, wvl, DD, VOC);
    for (int l = 0; l < NL; l++)
        wtrans_kernel<<<dim3(RH/32, DD/32), 256>>>(rW1 + (size_t)l*DD*RH,
                                                   r1h + (size_t)l*RH*DD,
                                                   r1l + (size_t)l*RH*DD, DD, RH);
    bcat_kernel<<<QKVS/256, 256>>>(bq, bk, bv);

    zero_cnt_kernel<<<1, 32>>>();
    embed_kernel<<<MM, 256>>>(x, emb);

    const int ZST = MM * DD;
    for (int l = 0; l < NL; l++) {
        // router GEMM1 (tensor, split-K4 -> tp planes, stride MM*RH)
        tgemm_kernel<<<NPERS, 256, TGSM>>>(
            h, r1h + (size_t)l*RH*DD, r1l + (size_t)l*RH*DD, nullptr, tp, MM*RH,
            MM, RH, DD/4, DD, 0, 0, 1, MM/128, 4, 1);
        router2_kernel<<<MM/8, 256>>>(rb1 + l*RH, rW2 + (size_t)l*RH*3, rb2 + l*3);
        compact_kernel<<<1, 1024>>>();
        tgemm_kernel<<<NPERS, 256, TGSM>>>(
            h, wqh, wql, bqkv, qkv, 0, MM, QKVS, DD, DD, 0, 0, QKVS/128, MM/128, 1, 1);
        attn_scores_mma_kernel<<<dim3(36, BHT), 256, SCSM>>>();
        softmax_kernel<<<BHT*SS, 256>>>();
        attn_av_mma_kernel<<<dim3(SS/128, BHT), 256, AVSM>>>();
        tgemm_kernel<<<NPERS, 256, TGSM>>>(
            a, woh, wol, nullptr, tp, ZST, MM, DD, DD/4, DD, 0, 1, DD/128, MM/128, 4, 1);
        ln_fused_kernel<<<MM, 256>>>(tp, 4, h, bo, ln1g, ln1b, h1, 1, 0);
        tgemm_kernel<<<NPERS, 256, TGSM>>>(
            h1, w1h, w1l, bf1, f1, 0, MM, DFF, DD, DD, 1, 2, DFF/128, MM/128, 1, 1);
        tgemm_kernel<<<NPERS, 256, TGSM>>>(
            f1, w2h, w2l, nullptr, tp, ZST, MM, DD, DFF/4, DFF, 0, 2, DD/128, MM/128, 4, 1);
        ln_fused_kernel<<<MM, 256>>>(tp, 4, h1, bf2, ln2g, ln2b, h, 0, 1);
    }

    // logits: 2xTF32 (output-only)
    tgemm_kernel<<<NPERS, 256, TGSM>>>(
        h, wvh, wvl, bout, out, 0, MM, VOC, DD, DD, 0, 0, VOC/128, MM/128, 1, 0);
    scalars_kernel<<<1, 1>>>(out);
}

// round 16
// speedup vs baseline: 1.2920x; 1.0326x over previous
#include <cuda_runtime.h>
#include <math.h>
#include <stdint.h>

#define BB 2
#define SS 1024
#define DD 1024
#define NH 16
#define HD 64
#define NL 12
#define DFF 4096
#define RH 128
#define VOC 32000
#define MM (BB*SS)
#define BHT (BB*NH)
#define QKVS 3072
#define NPERS 296

// ---- static scratch ----
__device__ float g_h [MM*DD];
__device__ float g_h1[MM*DD];
__device__ float g_tp[8*MM*DD];          // split-K partials (up to 8 planes of MM*DD)
__device__ float g_qkv[MM*QKVS];
__device__ float g_a [MM*DD];
__device__ float g_f1[MM*DFF];
__device__ float g_sc[(size_t)BHT*SS*SS];
__device__ unsigned char g_skip[MM];
__device__ int g_idx[MM];
__device__ int g_nact;
__device__ int g_cnt[3];
__device__ float g_wqkv_h[(size_t)QKVS*DD], g_wqkv_l[(size_t)QKVS*DD];
__device__ float g_wo_h[(size_t)DD*DD],     g_wo_l[(size_t)DD*DD];
__device__ float g_wf1_h[(size_t)DFF*DD],   g_wf1_l[(size_t)DFF*DD];
__device__ float g_wf2_h[(size_t)DD*DFF],   g_wf2_l[(size_t)DD*DFF];
__device__ float g_wout_h[(size_t)VOC*DD],  g_wout_l[(size_t)VOC*DD];
__device__ float g_rw1t_h[(size_t)NL*RH*DD], g_rw1t_l[(size_t)NL*RH*DD];
__device__ float g_bqkv[QKVS];

static __device__ __forceinline__ unsigned smem_u32(const void* p) {
    unsigned r;
    asm("{ .reg .u64 t; cvta.to.shared.u64 t, %1; cvt.u32.u64 %0, t; }" : "=r"(r) : "l"(p));
    return r;
}
static __device__ __forceinline__ float to_tf32f(float x) {
    float r; asm("cvt.rna.tf32.f32 %0, %1;" : "=f"(r) : "f"(x)); return r;
}
static __device__ __forceinline__ void mma8(float* c, const unsigned* a, const unsigned* b) {
    asm volatile(
        "mma.sync.aligned.m16n8k8.row.col.f32.tf32.tf32.f32 "
        "{%0,%1,%2,%3}, {%4,%5,%6,%7}, {%8,%9}, {%0,%1,%2,%3};"
        : "+f"(c[0]), "+f"(c[1]), "+f"(c[2]), "+f"(c[3])
        : "r"(a[0]), "r"(a[1]), "r"(a[2]), "r"(a[3]), "r"(b[0]), "r"(b[1]));
}
#define CP16(dst, src) \
    asm volatile("cp.async.cg.shared.global [%0], [%1], 16;" :: "r"(dst), "l"(src))

__global__ void zero_cnt_kernel() { if (threadIdx.x < 3) g_cnt[threadIdx.x] = 0; }

__global__ __launch_bounds__(1024) void compact_kernel() {
    __shared__ int ps[1024];
    int tid = threadIdx.x;
    int a0 = g_skip[2 * tid] ? 0 : 1;
    int a1 = g_skip[2 * tid + 1] ? 0 : 1;
    ps[tid] = a0 + a1;
    __syncthreads();
    for (int off = 1; off < 1024; off <<= 1) {
        int v = ps[tid];
        int add = (tid >= off) ? ps[tid - off] : 0;
        __syncthreads();
        ps[tid] = v + add;
        __syncthreads();
    }
    int base = ps[tid] - (a0 + a1);
    if (a0) g_idx[base] = 2 * tid;
    if (a1) g_idx[base + a0] = 2 * tid + 1;
    if (tid == 1023) g_nact = ps[1023];
}

// W[K][N] -> Th/Tl [N][K] with tf32 hi/lo split
__global__ __launch_bounds__(256) void wtrans_kernel(const float* __restrict__ W,
                                                     float* __restrict__ Th,
                                                     float* __restrict__ Tl, int K, int N) {
    __shared__ float tile[32][33];
    int n0 = blockIdx.x * 32, k0 = blockIdx.y * 32;
    int tx = threadIdx.x & 31, ty = threadIdx.x >> 5;
    for (int i = ty; i < 32; i += 8) tile[i][tx] = W[(size_t)(k0 + i) * N + n0 + tx];
    __syncthreads();
    for (int i = ty; i < 32; i += 8) {
        float v = tile[tx][i];
        float hv = to_tf32f(v);
        float lv = to_tf32f(v - hv);
        size_t o = (size_t)(n0 + i) * K + k0 + tx;
        Th[o] = hv; Tl[o] = lv;
    }
}

__global__ void bcat_kernel(const float* __restrict__ bq, const float* __restrict__ bk,
                            const float* __restrict__ bv) {
    int i = blockIdx.x * 256 + threadIdx.x;
    g_bqkv[i] = (i < 1024) ? bq[i] : (i < 2048) ? bk[i - 1024] : bv[i - 2048];
}

__global__ __launch_bounds__(256) void embed_kernel(const int* __restrict__ x,
                                                    const float* __restrict__ emb) {
    int tok = blockIdx.x, s = tok % SS, id = x[tok];
    int d0 = threadIdx.x * 4;
    float4 ev = *(const float4*)(emb + (size_t)id * DD + d0);
    float o[4] = {ev.x, ev.y, ev.z, ev.w};
#pragma unroll
    for (int j = 0; j < 4; j++) {
        int d = d0 + j;
        float ang = (float)s * expf((float)(d & ~1) * (-9.210340371976184f / 1024.0f));
        o[j] = o[j] * 32.0f + ((d & 1) ? cosf(ang) : sinf(ang));
    }
    *(float4*)(g_h + (size_t)tok * DD + d0) = make_float4(o[0], o[1], o[2], o[3]);
}

// ===== sum of 2 split-K planes + bias [+relu] [row guard by g_nact] =====
__global__ __launch_bounds__(256) void sum2_kernel(const float* __restrict__ tp,
                                                   size_t plane,
                                                   const float* __restrict__ bias,
                                                   float* __restrict__ outp,
                                                   int N, int relu, int guard) {
    int row = blockIdx.x;
    if (guard && row >= g_nact) return;
    size_t off = (size_t)row * N;
    for (int c = threadIdx.x * 4; c < N; c += 1024) {
        float4 a = *(const float4*)(tp + off + c);
        float4 b = *(const float4*)(tp + plane + off + c);
        float4 bi = *(const float4*)(bias + c);
        float4 v = make_float4(a.x + b.x + bi.x, a.y + b.y + bi.y,
                               a.z + b.z + bi.z, a.w + b.w + bi.w);
        if (relu) {
            v.x = fmaxf(v.x, 0.f); v.y = fmaxf(v.y, 0.f);
            v.z = fmaxf(v.z, 0.f); v.w = fmaxf(v.w, 0.f);
        }
        *(float4*)(outp + off + c) = v;
    }
}

// ===== persistent mma.sync TF32 GEMM (3- or 2-term), KCH=32, 2-stage, split-K, compaction =====
#define KCH 32
#define ROWW 36
#define MATB (128*ROWW*4)
#define STGB (3*MATB)
#define TGSM (2*STGB)

__global__ __launch_bounds__(256, 2)
void tgemm_kernel(const float* __restrict__ Ab, const float* __restrict__ Bhb,
                  const float* __restrict__ Blb, const float* __restrict__ bias,
                  float* __restrict__ Cb, size_t zstride,
                  int M, int N, int Ksub, int ldk, int relu, int mode,
                  int nxt, int nyt, int nzt, int full) {
    extern __shared__ char smem[];
    unsigned sb = smem_u32(smem);
    int tid = threadIdx.x, wid = tid >> 5, lane = tid & 31;
    int grp = lane >> 2, qid = lane & 3;
    int wm0 = (wid & 3) * 32, wn0 = (wid >> 2) * 64;
    int total = nxt * nyt * nzt;

    for (int ti = blockIdx.x; ti < total; ti += NPERS) {
        int bx = ti % nxt;
        int rem = ti / nxt;
        int by = rem % nyt;
        int z = rem / nyt;
        int bm = by * 128, bn = bx * 128;
        int Meff = M;
        if (mode) {
            Meff = g_nact;
            if (bm >= Meff) continue;
        }
        const float* A  = Ab  + (size_t)z * Ksub;
        const float* Bh = Bhb + (size_t)z * Ksub;
        const float* Bl = Blb + (size_t)z * Ksub;
        float* C = Cb + (size_t)z * zstride;

        float acc[2][8][4];
#pragma unroll
        for (int mt = 0; mt < 2; mt++)
#pragma unroll
            for (int nt = 0; nt < 8; nt++)
#pragma unroll
                for (int e = 0; e < 4; e++) acc[mt][nt][e] = 0.f;

        int nchunks = Ksub / KCH;
        {
            unsigned st = sb;
#pragma unroll
            for (int it = 0; it < 4; it++) {
                int idx = tid + it * 256;
                int row = idx >> 3, q4 = (idx & 7) * 4;
                int rr = bm + row;
                if (mode == 1) rr = g_idx[rr < Meff ? rr : Meff - 1];
                CP16(st + (row * ROWW + q4) * 4, A + (size_t)rr * ldk + q4);
                CP16(st + MATB + (row * ROWW + q4) * 4, Bh + (size_t)(bn + row) * ldk + q4);
                CP16(st + 2 * MATB + (row * ROWW + q4) * 4, Bl + (size_t)(bn + row) * ldk + q4);
            }
            asm volatile("cp.async.commit_group;");
        }

        for (int c = 0; c < nchunks; c++) {
            if (c + 1 < nchunks) {
                int kb = (c + 1) * KCH;
                unsigned st = sb + ((c + 1) & 1) * STGB;
#pragma unroll
                for (int it = 0; it < 4; it++) {
                    int idx = tid + it * 256;
                    int row = idx >> 3, q4 = (idx & 7) * 4;
                    int rr = bm + row;
                    if (mode == 1) rr = g_idx[rr < Meff ? rr : Meff - 1];
                    CP16(st + (row * ROWW + q4) * 4, A + (size_t)rr * ldk + kb + q4);
                    CP16(st + MATB + (row * ROWW + q4) * 4, Bh + (size_t)(bn + row) * ldk + kb + q4);
                    CP16(st + 2 * MATB + (row * ROWW + q4) * 4, Bl + (size_t)(bn + row) * ldk + kb + q4);
                }
                asm volatile("cp.async.commit_group;");
                asm volatile("cp.async.wait_group 1;");
            } else {
                asm volatile("cp.async.wait_group 0;");
            }
            __syncthreads();
            const float* As  = (const float*)(smem + (c & 1) * STGB);
            const float* Bhs = As + 128 * ROWW;
            const float* Bls = Bhs + 128 * ROWW;
#pragma unroll
            for (int s8 = 0; s8 < 4; s8++) {
                int k8 = s8 * 8;
                unsigned Ah[2][4], Al[2][4];
#pragma unroll
                for (int mt = 0; mt < 2; mt++) {
                    int ra = wm0 + mt * 16 + grp;
                    float x0 = As[ra * ROWW + k8 + qid];
                    float x1 = As[(ra + 8) * ROWW + k8 + qid];
                    float x2 = As[ra * ROWW + k8 + qid + 4];
                    float x3 = As[(ra + 8) * ROWW + k8 + qid + 4];
                    float h0 = to_tf32f(x0), h1 = to_tf32f(x1), h2 = to_tf32f(x2), h3 = to_tf32f(x3);
                    Ah[mt][0] = __float_as_uint(h0); Ah[mt][1] = __float_as_uint(h1);
                    Ah[mt][2] = __float_as_uint(h2); Ah[mt][3] = __float_as_uint(h3);
                    Al[mt][0] = __float_as_uint(to_tf32f(x0 - h0));
                    Al[mt][1] = __float_as_uint(to_tf32f(x1 - h1));
                    Al[mt][2] = __float_as_uint(to_tf32f(x2 - h2));
                    Al[mt][3] = __float_as_uint(to_tf32f(x3 - h3));
                }
#pragma unroll
                for (int nt = 0; nt < 8; nt++) {
                    int nr = wn0 + nt * 8 + grp;
                    unsigned bh[2], bl[2];
                    bh[0] = __float_as_uint(Bhs[nr * ROWW + k8 + qid]);
                    bh[1] = __float_as_uint(Bhs[nr * ROWW + k8 + qid + 4]);
                    bl[0] = __float_as_uint(Bls[nr * ROWW + k8 + qid]);
                    bl[1] = __float_as_uint(Bls[nr * ROWW + k8 + qid + 4]);
#pragma unroll
                    for (int mt = 0; mt < 2; mt++) {
                        mma8(acc[mt][nt], Ah[mt], bh);
                        mma8(acc[mt][nt], Ah[mt], bl);
                        if (full) mma8(acc[mt][nt], Al[mt], bh);
                    }
                }
            }
            __syncthreads();
        }

#pragma unroll
        for (int mt = 0; mt < 2; mt++) {
#pragma unroll
            for (int nt = 0; nt < 8; nt++) {
                int row0 = bm + wm0 + mt * 16 + grp;
                int col = bn + wn0 + nt * 8 + 2 * qid;
                float2 v0 = make_float2(acc[mt][nt][0], acc[mt][nt][1]);
                float2 v1 = make_float2(acc[mt][nt][2], acc[mt][nt][3]);
                if (bias) {
                    float2 bv = *(const float2*)(bias + col);
                    v0.x += bv.x; v0.y += bv.y; v1.x += bv.x; v1.y += bv.y;
                }
                if (relu) {
                    v0.x = fmaxf(v0.x, 0.f); v0.y = fmaxf(v0.y, 0.f);
                    v1.x = fmaxf(v1.x, 0.f); v1.y = fmaxf(v1.y, 0.f);
                }
                if (row0 < Meff)
                    *(float2*)(C + (size_t)row0 * N + col) = v0;
                if (row0 + 8 < Meff)
                    *(float2*)(C + (size_t)(row0 + 8) * N + col) = v1;
            }
        }
        __syncthreads();
    }
}

// ===== attention scores: raw Q/K staging (occ 2), register hi/lo split =====
#define ASTR 68
#define SCSM (2*128*ASTR*4)

__global__ __launch_bounds__(256, 2)
void attn_scores_mma_kernel() {
    int t = blockIdx.x;
    int qt = (int)((sqrtf(8.f * t + 1.f) - 1.f) * 0.5f);
    while ((qt + 1) * (qt + 2) / 2 <= t) qt++;
    while (qt * (qt + 1) / 2 > t) qt--;
    int kt = t - qt * (qt + 1) / 2;
    int bh = blockIdx.y;
    int b = bh >> 4, hh = bh & 15;

    extern __shared__ float sm[];
    float* Qs = sm;
    float* Ks = Qs + 128 * ASTR;

    int tid = threadIdx.x, wid = tid >> 5, lane = tid & 31;
    int grp = lane >> 2, qid = lane & 3;
    int wm0 = (wid & 3) * 32, wn0 = (wid >> 2) * 64;

    const float* qb = g_qkv + ((size_t)(b * SS + qt * 128)) * QKVS + hh * HD;
    const float* kb = g_qkv + ((size_t)(b * SS + kt * 128)) * QKVS + 1024 + hh * HD;
    for (int i = tid; i < 128 * 16; i += 256) {
        int row = i >> 4, c4 = (i & 15) * 4;
        float4 v = *(const float4*)(qb + (size_t)row * QKVS + c4);
        v.x *= 0.125f; v.y *= 0.125f; v.z *= 0.125f; v.w *= 0.125f;
        *(float4*)(Qs + row * ASTR + c4) = v;
        *(float4*)(Ks + row * ASTR + c4) = *(const float4*)(kb + (size_t)row * QKVS + c4);
    }
    __syncthreads();

    float acc[2][8][4];
#pragma unroll
    for (int mt = 0; mt < 2; mt++)
#pragma unroll
        for (int nt = 0; nt < 8; nt++)
#pragma unroll
            for (int e = 0; e < 4; e++) acc[mt][nt][e] = 0.f;

#pragma unroll
    for (int s = 0; s < 8; s++) {
        int k8 = s * 8;
        unsigned Ah[2][4], Al[2][4];
#pragma unroll
        for (int mt = 0; mt < 2; mt++) {
            int ra = wm0 + mt * 16 + grp;
            float x0 = Qs[ra * ASTR + k8 + qid];
            float x1 = Qs[(ra + 8) * ASTR + k8 + qid];
            float x2 = Qs[ra * ASTR + k8 + qid + 4];
            float x3 = Qs[(ra + 8) * ASTR + k8 + qid + 4];
            float h0 = to_tf32f(x0), h1 = to_tf32f(x1), h2 = to_tf32f(x2), h3 = to_tf32f(x3);
            Ah[mt][0] = __float_as_uint(h0); Ah[mt][1] = __float_as_uint(h1);
            Ah[mt][2] = __float_as_uint(h2); Ah[mt][3] = __float_as_uint(h3);
            Al[mt][0] = __float_as_uint(to_tf32f(x0 - h0));
            Al[mt][1] = __float_as_uint(to_tf32f(x1 - h1));
            Al[mt][2] = __float_as_uint(to_tf32f(x2 - h2));
            Al[mt][3] = __float_as_uint(to_tf32f(x3 - h3));
        }
#pragma unroll
        for (int nt = 0; nt < 8; nt++) {
            int nr = wn0 + nt * 8 + grp;
            float y0 = Ks[nr * ASTR + k8 + qid];
            float y1 = Ks[nr * ASTR + k8 + qid + 4];
            float g0 = to_tf32f(y0), g1 = to_tf32f(y1);
            unsigned bh2[2] = {__float_as_uint(g0), __float_as_uint(g1)};
            unsigned bl2[2] = {__float_as_uint(to_tf32f(y0 - g0)),
                               __float_as_uint(to_tf32f(y1 - g1))};
#pragma unroll
            for (int mt = 0; mt < 2; mt++) {
                mma8(acc[mt][nt], Ah[mt], bh2);
                mma8(acc[mt][nt], Ah[mt], bl2);
                mma8(acc[mt][nt], Al[mt], bh2);
            }
        }
    }

    bool diag = (kt == qt);
#pragma unroll
    for (int mt = 0; mt < 2; mt++) {
#pragma unroll
        for (int nt = 0; nt < 8; nt++) {
            int r0 = qt * 128 + wm0 + mt * 16 + grp;
            int c0 = kt * 128 + wn0 + nt * 8 + 2 * qid;
            float v0 = acc[mt][nt][0], v1 = acc[mt][nt][1];
            float v2 = acc[mt][nt][2], v3 = acc[mt][nt][3];
            if (diag) {
                if (c0 > r0)     v0 = -1e30f;
                if (c0 + 1 > r0) v1 = -1e30f;
                if (c0 > r0 + 8)     v2 = -1e30f;
                if (c0 + 1 > r0 + 8) v3 = -1e30f;
            }
            float* p0 = g_sc + ((size_t)bh * SS + r0) * SS + c0;
            *(float2*)p0 = make_float2(v0, v1);
            *(float2*)(p0 + 8 * SS) = make_float2(v2, v3);
        }
    }
}

// ===== prefix softmax =====
__global__ __launch_bounds__(256) void softmax_kernel() {
    int row = blockIdx.x;
    int qr = row & (SS - 1);
    int L = ((qr >> 7) + 1) << 7;
    float* sc = g_sc + (size_t)row * SS;
    int tid = threadIdx.x;
    bool valid = (tid * 4 < L);
    float4 v = valid ? *(float4*)&sc[tid * 4] : make_float4(-1e30f, -1e30f, -1e30f, -1e30f);
    __shared__ float red[8];
    __shared__ float stat;
    float m = fmaxf(fmaxf(v.x, v.y), fmaxf(v.z, v.w));
    for (int o = 16; o; o >>= 1) m = fmaxf(m, __shfl_down_sync(~0u, m, o));
    if ((tid & 31) == 0) red[tid >> 5] = m;
    __syncthreads();
    if (tid == 0) {
        float t = red[0];
        for (int i = 1; i < 8; i++) t = fmaxf(t, red[i]);
        stat = t;
    }
    __syncthreads();
    float mx = stat;
    float e0 = expf(v.x - mx), e1 = expf(v.y - mx), e2 = expf(v.z - mx), e3 = expf(v.w - mx);
    float s = e0 + e1 + e2 + e3;
    for (int o = 16; o; o >>= 1) s += __shfl_down_sync(~0u, s, o);
    __syncthreads();
    if ((tid & 31) == 0) red[tid >> 5] = s;
    __syncthreads();
    if (tid == 0) {
        float t = 0.f;
        for (int i = 0; i < 8; i++) t += red[i];
        stat = t;
    }
    __syncthreads();
    float inv = 1.0f / stat;
    if (valid) *(float4*)&sc[tid * 4] = make_float4(e0 * inv, e1 * inv, e2 * inv, e3 * inv);
}

// ===== tensor-core AV: raw double-buffered cp.async staging (LPT order) ====
#define PSTR 68
#define VSTR 72
#define PBYT (128*PSTR*4)
#define VBYT (64*VSTR*4)
#define AVSTG (PBYT + VBYT)
#define AVSM (2*AVSTG)

__global__ __launch_bounds__(256, 2)
void attn_av_mma_kernel() {
    int qt = gridDim.x - 1 - blockIdx.x;
    int bh = blockIdx.y;
    int b = bh >> 4, hh = bh & 15;

    extern __shared__ char smc[];
    unsigned sb = smem_u32(smc);

    int tid = threadIdx.x, wid = tid >> 5, lane = tid & 31;
    int grp = lane >> 2, qid = lane & 3;
    int wm0 = (wid & 3) * 32, wn0 = (wid >> 2) * 32;

    float acc[2][4][4];
#pragma unroll
    for (int mt = 0; mt < 2; mt++)
#pragma unroll
        for (int nt = 0; nt < 4; nt++)
#pragma unroll
            for (int e = 0; e < 4; e++) acc[mt][nt][e] = 0.f;

    int nchunks = (qt + 1) * 2;
    const float* pbase = g_sc + ((size_t)bh * SS + qt * 128) * SS;
    const float* vbase = g_qkv + ((size_t)(b * SS)) * QKVS + 2048 + hh * HD;

    {
        unsigned stP = sb;
        unsigned stV = sb + PBYT;
#pragma unroll
        for (int it = 0; it < 8; it++) {
            int idx = tid + it * 256;
            int row = idx >> 4, c4 = (idx & 15) * 4;
            CP16(stP + (row * PSTR + c4) * 4, pbase + (size_t)row * SS + c4);
        }
#pragma unroll
        for (int it = 0; it < 4; it++) {
            int idx = tid + it * 256;
            int tok = idx >> 4, d4 = (idx & 15) * 4;
            CP16(stV + (tok * VSTR + d4) * 4, vbase + (size_t)tok * QKVS + d4);
        }
        asm volatile("cp.async.commit_group;");
    }

    for (int kc = 0; kc < nchunks; kc++) {
        if (kc + 1 < nchunks) {
            unsigned st = sb + ((kc + 1) & 1) * AVSTG;
            unsigned stP = st, stV = st + PBYT;
            const float* pb = pbase + (kc + 1) * 64;
            const float* vb = vbase + (size_t)(kc + 1) * 64 * QKVS;
#pragma unroll
            for (int it = 0; it < 8; it++) {
                int idx = tid + it * 256;
                int row = idx >> 4, c4 = (idx & 15) * 4;
                CP16(stP + (row * PSTR + c4) * 4, pb + (size_t)row * SS + c4);
            }
#pragma unroll
            for (int it = 0; it < 4; it++) {
                int idx = tid + it * 256;
                int tok = idx >> 4, d4 = (idx & 15) * 4;
                CP16(stV + (tok * VSTR + d4) * 4, vb + (size_t)tok * QKVS + d4);
            }
            asm volatile("cp.async.commit_group;");
            asm volatile("cp.async.wait_group 1;");
        } else {
            asm volatile("cp.async.wait_group 0;");
        }
        __syncthreads();

        const float* Pr = (const float*)(smc + (kc & 1) * AVSTG);
        const float* Vr = Pr + 128 * PSTR;

#pragma unroll
        for (int s = 0; s < 8; s++) {
            int k8 = s * 8;
            unsigned Ah[2][4], Al[2][4];
#pragma unroll
            for (int mt = 0; mt < 2; mt++) {
                int ra = wm0 + mt * 16 + grp;
                float x0 = Pr[ra * PSTR + k8 + qid];
                float x1 = Pr[(ra + 8) * PSTR + k8 + qid];
                float x2 = Pr[ra * PSTR + k8 + qid + 4];
                float x3 = Pr[(ra + 8) * PSTR + k8 + qid + 4];
                float h0 = to_tf32f(x0), h1 = to_tf32f(x1), h2 = to_tf32f(x2), h3 = to_tf32f(x3);
                Ah[mt][0] = __float_as_uint(h0); Ah[mt][1] = __float_as_uint(h1);
                Ah[mt][2] = __float_as_uint(h2); Ah[mt][3] = __float_as_uint(h3);
                Al[mt][0] = __float_as_uint(to_tf32f(x0 - h0));
                Al[mt][1] = __float_as_uint(to_tf32f(x1 - h1));
                Al[mt][2] = __float_as_uint(to_tf32f(x2 - h2));
                Al[mt][3] = __float_as_uint(to_tf32f(x3 - h3));
            }
#pragma unroll
            for (int nt = 0; nt < 4; nt++) {
                int nr = wn0 + nt * 8 + grp;
                float y0 = Vr[(k8 + qid) * VSTR + nr];
                float y1 = Vr[(k8 + qid + 4) * VSTR + nr];
                float g0 = to_tf32f(y0), g1 = to_tf32f(y1);
                unsigned bh2[2] = {__float_as_uint(g0), __float_as_uint(g1)};
                unsigned bl2[2] = {__float_as_uint(to_tf32f(y0 - g0)),
                                   __float_as_uint(to_tf32f(y1 - g1))};
#pragma unroll
                for (int mt = 0; mt < 2; mt++) {
                    mma8(acc[mt][nt], Ah[mt], bh2);
                    mma8(acc[mt][nt], Ah[mt], bl2);
                    mma8(acc[mt][nt], Al[mt], bh2);
                }
            }
        }
        __syncthreads();
    }

#pragma unroll
    for (int mt = 0; mt < 2; mt++) {
#pragma unroll
        for (int nt = 0; nt < 4; nt++) {
            int r0 = qt * 128 + wm0 + mt * 16 + grp;
            int c0 = hh * HD + wn0 + nt * 8 + 2 * qid;
            float* p0 = g_a + ((size_t)(b * SS) + r0) * DD + c0;
            *(float2*)p0 = make_float2(acc[mt][nt][0], acc[mt][nt][1]);
            *(float2*)(p0 + 8 * DD) = make_float2(acc[mt][nt][2], acc[mt][nt][3]);
        }
    }
}

// ===== fused LN on compact rows: out = LN(sum planes + res + bias) =====
__global__ __launch_bounds__(256) void ln_fused_kernel(const float* __restrict__ inb,
                                                       int nparts,
                                                       const float* __restrict__ res,
                                                       const float* __restrict__ bias,
                                                       const float* __restrict__ g,
                                                       const float* __restrict__ bsh,
                                                       float* __restrict__ out,
                                                       int resGather, int outScatter) {
    int row = blockIdx.x;
    if (row >= g_nact) return;
    int orow = g_idx[row];
    size_t inoff = (size_t)row * DD;
    size_t resoff = (size_t)(resGather ? orow : row) * DD;
    size_t outoff = (size_t)(outScatter ? orow : row) * DD;
    int tid = threadIdx.x;
    float4 v = *(const float4*)&inb[inoff + tid * 4];
    for (int p = 1; p < nparts; p++) {
        float4 w = *(const float4*)&inb[(size_t)p * MM * DD + inoff + tid * 4];
        v.x += w.x; v.y += w.y; v.z += w.z; v.w += w.w;
    }
    float4 r = *(const float4*)&res[resoff + tid * 4];
    float4 bv = *(const float4*)&bias[tid * 4];
    v.x += r.x + bv.x; v.y += r.y + bv.y;
    v.z += r.z + bv.z; v.w += r.w + bv.w;
    __shared__ float red[8];
    __shared__ float stat;
    float s = v.x + v.y + v.z + v.w;
    for (int o = 16; o; o >>= 1) s += __shfl_down_sync(~0u, s, o);
    if ((tid & 31) == 0) red[tid >> 5] = s;
    __syncthreads();
    if (tid == 0) {
        float t = 0.f;
        for (int i = 0; i < 8; i++) t += red[i];
        stat = t * (1.0f / DD);
    }
    __syncthreads();
    float mu = stat;
    float dx = v.x - mu, dy = v.y - mu, dz = v.z - mu, dw = v.w - mu;
    float ss = dx * dx + dy * dy + dz * dz + dw * dw;
    for (int o = 16; o; o >>= 1) ss += __shfl_down_sync(~0u, ss, o);
    __syncthreads();
    if ((tid & 31) == 0) red[tid >> 5] = ss;
    __syncthreads();
    if (tid == 0) {
        float t = 0.f;
        for (int i = 0; i < 8; i++) t += red[i];
        stat = rsqrtf(t * (1.0f / DD) + 1e-5f);
    }
    __syncthreads();
    float rs = stat;
    float4 gg = *(const float4*)&g[tid * 4];
    float4 bb = *(const float4*)&bsh[tid * 4];
    *(float4*)&out[outoff + tid * 4] =
        make_float4(dx * rs * gg.x + bb.x, dy * rs * gg.y + bb.y,
                    dz * rs * gg.z + bb.z, dw * rs * gg.w + bb.w);
}

// ===== router head: zr = relu(sum of 4 tp planes + rb1); logits; argmax; counters ====
__global__ __launch_bounds__(256) void router2_kernel(const float* __restrict__ rb1,
                                                      const float* __restrict__ rw2,
                                                      const float* __restrict__ rb2) {
    int w = (blockIdx.x * blockDim.x + threadIdx.x) >> 5;
    int lane = threadIdx.x & 31;
    if (w >= MM) return;
    float s0 = 0.f, s1 = 0.f, s2 = 0.f;
#pragma unroll
    for (int u = 0; u < 4; u++) {
        int j = lane + 32 * u;
        size_t o = (size_t)w * RH + j;
        float zv = g_tp[o] + g_tp[(size_t)MM * RH + o]
                 + g_tp[2 * (size_t)MM * RH + o] + g_tp[3 * (size_t)MM * RH + o] + rb1[j];
        zv = fmaxf(zv, 0.f);
        s0 += zv * rw2[j * 3 + 0];
        s1 += zv * rw2[j * 3 + 1];
        s2 += zv * rw2[j * 3 + 2];
    }
    for (int o = 16; o; o >>= 1) {
        s0 += __shfl_down_sync(~0u, s0, o);
        s1 += __shfl_down_sync(~0u, s1, o);
        s2 += __shfl_down_sync(~0u, s2, o);
    }
    if (lane == 0) {
        s0 += rb2[0]; s1 += rb2[1]; s2 += rb2[2];
        int a = 0; float best = s0;
        if (s1 > best) { best = s1; a = 1; }
        if (s2 > best) { best = s2; a = 2; }
        g_skip[w] = (a == 0);
        atomicAdd(&g_cnt[a], 1);
    }
}

__global__ void scalars_kernel(float* out) {
    float fs = (float)g_cnt[0], ff = (float)g_cnt[1], fr = (float)g_cnt[2];
    out[(size_t)MM * VOC + 0] = (ff + fr) / (float)MM;
    out[(size_t)MM * VOC + 1] = fs / (float)(MM * NL);
    out[(size_t)MM * VOC + 2] = ff / (float)(MM * NL);
    out[(size_t)MM * VOC + 3] = fr / (float)(MM * NL);
}

extern "C" void kernel_launch(void* const* d_in, const int* in_sizes, int n_in,
                              void* d_out, int out_size) {
    const int*   x    = (const int*)d_in[0];
    const float* emb  = (const float*)d_in[1];
    const float* Wq   = (const float*)d_in[2];
    const float* bq   = (const float*)d_in[3];
    const float* Wk   = (const float*)d_in[4];
    const float* bk   = (const float*)d_in[5];
    const float* Wv   = (const float*)d_in[6];
    const float* bv   = (const float*)d_in[7];
    const float* Wo   = (const float*)d_in[8];
    const float* bo   = (const float*)d_in[9];
    const float* ln1g = (const float*)d_in[10];
    const float* ln1b = (const float*)d_in[11];
    const float* Wf1  = (const float*)d_in[12];
    const float* bf1  = (const float*)d_in[13];
    const float* Wf2  = (const float*)d_in[14];
    const float* bf2  = (const float*)d_in[15];
    const float* ln2g = (const float*)d_in[16];
    const float* ln2b = (const float*)d_in[17];
    const float* rW1  = (const float*)d_in[18];
    const float* rb1  = (const float*)d_in[19];
    const float* rW2  = (const float*)d_in[20];
    const float* rb2  = (const float*)d_in[21];
    const float* Wout = (const float*)d_in[22];
    const float* bout = (const float*)d_in[23];
    float* out = (float*)d_out;

    cudaFuncSetAttribute(tgemm_kernel, cudaFuncAttributeMaxDynamicSharedMemorySize, TGSM);
    cudaFuncSetAttribute(attn_scores_mma_kernel, cudaFuncAttributeMaxDynamicSharedMemorySize, SCSM);
    cudaFuncSetAttribute(attn_av_mma_kernel, cudaFuncAttributeMaxDynamicSharedMemorySize, AVSM);

    float *h, *h1, *tp, *qkv, *a, *f1;
    float *wqh, *wql, *woh, *wol, *w1h, *w1l, *w2h, *w2l, *wvh, *wvl, *r1h, *r1l, *bqkv;
    cudaGetSymbolAddress((void**)&h, g_h);
    cudaGetSymbolAddress((void**)&h1, g_h1);
    cudaGetSymbolAddress((void**)&tp, g_tp);
    cudaGetSymbolAddress((void**)&qkv, g_qkv);
    cudaGetSymbolAddress((void**)&a, g_a);
    cudaGetSymbolAddress((void**)&f1, g_f1);
    cudaGetSymbolAddress((void**)&wqh, g_wqkv_h);
    cudaGetSymbolAddress((void**)&wql, g_wqkv_l);
    cudaGetSymbolAddress((void**)&woh, g_wo_h);
    cudaGetSymbolAddress((void**)&wol, g_wo_l);
    cudaGetSymbolAddress((void**)&w1h, g_wf1_h);
    cudaGetSymbolAddress((void**)&w1l, g_wf1_l);
    cudaGetSymbolAddress((void**)&w2h, g_wf2_h);
    cudaGetSymbolAddress((void**)&w2l, g_wf2_l);
    cudaGetSymbolAddress((void**)&wvh, g_wout_h);
    cudaGetSymbolAddress((void**)&wvl, g_wout_l);
    cudaGetSymbolAddress((void**)&r1h, g_rw1t_h);
    cudaGetSymbolAddress((void**)&r1l, g_rw1t_l);
    cudaGetSymbolAddress((void**)&bqkv, g_bqkv);

    wtrans_kernel<<<dim3(DD/32, DD/32), 256>>>(Wq, wqh, wql, DD, DD);
    wtrans_kernel<<<dim3(DD/32, DD/32), 256>>>(Wk, wqh + (size_t)1024*DD, wql + (size_t)1024*DD, DD, DD);
    wtrans_kernel<<<dim3(DD/32, DD/32), 256>>>(Wv, wqh + (size_t)2048*DD, wql + (size_t)2048*DD, DD, DD);
    wtrans_kernel<<<dim3(DD/32, DD/32), 256>>>(Wo, woh, wol, DD, DD);
    wtrans_kernel<<<dim3(DFF/32, DD/32), 256>>>(Wf1, w1h, w1l, DD, DFF);
    wtrans_kernel<<<dim3(DD/32, DFF/32), 256>>>(Wf2, w2h, w2l, DFF, DD);
    wtrans_kernel<<<dim3(VOC/32, DD/32), 256>>>(Wout, wvh, wvl, DD, VOC);
    for (int l = 0; l < NL; l++)
        wtrans_kernel<<<dim3(RH/32, DD/32), 256>>>(rW1 + (size_t)l*DD*RH,
                                                   r1h + (size_t)l*RH*DD,
                                                   r1l + (size_t)l*RH*DD, DD, RH);
    bcat_kernel<<<QKVS/256, 256>>>(bq, bk, bv);

    zero_cnt_kernel<<<1, 32>>>();
    embed_kernel<<<MM, 256>>>(x, emb);

    const size_t ZST = (size_t)MM * DD;
    for (int l = 0; l < NL; l++) {
        // router GEMM1 (tensor, split-K4 -> tp planes, stride MM*RH)
        tgemm_kernel<<<NPERS, 256, TGSM>>>(
            h, r1h + (size_t)l*RH*DD, r1l + (size_t)l*RH*DD, nullptr, tp, (size_t)MM*RH,
            MM, RH, DD/4, DD, 0, 0, 1, MM/128, 4, 1);
        router2_kernel<<<MM/8, 256>>>(rb1 + l*RH, rW2 + (size_t)l*RH*3, rb2 + l*3);
        compact_kernel<<<1, 1024>>>();
        // QKV split-K2 -> tp planes (stride MM*QKVS), then sum+bias
        tgemm_kernel<<<NPERS, 256, TGSM>>>(
            h, wqh, wql, nullptr, tp, (size_t)MM*QKVS,
            MM, QKVS, DD/2, DD, 0, 0, QKVS/128, MM/128, 2, 1);
        sum2_kernel<<<MM, 256>>>(tp, (size_t)MM*QKVS, bqkv, qkv, QKVS, 0, 0);
        attn_scores_mma_kernel<<<dim3(36, BHT), 256, SCSM>>>();
        softmax_kernel<<<BHT*SS, 256>>>();
        attn_av_mma_kernel<<<dim3(SS/128, BHT), 256, AVSM>>>();
        // O-proj: gather active rows, split-K4 -> tp planes
        tgemm_kernel<<<NPERS, 256, TGSM>>>(
            a, woh, wol, nullptr, tp, ZST, MM, DD, DD/4, DD, 0, 1, DD/128, MM/128, 4, 1);
        ln_fused_kernel<<<MM, 256>>>(tp, 4, h, bo, ln1g, ln1b, h1, 1, 0);
        // FF1 compact, split-K2 -> tp planes (stride MM*DFF), sum+bias+relu
        tgemm_kernel<<<NPERS, 256, TGSM>>>(
            h1, w1h, w1l, nullptr, tp, (size_t)MM*DFF,
            MM, DFF, DD/2, DD, 0, 2, DFF/128, MM/128, 2, 1);
        sum2_kernel<<<MM, 256>>>(tp, (size_t)MM*DFF, bf1, f1, DFF, 1, 1);
        // FF2 compact, split-K8 -> 8 tp planes
        tgemm_kernel<<<NPERS, 256, TGSM>>>(
            f1, w2h, w2l, nullptr, tp, ZST, MM, DD, DFF/8, DFF, 0, 2, DD/128, MM/128, 8, 1);
        ln_fused_kernel<<<MM, 256>>>(tp, 8, h1, bf2, ln2g, ln2b, h, 0, 1);
    }

    // logits: 2xTF32 (output-only)
    tgemm_kernel<<<NPERS, 256, TGSM>>>(
        h, wvh, wvl, bout, out, 0, MM, VOC, DD, DD, 0, 0, VOC/128, MM/128, 1, 0);
    scalars_kernel<<<1, 1>>>(out);
}

// round 17
// speedup vs baseline: 1.7426x; 1.3488x over previous
#include <cuda_runtime.h>
#include <cuda_fp16.h>
#include <math.h>
#include <stdint.h>

#define BB 2
#define SS 1024
#define DD 1024
#define NH 16
#define HD 64
#define NL 12
#define DFF 4096
#define RH 128
#define VOC 32000
#define MM (BB*SS)
#define BHT (BB*NH)
#define QKVS 3072
#define NPERS 296
#define SCL 9.5367431640625e-07f   // 2^-20, exact

// ---- static scratch ----
__device__ float g_h [MM*DD];
__device__ float g_h1[MM*DD];
__device__ float g_tp[8*MM*DD];
__device__ float g_qkv[MM*QKVS];
__device__ float g_a [MM*DD];
__device__ float g_f1[MM*DFF];
__device__ float g_sc[(size_t)BHT*SS*SS];
__device__ unsigned char g_skip[MM];
__device__ int g_idx[MM];
__device__ int g_nact;
__device__ int g_cnt[3];
// fp16 split weights, [N][K], scaled x1024
__device__ __half g_wqkv_h[(size_t)QKVS*DD], g_wqkv_l[(size_t)QKVS*DD];
__device__ __half g_wo_h[(size_t)DD*DD],     g_wo_l[(size_t)DD*DD];
__device__ __half g_wf1_h[(size_t)DFF*DD],   g_wf1_l[(size_t)DFF*DD];
__device__ __half g_wf2_h[(size_t)DD*DFF],   g_wf2_l[(size_t)DD*DFF];
__device__ __half g_wout_h[(size_t)VOC*DD],  g_wout_l[(size_t)VOC*DD];
__device__ __half g_rw1t_h[(size_t)NL*RH*DD], g_rw1t_l[(size_t)NL*RH*DD];
__device__ float g_bqkv[QKVS];

static __device__ __forceinline__ unsigned smem_u32(const void* p) {
    unsigned r;
    asm("{ .reg .u64 t; cvta.to.shared.u64 t, %1; cvt.u32.u64 %0, t; }" : "=r"(r) : "l"(p));
    return r;
}
static __device__ __forceinline__ float to_tf32f(float x) {
    float r; asm("cvt.rna.tf32.f32 %0, %1;" : "=f"(r) : "f"(x)); return r;
}
// tf32 mma (attention kernels)
static __device__ __forceinline__ void mma8(float* c, const unsigned* a, const unsigned* b) {
    asm volatile(
        "mma.sync.aligned.m16n8k8.row.col.f32.tf32.tf32.f32 "
        "{%0,%1,%2,%3}, {%4,%5,%6,%7}, {%8,%9}, {%0,%1,%2,%3};"
        : "+f"(c[0]), "+f"(c[1]), "+f"(c[2]), "+f"(c[3])
        : "r"(a[0]), "r"(a[1]), "r"(a[2]), "r"(a[3]), "r"(b[0]), "r"(b[1]));
}
// fp16 mma (GEMMs)
static __device__ __forceinline__ void mmah(float* c, const unsigned* a, const unsigned* b) {
    asm volatile(
        "mma.sync.aligned.m16n8k16.row.col.f32.f16.f16.f32 "
        "{%0,%1,%2,%3}, {%4,%5,%6,%7}, {%8,%9}, {%0,%1,%2,%3};"
        : "+f"(c[0]), "+f"(c[1]), "+f"(c[2]), "+f"(c[3])
        : "r"(a[0]), "r"(a[1]), "r"(a[2]), "r"(a[3]), "r"(b[0]), "r"(b[1]));
}
// split scaled fp32 pair -> packed fp16 hi/lo half2 regs
static __device__ __forceinline__ void sp2(float2 p, unsigned &hr, unsigned &lr) {
    float s0 = p.x * 1024.f, s1 = p.y * 1024.f;
    __half h0 = __float2half_rn(s0), h1 = __float2half_rn(s1);
    __half l0 = __float2half_rn(s0 - __half2float(h0));
    __half l1 = __float2half_rn(s1 - __half2float(h1));
    hr = ((unsigned)__half_as_ushort(h1) << 16) | __half_as_ushort(h0);
    lr = ((unsigned)__half_as_ushort(l1) << 16) | __half_as_ushort(l0);
}
#define CP16(dst, src) \
    asm volatile("cp.async.cg.shared.global [%0], [%1], 16;" :: "r"(dst), "l"(src))

__global__ void zero_cnt_kernel() { if (threadIdx.x < 3) g_cnt[threadIdx.x] = 0; }

__global__ __launch_bounds__(1024) void compact_kernel() {
    __shared__ int ps[1024];
    int tid = threadIdx.x;
    int a0 = g_skip[2 * tid] ? 0 : 1;
    int a1 = g_skip[2 * tid + 1] ? 0 : 1;
    ps[tid] = a0 + a1;
    __syncthreads();
    for (int off = 1; off < 1024; off <<= 1) {
        int v = ps[tid];
        int add = (tid >= off) ? ps[tid - off] : 0;
        __syncthreads();
        ps[tid] = v + add;
        __syncthreads();
    }
    int base = ps[tid] - (a0 + a1);
    if (a0) g_idx[base] = 2 * tid;
    if (a1) g_idx[base + a0] = 2 * tid + 1;
    if (tid == 1023) g_nact = ps[1023];
}

// W[K][N] fp32 -> Th/Tl [N][K] fp16, scaled x1024
__global__ __launch_bounds__(256) void wtrans_kernel(const float* __restrict__ W,
                                                     __half* __restrict__ Th,
                                                     __half* __restrict__ Tl, int K, int N) {
    __shared__ float tile[32][33];
    int n0 = blockIdx.x * 32, k0 = blockIdx.y * 32;
    int tx = threadIdx.x & 31, ty = threadIdx.x >> 5;
    for (int i = ty; i < 32; i += 8) tile[i][tx] = W[(size_t)(k0 + i) * N + n0 + tx];
    __syncthreads();
    for (int i = ty; i < 32; i += 8) {
        float v = tile[tx][i] * 1024.f;
        __half hv = __float2half_rn(v);
        __half lv = __float2half_rn(v - __half2float(hv));
        size_t o = (size_t)(n0 + i) * K + k0 + tx;
        Th[o] = hv; Tl[o] = lv;
    }
}

__global__ void bcat_kernel(const float* __restrict__ bq, const float* __restrict__ bk,
                            const float* __restrict__ bv) {
    int i = blockIdx.x * 256 + threadIdx.x;
    g_bqkv[i] = (i < 1024) ? bq[i] : (i < 2048) ? bk[i - 1024] : bv[i - 2048];
}

__global__ __launch_bounds__(256) void embed_kernel(const int* __restrict__ x,
                                                    const float* __restrict__ emb) {
    int tok = blockIdx.x, s = tok % SS, id = x[tok];
    int d0 = threadIdx.x * 4;
    float4 ev = *(const float4*)(emb + (size_t)id * DD + d0);
    float o[4] = {ev.x, ev.y, ev.z, ev.w};
#pragma unroll
    for (int j = 0; j < 4; j++) {
        int d = d0 + j;
        float ang = (float)s * expf((float)(d & ~1) * (-9.210340371976184f / 1024.0f));
        o[j] = o[j] * 32.0f + ((d & 1) ? cosf(ang) : sinf(ang));
    }
    *(float4*)(g_h + (size_t)tok * DD + d0) = make_float4(o[0], o[1], o[2], o[3]);
}

// ===== sum of 2 split-K planes + bias [+relu] [row guard] =====
__global__ __launch_bounds__(256) void sum2_kernel(const float* __restrict__ tp,
                                                   size_t plane,
                                                   const float* __restrict__ bias,
                                                   float* __restrict__ outp,
                                                   int N, int relu, int guard) {
    int row = blockIdx.x;
    if (guard && row >= g_nact) return;
    size_t off = (size_t)row * N;
    for (int c = threadIdx.x * 4; c < N; c += 1024) {
        float4 a = *(const float4*)(tp + off + c);
        float4 b = *(const float4*)(tp + plane + off + c);
        float4 bi = *(const float4*)(bias + c);
        float4 v = make_float4(a.x + b.x + bi.x, a.y + b.y + bi.y,
                               a.z + b.z + bi.z, a.w + b.w + bi.w);
        if (relu) {
            v.x = fmaxf(v.x, 0.f); v.y = fmaxf(v.y, 0.f);
            v.z = fmaxf(v.z, 0.f); v.w = fmaxf(v.w, 0.f);
        }
        *(float4*)(outp + off + c) = v;
    }
}

// ===== persistent 3xFP16 GEMM, KCH=32, 2-stage, split-K, compaction =====
#define KCH 32
#define ROWW 36                   // A row stride (floats)
#define ROWH 40                   // B row stride (halves)
#define ABYT (128*ROWW*4)         // 18432
#define BBYT (128*ROWH*2)         // 10240
#define STGB (ABYT + 2*BBYT)      // 38912
#define TGSM (2*STGB)             // 77824

__global__ __launch_bounds__(256, 2)
void tgemm_kernel(const float* __restrict__ Ab, const __half* __restrict__ Bhb,
                  const __half* __restrict__ Blb, const float* __restrict__ bias,
                  float* __restrict__ Cb, size_t zstride,
                  int M, int N, int Ksub, int ldk, int relu, int mode,
                  int nxt, int nyt, int nzt, int full) {
    extern __shared__ char smem[];
    unsigned sb = smem_u32(smem);
    int tid = threadIdx.x, wid = tid >> 5, lane = tid & 31;
    int grp = lane >> 2, qid = lane & 3;
    int wm0 = (wid & 3) * 32, wn0 = (wid >> 2) * 64;
    int total = nxt * nyt * nzt;

    for (int ti = blockIdx.x; ti < total; ti += NPERS) {
        int bx = ti % nxt;
        int rem = ti / nxt;
        int by = rem % nyt;
        int z = rem / nyt;
        int bm = by * 128, bn = bx * 128;
        int Meff = M;
        if (mode) {
            Meff = g_nact;
            if (bm >= Meff) continue;
        }
        const float*  A  = Ab  + (size_t)z * Ksub;
        const __half* Bh = Bhb + (size_t)z * Ksub;
        const __half* Bl = Blb + (size_t)z * Ksub;
        float* C = Cb + (size_t)z * zstride;

        float acc[2][8][4];
#pragma unroll
        for (int mt = 0; mt < 2; mt++)
#pragma unroll
            for (int nt = 0; nt < 8; nt++)
#pragma unroll
                for (int e = 0; e < 4; e++) acc[mt][nt][e] = 0.f;

        int nchunks = Ksub / KCH;
        // staging: A 1024 chunks (4 it), Bh 512 (2 it), Bl 512 (2 it)
#pragma unroll
        for (int it = 0; it < 8; it++) {
            unsigned st = sb;
            if (it < 4) {
                int idx = tid + it * 256;
                int row = idx >> 3, q4 = (idx & 7) * 4;
                int rr = bm + row;
                if (mode == 1) rr = g_idx[rr < Meff ? rr : Meff - 1];
                CP16(st + (row * ROWW + q4) * 4, A + (size_t)rr * ldk + q4);
            } else if (it < 6) {
                int idx = tid + (it - 4) * 256;
                int row = idx >> 2, c8 = (idx & 3) * 8;
                CP16(st + ABYT + row * (ROWH * 2) + c8 * 2,
                     Bh + (size_t)(bn + row) * ldk + c8);
            } else {
                int idx = tid + (it - 6) * 256;
                int row = idx >> 2, c8 = (idx & 3) * 8;
                CP16(st + ABYT + BBYT + row * (ROWH * 2) + c8 * 2,
                     Bl + (size_t)(bn + row) * ldk + c8);
            }
        }
        asm volatile("cp.async.commit_group;");

        for (int c = 0; c < nchunks; c++) {
            if (c + 1 < nchunks) {
                int kb = (c + 1) * KCH;
                unsigned st = sb + ((c + 1) & 1) * STGB;
#pragma unroll
                for (int it = 0; it < 8; it++) {
                    if (it < 4) {
                        int idx = tid + it * 256;
                        int row = idx >> 3, q4 = (idx & 7) * 4;
                        int rr = bm + row;
                        if (mode == 1) rr = g_idx[rr < Meff ? rr : Meff - 1];
                        CP16(st + (row * ROWW + q4) * 4, A + (size_t)rr * ldk + kb + q4);
                    } else if (it < 6) {
                        int idx = tid + (it - 4) * 256;
                        int row = idx >> 2, c8 = (idx & 3) * 8;
                        CP16(st + ABYT + row * (ROWH * 2) + c8 * 2,
                             Bh + (size_t)(bn + row) * ldk + kb + c8);
                    } else {
                        int idx = tid + (it - 6) * 256;
                        int row = idx >> 2, c8 = (idx & 3) * 8;
                        CP16(st + ABYT + BBYT + row * (ROWH * 2) + c8 * 2,
                             Bl + (size_t)(bn + row) * ldk + kb + c8);
                    }
                }
                asm volatile("cp.async.commit_group;");
                asm volatile("cp.async.wait_group 1;");
            } else {
                asm volatile("cp.async.wait_group 0;");
            }
            __syncthreads();
            const float*  As  = (const float*)(smem + (c & 1) * STGB);
            const __half* Bhs = (const __half*)(smem + (c & 1) * STGB + ABYT);
            const __half* Bls = (const __half*)(smem + (c & 1) * STGB + ABYT + BBYT);
#pragma unroll
            for (int s16 = 0; s16 < 2; s16++) {
                int k16 = s16 * 16;
                int cb = k16 + 2 * qid;
                unsigned Ah[2][4], Al[2][4];
#pragma unroll
                for (int mt = 0; mt < 2; mt++) {
                    int ra = wm0 + mt * 16 + grp;
                    float2 p0 = *(const float2*)&As[ra * ROWW + cb];
                    float2 p1 = *(const float2*)&As[(ra + 8) * ROWW + cb];
                    float2 p2 = *(const float2*)&As[ra * ROWW + cb + 8];
                    float2 p3 = *(const float2*)&As[(ra + 8) * ROWW + cb + 8];
                    sp2(p0, Ah[mt][0], Al[mt][0]);
                    sp2(p1, Ah[mt][1], Al[mt][1]);
                    sp2(p2, Ah[mt][2], Al[mt][2]);
                    sp2(p3, Ah[mt][3], Al[mt][3]);
                }
#pragma unroll
                for (int nt = 0; nt < 8; nt++) {
                    int nr = wn0 + nt * 8 + grp;
                    unsigned bh[2], bl[2];
                    bh[0] = *(const unsigned*)&Bhs[nr * ROWH + cb];
                    bh[1] = *(const unsigned*)&Bhs[nr * ROWH + cb + 8];
                    bl[0] = *(const unsigned*)&Bls[nr * ROWH + cb];
                    bl[1] = *(const unsigned*)&Bls[nr * ROWH + cb + 8];
#pragma unroll
                    for (int mt = 0; mt < 2; mt++) {
                        mmah(acc[mt][nt], Ah[mt], bh);
                        mmah(acc[mt][nt], Ah[mt], bl);
                        if (full) mmah(acc[mt][nt], Al[mt], bh);
                    }
                }
            }
            __syncthreads();
        }

#pragma unroll
        for (int mt = 0; mt < 2; mt++) {
#pragma unroll
            for (int nt = 0; nt < 8; nt++) {
                int row0 = bm + wm0 + mt * 16 + grp;
                int col = bn + wn0 + nt * 8 + 2 * qid;
                float2 v0 = make_float2(acc[mt][nt][0] * SCL, acc[mt][nt][1] * SCL);
                float2 v1 = make_float2(acc[mt][nt][2] * SCL, acc[mt][nt][3] * SCL);
                if (bias) {
                    float2 bv = *(const float2*)(bias + col);
                    v0.x += bv.x; v0.y += bv.y; v1.x += bv.x; v1.y += bv.y;
                }
                if (relu) {
                    v0.x = fmaxf(v0.x, 0.f); v0.y = fmaxf(v0.y, 0.f);
                    v1.x = fmaxf(v1.x, 0.f); v1.y = fmaxf(v1.y, 0.f);
                }
                if (row0 < Meff)
                    *(float2*)(C + (size_t)row0 * N + col) = v0;
                if (row0 + 8 < Meff)
                    *(float2*)(C + (size_t)(row0 + 8) * N + col) = v1;
            }
        }
        __syncthreads();
    }
}

// ===== attention scores: raw Q/K staging (occ 2), tf32x3 =====
#define ASTR 68
#define SCSM (2*128*ASTR*4)

__global__ __launch_bounds__(256, 2)
void attn_scores_mma_kernel() {
    int t = blockIdx.x;
    int qt = (int)((sqrtf(8.f * t + 1.f) - 1.f) * 0.5f);
    while ((qt + 1) * (qt + 2) / 2 <= t) qt++;
    while (qt * (qt + 1) / 2 > t) qt--;
    int kt = t - qt * (qt + 1) / 2;
    int bh = blockIdx.y;
    int b = bh >> 4, hh = bh & 15;

    extern __shared__ float sm[];
    float* Qs = sm;
    float* Ks = Qs + 128 * ASTR;

    int tid = threadIdx.x, wid = tid >> 5, lane = tid & 31;
    int grp = lane >> 2, qid = lane & 3;
    int wm0 = (wid & 3) * 32, wn0 = (wid >> 2) * 64;

    const float* qb = g_qkv + ((size_t)(b * SS + qt * 128)) * QKVS + hh * HD;
    const float* kb = g_qkv + ((size_t)(b * SS + kt * 128)) * QKVS + 1024 + hh * HD;
    for (int i = tid; i < 128 * 16; i += 256) {
        int row = i >> 4, c4 = (i & 15) * 4;
        float4 v = *(const float4*)(qb + (size_t)row * QKVS + c4);
        v.x *= 0.125f; v.y *= 0.125f; v.z *= 0.125f; v.w *= 0.125f;
        *(float4*)(Qs + row * ASTR + c4) = v;
        *(float4*)(Ks + row * ASTR + c4) = *(const float4*)(kb + (size_t)row * QKVS + c4);
    }
    __syncthreads();

    float acc[2][8][4];
#pragma unroll
    for (int mt = 0; mt < 2; mt++)
#pragma unroll
        for (int nt = 0; nt < 8; nt++)
#pragma unroll
            for (int e = 0; e < 4; e++) acc[mt][nt][e] = 0.f;

#pragma unroll
    for (int s = 0; s < 8; s++) {
        int k8 = s * 8;
        unsigned Ah[2][4], Al[2][4];
#pragma unroll
        for (int mt = 0; mt < 2; mt++) {
            int ra = wm0 + mt * 16 + grp;
            float x0 = Qs[ra * ASTR + k8 + qid];
            float x1 = Qs[(ra + 8) * ASTR + k8 + qid];
            float x2 = Qs[ra * ASTR + k8 + qid + 4];
            float x3 = Qs[(ra + 8) * ASTR + k8 + qid + 4];
            float h0 = to_tf32f(x0), h1 = to_tf32f(x1), h2 = to_tf32f(x2), h3 = to_tf32f(x3);
            Ah[mt][0] = __float_as_uint(h0); Ah[mt][1] = __float_as_uint(h1);
            Ah[mt][2] = __float_as_uint(h2); Ah[mt][3] = __float_as_uint(h3);
            Al[mt][0] = __float_as_uint(to_tf32f(x0 - h0));
            Al[mt][1] = __float_as_uint(to_tf32f(x1 - h1));
            Al[mt][2] = __float_as_uint(to_tf32f(x2 - h2));
            Al[mt][3] = __float_as_uint(to_tf32f(x3 - h3));
        }
#pragma unroll
        for (int nt = 0; nt < 8; nt++) {
            int nr = wn0 + nt * 8 + grp;
            float y0 = Ks[nr * ASTR + k8 + qid];
            float y1 = Ks[nr * ASTR + k8 + qid + 4];
            float g0 = to_tf32f(y0), g1 = to_tf32f(y1);
            unsigned bh2[2] = {__float_as_uint(g0), __float_as_uint(g1)};
            unsigned bl2[2] = {__float_as_uint(to_tf32f(y0 - g0)),
                               __float_as_uint(to_tf32f(y1 - g1))};
#pragma unroll
            for (int mt = 0; mt < 2; mt++) {
                mma8(acc[mt][nt], Ah[mt], bh2);
                mma8(acc[mt][nt], Ah[mt], bl2);
                mma8(acc[mt][nt], Al[mt], bh2);
            }
        }
    }

    bool diag = (kt == qt);
#pragma unroll
    for (int mt = 0; mt < 2; mt++) {
#pragma unroll
        for (int nt = 0; nt < 8; nt++) {
            int r0 = qt * 128 + wm0 + mt * 16 + grp;
            int c0 = kt * 128 + wn0 + nt * 8 + 2 * qid;
            float v0 = acc[mt][nt][0], v1 = acc[mt][nt][1];
            float v2 = acc[mt][nt][2], v3 = acc[mt][nt][3];
            if (diag) {
                if (c0 > r0)     v0 = -1e30f;
                if (c0 + 1 > r0) v1 = -1e30f;
                if (c0 > r0 + 8)     v2 = -1e30f;
                if (c0 + 1 > r0 + 8) v3 = -1e30f;
            }
            float* p0 = g_sc + ((size_t)bh * SS + r0) * SS + c0;
            *(float2*)p0 = make_float2(v0, v1);
            *(float2*)(p0 + 8 * SS) = make_float2(v2, v3);
        }
    }
}

// ===== prefix softmax =====
__global__ __launch_bounds__(256) void softmax_kernel() {
    int row = blockIdx.x;
    int qr = row & (SS - 1);
    int L = ((qr >> 7) + 1) << 7;
    float* sc = g_sc + (size_t)row * SS;
    int tid = threadIdx.x;
    bool valid = (tid * 4 < L);
    float4 v = valid ? *(float4*)&sc[tid * 4] : make_float4(-1e30f, -1e30f, -1e30f, -1e30f);
    __shared__ float red[8];
    __shared__ float stat;
    float m = fmaxf(fmaxf(v.x, v.y), fmaxf(v.z, v.w));
    for (int o = 16; o; o >>= 1) m = fmaxf(m, __shfl_down_sync(~0u, m, o));
    if ((tid & 31) == 0) red[tid >> 5] = m;
    __syncthreads();
    if (tid == 0) {
        float t = red[0];
        for (int i = 1; i < 8; i++) t = fmaxf(t, red[i]);
        stat = t;
    }
    __syncthreads();
    float mx = stat;
    float e0 = expf(v.x - mx), e1 = expf(v.y - mx), e2 = expf(v.z - mx), e3 = expf(v.w - mx);
    float s = e0 + e1 + e2 + e3;
    for (int o = 16; o; o >>= 1) s += __shfl_down_sync(~0u, s, o);
    __syncthreads();
    if ((tid & 31) == 0) red[tid >> 5] = s;
    __syncthreads();
    if (tid == 0) {
        float t = 0.f;
        for (int i = 0; i < 8; i++) t += red[i];
        stat = t;
    }
    __syncthreads();
    float inv = 1.0f / stat;
    if (valid) *(float4*)&sc[tid * 4] = make_float4(e0 * inv, e1 * inv, e2 * inv, e3 * inv);
}

// ===== tensor-core AV (tf32x3, LPT order) ====
#define PSTR 68
#define VSTR 72
#define PBYT (128*PSTR*4)
#define VBYT (64*VSTR*4)
#define AVSTG (PBYT + VBYT)
#define AVSM (2*AVSTG)

__global__ __launch_bounds__(256, 2)
void attn_av_mma_kernel() {
    int qt = gridDim.x - 1 - blockIdx.x;
    int bh = blockIdx.y;
    int b = bh >> 4, hh = bh & 15;

    extern __shared__ char smc[];
    unsigned sb = smem_u32(smc);

    int tid = threadIdx.x, wid = tid >> 5, lane = tid & 31;
    int grp = lane >> 2, qid = lane & 3;
    int wm0 = (wid & 3) * 32, wn0 = (wid >> 2) * 32;

    float acc[2][4][4];
#pragma unroll
    for (int mt = 0; mt < 2; mt++)
#pragma unroll
        for (int nt = 0; nt < 4; nt++)
#pragma unroll
            for (int e = 0; e < 4; e++) acc[mt][nt][e] = 0.f;

    int nchunks = (qt + 1) * 2;
    const float* pbase = g_sc + ((size_t)bh * SS + qt * 128) * SS;
    const float* vbase = g_qkv + ((size_t)(b * SS)) * QKVS + 2048 + hh * HD;

    {
        unsigned stP = sb;
        unsigned stV = sb + PBYT;
#pragma unroll
        for (int it = 0; it < 8; it++) {
            int idx = tid + it * 256;
            int row = idx >> 4, c4 = (idx & 15) * 4;
            CP16(stP + (row * PSTR + c4) * 4, pbase + (size_t)row * SS + c4);
        }
#pragma unroll
        for (int it = 0; it < 4; it++) {
            int idx = tid + it * 256;
            int tok = idx >> 4, d4 = (idx & 15) * 4;
            CP16(stV + (tok * VSTR + d4) * 4, vbase + (size_t)tok * QKVS + d4);
        }
        asm volatile("cp.async.commit_group;");
    }

    for (int kc = 0; kc < nchunks; kc++) {
        if (kc + 1 < nchunks) {
            unsigned st = sb + ((kc + 1) & 1) * AVSTG;
            unsigned stP = st, stV = st + PBYT;
            const float* pb = pbase + (kc + 1) * 64;
            const float* vb = vbase + (size_t)(kc + 1) * 64 * QKVS;
#pragma unroll
            for (int it = 0; it < 8; it++) {
                int idx = tid + it * 256;
                int row = idx >> 4, c4 = (idx & 15) * 4;
                CP16(stP + (row * PSTR + c4) * 4, pb + (size_t)row * SS + c4);
            }
#pragma unroll
            for (int it = 0; it < 4; it++) {
                int idx = tid + it * 256;
                int tok = idx >> 4, d4 = (idx & 15) * 4;
                CP16(stV + (tok * VSTR + d4) * 4, vb + (size_t)tok * QKVS + d4);
            }
            asm volatile("cp.async.commit_group;");
            asm volatile("cp.async.wait_group 1;");
        } else {
            asm volatile("cp.async.wait_group 0;");
        }
        __syncthreads();

        const float* Pr = (const float*)(smc + (kc & 1) * AVSTG);
        const float* Vr = Pr + 128 * PSTR;

#pragma unroll
        for (int s = 0; s < 8; s++) {
            int k8 = s * 8;
            unsigned Ah[2][4], Al[2][4];
#pragma unroll
            for (int mt = 0; mt < 2; mt++) {
                int ra = wm0 + mt * 16 + grp;
                float x0 = Pr[ra * PSTR + k8 + qid];
                float x1 = Pr[(ra + 8) * PSTR + k8 + qid];
                float x2 = Pr[ra * PSTR + k8 + qid + 4];
                float x3 = Pr[(ra + 8) * PSTR + k8 + qid + 4];
                float h0 = to_tf32f(x0), h1 = to_tf32f(x1), h2 = to_tf32f(x2), h3 = to_tf32f(x3);
                Ah[mt][0] = __float_as_uint(h0); Ah[mt][1] = __float_as_uint(h1);
                Ah[mt][2] = __float_as_uint(h2); Ah[mt][3] = __float_as_uint(h3);
                Al[mt][0] = __float_as_uint(to_tf32f(x0 - h0));
                Al[mt][1] = __float_as_uint(to_tf32f(x1 - h1));
                Al[mt][2] = __float_as_uint(to_tf32f(x2 - h2));
                Al[mt][3] = __float_as_uint(to_tf32f(x3 - h3));
            }
#pragma unroll
            for (int nt = 0; nt < 4; nt++) {
                int nr = wn0 + nt * 8 + grp;
                float y0 = Vr[(k8 + qid) * VSTR + nr];
                float y1 = Vr[(k8 + qid + 4) * VSTR + nr];
                float g0 = to_tf32f(y0), g1 = to_tf32f(y1);
                unsigned bh2[2] = {__float_as_uint(g0), __float_as_uint(g1)};
                unsigned bl2[2] = {__float_as_uint(to_tf32f(y0 - g0)),
                                   __float_as_uint(to_tf32f(y1 - g1))};
#pragma unroll
                for (int mt = 0; mt < 2; mt++) {
                    mma8(acc[mt][nt], Ah[mt], bh2);
                    mma8(acc[mt][nt], Ah[mt], bl2);
                    mma8(acc[mt][nt], Al[mt], bh2);
                }
            }
        }
        __syncthreads();
    }

#pragma unroll
    for (int mt = 0; mt < 2; mt++) {
#pragma unroll
        for (int nt = 0; nt < 4; nt++) {
            int r0 = qt * 128 + wm0 + mt * 16 + grp;
            int c0 = hh * HD + wn0 + nt * 8 + 2 * qid;
            float* p0 = g_a + ((size_t)(b * SS) + r0) * DD + c0;
            *(float2*)p0 = make_float2(acc[mt][nt][0], acc[mt][nt][1]);
            *(float2*)(p0 + 8 * DD) = make_float2(acc[mt][nt][2], acc[mt][nt][3]);
        }
    }
}

// ===== fused LN on compact rows =====
__global__ __launch_bounds__(256) void ln_fused_kernel(const float* __restrict__ inb,
                                                       int nparts,
                                                       const float* __restrict__ res,
                                                       const float* __restrict__ bias,
                                                       const float* __restrict__ g,
                                                       const float* __restrict__ bsh,
                                                       float* __restrict__ out,
                                                       int resGather, int outScatter) {
    int row = blockIdx.x;
    if (row >= g_nact) return;
    int orow = g_idx[row];
    size_t inoff = (size_t)row * DD;
    size_t resoff = (size_t)(resGather ? orow : row) * DD;
    size_t outoff = (size_t)(outScatter ? orow : row) * DD;
    int tid = threadIdx.x;
    float4 v = *(const float4*)&inb[inoff + tid * 4];
    for (int p = 1; p < nparts; p++) {
        float4 w = *(const float4*)&inb[(size_t)p * MM * DD + inoff + tid * 4];
        v.x += w.x; v.y += w.y; v.z += w.z; v.w += w.w;
    }
    float4 r = *(const float4*)&res[resoff + tid * 4];
    float4 bv = *(const float4*)&bias[tid * 4];
    v.x += r.x + bv.x; v.y += r.y + bv.y;
    v.z += r.z + bv.z; v.w += r.w + bv.w;
    __shared__ float red[8];
    __shared__ float stat;
    float s = v.x + v.y + v.z + v.w;
    for (int o = 16; o; o >>= 1) s += __shfl_down_sync(~0u, s, o);
    if ((tid & 31) == 0) red[tid >> 5] = s;
    __syncthreads();
    if (tid == 0) {
        float t = 0.f;
        for (int i = 0; i < 8; i++) t += red[i];
        stat = t * (1.0f / DD);
    }
    __syncthreads();
    float mu = stat;
    float dx = v.x - mu, dy = v.y - mu, dz = v.z - mu, dw = v.w - mu;
    float ss = dx * dx + dy * dy + dz * dz + dw * dw;
    for (int o = 16; o; o >>= 1) ss += __shfl_down_sync(~0u, ss, o);
    __syncthreads();
    if ((tid & 31) == 0) red[tid >> 5] = ss;
    __syncthreads();
    if (tid == 0) {
        float t = 0.f;
        for (int i = 0; i < 8; i++) t += red[i];
        stat = rsqrtf(t * (1.0f / DD) + 1e-5f);
    }
    __syncthreads();
    float rs = stat;
    float4 gg = *(const float4*)&g[tid * 4];
    float4 bb = *(const float4*)&bsh[tid * 4];
    *(float4*)&out[outoff + tid * 4] =
        make_float4(dx * rs * gg.x + bb.x, dy * rs * gg.y + bb.y,
                    dz * rs * gg.z + bb.z, dw * rs * gg.w + bb.w);
}

// ===== router head =====
__global__ __launch_bounds__(256) void router2_kernel(const float* __restrict__ rb1,
                                                      const float* __restrict__ rw2,
                                                      const float* __restrict__ rb2) {
    int w = (blockIdx.x * blockDim.x + threadIdx.x) >> 5;
    int lane = threadIdx.x & 31;
    if (w >= MM) return;
    float s0 = 0.f, s1 = 0.f, s2 = 0.f;
#pragma unroll
    for (int u = 0; u < 4; u++) {
        int j = lane + 32 * u;
        size_t o = (size_t)w * RH + j;
        float zv = g_tp[o] + g_tp[(size_t)MM * RH + o]
                 + g_tp[2 * (size_t)MM * RH + o] + g_tp[3 * (size_t)MM * RH + o] + rb1[j];
        zv = fmaxf(zv, 0.f);
        s0 += zv * rw2[j * 3 + 0];
        s1 += zv * rw2[j * 3 + 1];
        s2 += zv * rw2[j * 3 + 2];
    }
    for (int o = 16; o; o >>= 1) {
        s0 += __shfl_down_sync(~0u, s0, o);
        s1 += __shfl_down_sync(~0u, s1, o);
        s2 += __shfl_down_sync(~0u, s2, o);
    }
    if (lane == 0) {
        s0 += rb2[0]; s1 += rb2[1]; s2 += rb2[2];
        int a = 0; float best = s0;
        if (s1 > best) { best = s1; a = 1; }
        if (s2 > best) { best = s2; a = 2; }
        g_skip[w] = (a == 0);
        atomicAdd(&g_cnt[a], 1);
    }
}

__global__ void scalars_kernel(float* out) {
    float fs = (float)g_cnt[0], ff = (float)g_cnt[1], fr = (float)g_cnt[2];
    out[(size_t)MM * VOC + 0] = (ff + fr) / (float)MM;
    out[(size_t)MM * VOC + 1] = fs / (float)(MM * NL);
    out[(size_t)MM * VOC + 2] = ff / (float)(MM * NL);
    out[(size_t)MM * VOC + 3] = fr / (float)(MM * NL);
}

extern "C" void kernel_launch(void* const* d_in, const int* in_sizes, int n_in,
                              void* d_out, int out_size) {
    const int*   x    = (const int*)d_in[0];
    const float* emb  = (const float*)d_in[1];
    const float* Wq   = (const float*)d_in[2];
    const float* bq   = (const float*)d_in[3];
    const float* Wk   = (const float*)d_in[4];
    const float* bk   = (const float*)d_in[5];
    const float* Wv   = (const float*)d_in[6];
    const float* bv   = (const float*)d_in[7];
    const float* Wo   = (const float*)d_in[8];
    const float* bo   = (const float*)d_in[9];
    const float* ln1g = (const float*)d_in[10];
    const float* ln1b = (const float*)d_in[11];
    const float* Wf1  = (const float*)d_in[12];
    const float* bf1  = (const float*)d_in[13];
    const float* Wf2  = (const float*)d_in[14];
    const float* bf2  = (const float*)d_in[15];
    const float* ln2g = (const float*)d_in[16];
    const float* ln2b = (const float*)d_in[17];
    const float* rW1  = (const float*)d_in[18];
    const float* rb1  = (const float*)d_in[19];
    const float* rW2  = (const float*)d_in[20];
    const float* rb2  = (const float*)d_in[21];
    const float* Wout = (const float*)d_in[22];
    const float* bout = (const float*)d_in[23];
    float* out = (float*)d_out;

    cudaFuncSetAttribute(tgemm_kernel, cudaFuncAttributeMaxDynamicSharedMemorySize, TGSM);
    cudaFuncSetAttribute(attn_scores_mma_kernel, cudaFuncAttributeMaxDynamicSharedMemorySize, SCSM);
    cudaFuncSetAttribute(attn_av_mma_kernel, cudaFuncAttributeMaxDynamicSharedMemorySize, AVSM);

    float *h, *h1, *tp, *qkv, *a, *f1, *bqkv;
    __half *wqh, *wql, *woh, *wol, *w1h, *w1l, *w2h, *w2l, *wvh, *wvl, *r1h, *r1l;
    cudaGetSymbolAddress((void**)&h, g_h);
    cudaGetSymbolAddress((void**)&h1, g_h1);
    cudaGetSymbolAddress((void**)&tp, g_tp);
    cudaGetSymbolAddress((void**)&qkv, g_qkv);
    cudaGetSymbolAddress((void**)&a, g_a);
    cudaGetSymbolAddress((void**)&f1, g_f1);
    cudaGetSymbolAddress((void**)&wqh, g_wqkv_h);
    cudaGetSymbolAddress((void**)&wql, g_wqkv_l);
    cudaGetSymbolAddress((void**)&woh, g_wo_h);
    cudaGetSymbolAddress((void**)&wol, g_wo_l);
    cudaGetSymbolAddress((void**)&w1h, g_wf1_h);
    cudaGetSymbolAddress((void**)&w1l, g_wf1_l);
    cudaGetSymbolAddress((void**)&w2h, g_wf2_h);
    cudaGetSymbolAddress((void**)&w2l, g_wf2_l);
    cudaGetSymbolAddress((void**)&wvh, g_wout_h);
    cudaGetSymbolAddress((void**)&wvl, g_wout_l);
    cudaGetSymbolAddress((void**)&r1h, g_rw1t_h);
    cudaGetSymbolAddress((void**)&r1l, g_rw1t_l);
    cudaGetSymbolAddress((void**)&bqkv, g_bqkv);

    wtrans_kernel<<<dim3(DD/32, DD/32), 256>>>(Wq, wqh, wql, DD, DD);
    wtrans_kernel<<<dim3(DD/32, DD/32), 256>>>(Wk, wqh + (size_t)1024*DD, wql + (size_t)1024*DD, DD, DD);
    wtrans_kernel<<<dim3(DD/32, DD/32), 256>>>(Wv, wqh + (size_t)2048*DD, wql + (size_t)2048*DD, DD, DD);
    wtrans_kernel<<<dim3(DD/32, DD/32), 256>>>(Wo, woh, wol, DD, DD);
    wtrans_kernel<<<dim3(DFF/32, DD/32), 256>>>(Wf1, w1h, w1l, DD, DFF);
    wtrans_kernel<<<dim3(DD/32, DFF/32), 256>>>(Wf2, w2h, w2l, DFF, DD);
    wtrans_kernel<<<dim3(VOC/32, DD/32), 256>>>(Wout, wvh, wvl, DD, VOC);
    for (int l = 0; l < NL; l++)
        wtrans_kernel<<<dim3(RH/32, DD/32), 256>>>(rW1 + (size_t)l*DD*RH,
                                                   r1h + (size_t)l*RH*DD,
                                                   r1l + (size_t)l*RH*DD, DD, RH);
    bcat_kernel<<<QKVS/256, 256>>>(bq, bk, bv);

    zero_cnt_kernel<<<1, 32>>>();
    embed_kernel<<<MM, 256>>>(x, emb);

    const size_t ZST = (size_t)MM * DD;
    for (int l = 0; l < NL; l++) {
        tgemm_kernel<<<NPERS, 256, TGSM>>>(
            h, r1h + (size_t)l*RH*DD, r1l + (size_t)l*RH*DD, nullptr, tp, (size_t)MM*RH,
            MM, RH, DD/4, DD, 0, 0, 1, MM/128, 4, 1);
        router2_kernel<<<MM/8, 256>>>(rb1 + l*RH, rW2 + (size_t)l*RH*3, rb2 + l*3);
        compact_kernel<<<1, 1024>>>();
        tgemm_kernel<<<NPERS, 256, TGSM>>>(
            h, wqh, wql, nullptr, tp, (size_t)MM*QKVS,
            MM, QKVS, DD/2, DD, 0, 0, QKVS/128, MM/128, 2, 1);
        sum2_kernel<<<MM, 256>>>(tp, (size_t)MM*QKVS, bqkv, qkv, QKVS, 0, 0);
        attn_scores_mma_kernel<<<dim3(36, BHT), 256, SCSM>>>();
        softmax_kernel<<<BHT*SS, 256>>>();
        attn_av_mma_kernel<<<dim3(SS/128, BHT), 256, AVSM>>>();
        tgemm_kernel<<<NPERS, 256, TGSM>>>(
            a, woh, wol, nullptr, tp, ZST, MM, DD, DD/4, DD, 0, 1, DD/128, MM/128, 4, 1);
        ln_fused_kernel<<<MM, 256>>>(tp, 4, h, bo, ln1g, ln1b, h1, 1, 0);
        tgemm_kernel<<<NPERS, 256, TGSM>>>(
            h1, w1h, w1l, nullptr, tp, (size_t)MM*DFF,
            MM, DFF, DD/2, DD, 0, 2, DFF/128, MM/128, 2, 1);
        sum2_kernel<<<MM, 256>>>(tp, (size_t)MM*DFF, bf1, f1, DFF, 1, 1);
        tgemm_kernel<<<NPERS, 256, TGSM>>>(
            f1, w2h, w2l, nullptr, tp, ZST, MM, DD, DFF/8, DFF, 0, 2, DD/128, MM/128, 8, 1);
        ln_fused_kernel<<<MM, 256>>>(tp, 8, h1, bf2, ln2g, ln2b, h, 0, 1);
    }

    // logits: 2xFP16 (output-only)
    tgemm_kernel<<<NPERS, 256, TGSM>>>(
        h, wvh, wvl, bout, out, 0, MM, VOC, DD, DD, 0, 0, VOC/128, MM/128, 1, 0);
    scalars_kernel<<<1, 1>>>(out);
}